// round 10
// baseline (speedup 1.0000x reference)
#include <cuda_runtime.h>
#include <cuda_bf16.h>
#include <math.h>
#include <stdint.h>

// Problem constants
#define BATCH 2
#define SEQ 2048
#define TOK (BATCH*SEQ)          // 4096
#define HID 3584
#define NH 32
#define NKV 4
#define HD 128
#define QD (NH*HD)               // 4096
#define KVD (NKV*HD)             // 512

// fp32 scratch
__device__ float g_q[(size_t)TOK*QD];
// split-bf16 scratch
__device__ __nv_bfloat16 g_hh[(size_t)TOK*HID],  g_hl[(size_t)TOK*HID];
__device__ __nv_bfloat16 g_wqh[(size_t)QD*HID],  g_wql[(size_t)QD*HID];
__device__ __nv_bfloat16 g_wkh[(size_t)KVD*HID], g_wkl[(size_t)KVD*HID];
__device__ __nv_bfloat16 g_wvh[(size_t)KVD*HID], g_wvl[(size_t)KVD*HID];
__device__ __nv_bfloat16 g_woh[(size_t)HID*QD],  g_wol[(size_t)HID*QD];
__device__ __nv_bfloat16 g_ah[(size_t)TOK*QD],   g_al[(size_t)TOK*QD];
__device__ __nv_bfloat16 g_kh[(size_t)TOK*KVD],  g_kl[(size_t)TOK*KVD];
__device__ __nv_bfloat16 g_vh[(size_t)TOK*KVD],  g_vl[(size_t)TOK*KVD];

// ===========================================================================
// PTX helpers
// ===========================================================================
__device__ __forceinline__ uint32_t smem_u32(const void* p) {
    uint32_t a;
    asm("{ .reg .u64 t; cvta.to.shared.u64 t, %1; cvt.u32.u64 %0, t; }" : "=r"(a) : "l"(p));
    return a;
}
__device__ __forceinline__ void cp_async16(uint32_t dst, const void* src) {
    asm volatile("cp.async.cg.shared.global [%0], [%1], 16;" :: "r"(dst), "l"(src) : "memory");
}
#define CP_COMMIT() asm volatile("cp.async.commit_group;" ::: "memory")
#define CP_WAIT(n)  asm volatile("cp.async.wait_group %0;" :: "n"(n) : "memory")

__device__ __forceinline__ void ldm4(uint32_t* r, uint32_t addr) {
    asm volatile("ldmatrix.sync.aligned.m8n8.x4.shared.b16 {%0,%1,%2,%3}, [%4];"
                 : "=r"(r[0]), "=r"(r[1]), "=r"(r[2]), "=r"(r[3]) : "r"(addr));
}
__device__ __forceinline__ void ldm4t(uint32_t* r, uint32_t addr) {
    asm volatile("ldmatrix.sync.aligned.m8n8.x4.trans.shared.b16 {%0,%1,%2,%3}, [%4];"
                 : "=r"(r[0]), "=r"(r[1]), "=r"(r[2]), "=r"(r[3]) : "r"(addr));
}
__device__ __forceinline__ void mma_bf16(float* c, const uint32_t* a, const uint32_t* b) {
    asm volatile("mma.sync.aligned.m16n8k16.row.col.f32.bf16.bf16.f32 "
                 "{%0,%1,%2,%3}, {%4,%5,%6,%7}, {%8,%9}, {%0,%1,%2,%3};"
                 : "+f"(c[0]), "+f"(c[1]), "+f"(c[2]), "+f"(c[3])
                 : "r"(a[0]), "r"(a[1]), "r"(a[2]), "r"(a[3]), "r"(b[0]), "r"(b[1]));
}
__device__ __forceinline__ uint32_t cvt2bf(float hi, float lo) {
    uint32_t r;
    asm("cvt.rn.bf16x2.f32 %0, %1, %2;" : "=r"(r) : "f"(hi), "f"(lo));
    return r;
}
__device__ __forceinline__ float bfloF(uint32_t p) { return __int_as_float(p << 16); }
__device__ __forceinline__ float bfhiF(uint32_t p) { return __int_as_float(p & 0xffff0000u); }

// fast 2^t on the FMA pipe (no MUFU); exp2(0) == 1.0 exactly
__device__ __forceinline__ float fast_exp2(float t) {
    t = fmaxf(t, -120.0f);
    float r = t + 12582912.0f;
    float n = r - 12582912.0f;
    float f = t - n;
    int   ni = __float_as_int(r);
    float p = 1.3392112e-3f;
    p = fmaf(p, f, 9.6183463e-3f);
    p = fmaf(p, f, 5.5503277e-2f);
    p = fmaf(p, f, 2.4022652e-1f);
    p = fmaf(p, f, 6.9314718e-1f);
    p = fmaf(p, f, 1.0f);
    return __int_as_float(__float_as_int(p) + (ni << 23));
}

// ===========================================================================
// Fused split: all five fp32->bf16(hi,lo) splits in one launch.
// ===========================================================================
#define SPL_N0 (TOK*HID)
#define SPL_N1 (SPL_N0 + QD*HID)
#define SPL_N2 (SPL_N1 + KVD*HID)
#define SPL_N3 (SPL_N2 + KVD*HID)
#define SPL_N4 (SPL_N3 + HID*QD)

__global__ void split_all_kernel(
    const float* __restrict__ x0, const float* __restrict__ x1,
    const float* __restrict__ x2, const float* __restrict__ x3,
    const float* __restrict__ x4,
    __nv_bfloat16* __restrict__ h0, __nv_bfloat16* __restrict__ l0,
    __nv_bfloat16* __restrict__ h1, __nv_bfloat16* __restrict__ l1,
    __nv_bfloat16* __restrict__ h2, __nv_bfloat16* __restrict__ l2,
    __nv_bfloat16* __restrict__ h3, __nv_bfloat16* __restrict__ l3,
    __nv_bfloat16* __restrict__ h4, __nv_bfloat16* __restrict__ l4)
{
    int i = blockIdx.x * 256 + threadIdx.x;
    if (i >= SPL_N4) return;
    const float* x; __nv_bfloat16 *h, *l; int off;
    if (i < SPL_N0)      { x = x0; h = h0; l = l0; off = i; }
    else if (i < SPL_N1) { x = x1; h = h1; l = l1; off = i - SPL_N0; }
    else if (i < SPL_N2) { x = x2; h = h2; l = l2; off = i - SPL_N1; }
    else if (i < SPL_N3) { x = x3; h = h3; l = l3; off = i - SPL_N2; }
    else                 { x = x4; h = h4; l = l4; off = i - SPL_N3; }
    float v = x[off];
    __nv_bfloat16 hv = __float2bfloat16(v);
    h[off] = hv;
    l[off] = __float2bfloat16(v - __bfloat162float(hv));
}

// ===========================================================================
// mma.sync split-bf16 GEMM mainloop: 128x128x32 tiles, 5-stage cp.async
// pipeline, register double-buffered ldmatrix fragments, 8 warps (2x4),
// warp 64x32, 3-term split product.
// ===========================================================================
#define TSTR 40
#define TILE_B (128*TSTR*2)           // 10240
#define STAGE_B (4*TILE_B)            // 40960
#define GEMM_SMEM (5*STAGE_B)         // 204800, 5 stages

__device__ __forceinline__ void gemm_issue_loads(
    uint32_t sstage, const __nv_bfloat16* pAh, const __nv_bfloat16* pAl,
    const __nv_bfloat16* pBh, const __nv_bfloat16* pBl, int K, int ko, int tid)
{
    #pragma unroll
    for (int i = 0; i < 2; i++) {
        int c = tid + (i << 8);
        int row = c >> 2;
        int kc  = c & 3;
        uint32_t dst = (uint32_t)(row * TSTR + kc * 8) * 2;
        size_t src = (size_t)row * K + ko + kc * 8;
        cp_async16(sstage + 0*TILE_B + dst, pAh + src);
        cp_async16(sstage + 1*TILE_B + dst, pAl + src);
        cp_async16(sstage + 2*TILE_B + dst, pBh + src);
        cp_async16(sstage + 3*TILE_B + dst, pBl + src);
    }
}

// Load one half-k (kk in {0,1}) fragment set from stage base st.
__device__ __forceinline__ void load_frags(
    uint32_t st, int kk, int wm, int wn, uint32_t laneA, uint32_t laneB,
    uint32_t ah[4][4], uint32_t al[4][4], uint32_t bh[4][2], uint32_t bl[4][2])
{
    #pragma unroll
    for (int mi = 0; mi < 4; mi++) {
        uint32_t aoff = (uint32_t)(((wm * 64 + mi * 16) * TSTR + kk * 16) * 2);
        ldm4(ah[mi], st + aoff + laneA);
        ldm4(al[mi], st + TILE_B + aoff + laneA);
    }
    #pragma unroll
    for (int nj2 = 0; nj2 < 2; nj2++) {
        uint32_t boff = (uint32_t)(((wn * 32 + nj2 * 16) * TSTR + kk * 16) * 2);
        uint32_t r[4];
        ldm4(r, st + 2*TILE_B + boff + laneB);
        bh[nj2*2][0] = r[0]; bh[nj2*2][1] = r[1];
        bh[nj2*2+1][0] = r[2]; bh[nj2*2+1][1] = r[3];
        ldm4(r, st + 3*TILE_B + boff + laneB);
        bl[nj2*2][0] = r[0]; bl[nj2*2][1] = r[1];
        bl[nj2*2+1][0] = r[2]; bl[nj2*2+1][1] = r[3];
    }
}

__device__ __forceinline__ void mma_block(
    float acc[4][4][4], uint32_t ah[4][4], uint32_t al[4][4],
    uint32_t bh[4][2], uint32_t bl[4][2])
{
    #pragma unroll
    for (int mi = 0; mi < 4; mi++)
        #pragma unroll
        for (int nj = 0; nj < 4; nj++) {
            mma_bf16(acc[mi][nj], ah[mi], bh[nj]);
            mma_bf16(acc[mi][nj], ah[mi], bl[nj]);
            mma_bf16(acc[mi][nj], al[mi], bh[nj]);
        }
}

// Fills acc[4][4][4]; after return all cp.asyncs are complete and smem is
// reusable by the caller's epilogue (after one __syncthreads).
__device__ __forceinline__ void gemm_mainloop(
    const __nv_bfloat16* __restrict__ pAh, const __nv_bfloat16* __restrict__ pAl,
    const __nv_bfloat16* __restrict__ pBh, const __nv_bfloat16* __restrict__ pBl,
    int K, char* smem, float acc[4][4][4])
{
    uint32_t sbase = smem_u32(smem);
    const int tid  = threadIdx.x;
    const int lane = tid & 31;
    const int wid  = tid >> 5;
    const int wm   = wid >> 2;
    const int wn   = wid & 3;

    const uint32_t laneA = (uint32_t)((lane & 15) * TSTR + ((lane >> 4) << 3)) * 2;
    const uint32_t laneB = (uint32_t)(((lane & 7) + ((lane >> 4) << 3)) * TSTR
                                      + (((lane >> 3) & 1) << 3)) * 2;

    #pragma unroll
    for (int i = 0; i < 4; i++)
        #pragma unroll
        for (int j = 0; j < 4; j++)
            #pragma unroll
            for (int r = 0; r < 4; r++) acc[i][j][r] = 0.f;

    const int KT = K >> 5;   // >= 5 for all calls (112 / 128)
    #pragma unroll
    for (int i = 0; i < 4; i++) {
        gemm_issue_loads(sbase + i * STAGE_B, pAh, pAl, pBh, pBl, K, i << 5, tid);
        CP_COMMIT();
    }

    // stages 0 and 1 resident
    CP_WAIT(2);
    __syncthreads();

    uint32_t ahA[4][4], alA[4][4], bhA[4][2], blA[4][2];
    uint32_t ahB[4][4], alB[4][4], bhB[4][2], blB[4][2];
    load_frags(sbase, 0, wm, wn, laneA, laneB, ahA, alA, bhA, blA);

    int cur = 0, pf = 4;
    for (int kt = 0; kt < KT; kt++) {
        uint32_t stCur  = sbase + (uint32_t)cur * STAGE_B;
        int nxt = cur + 1; if (nxt == 5) nxt = 0;
        uint32_t stNext = sbase + (uint32_t)nxt * STAGE_B;

        // kk=0: prefetch kk=1 fragments, then MMA on buffered kk=0 set
        load_frags(stCur, 1, wm, wn, laneA, laneB, ahB, alB, bhB, blB);
        mma_block(acc, ahA, alA, bhA, blA);

        // kk=1: prefetch next kt's kk=0 fragments (stage kt+1 is resident),
        // then MMA on kk=1 set
        if (kt + 1 < KT)
            load_frags(stNext, 0, wm, wn, laneA, laneB, ahA, alA, bhA, blA);
        mma_block(acc, ahB, alB, bhB, blB);

        // issue gmem prefetch for stage kt+4
        if (kt + 4 < KT) {
            gemm_issue_loads(sbase + (uint32_t)pf * STAGE_B,
                             pAh, pAl, pBh, pBl, K, (kt + 4) << 5, tid);
            CP_COMMIT();
        }

        // wait so that stages kt+1 AND kt+2 are resident for the next iter
        if (kt + 1 < KT) {
            int rem = KT - 2 - kt;       // stages after stage kt+1
            if (rem >= 3)      { CP_WAIT(2); }
            else if (rem == 2) { CP_WAIT(1); }
            else               { CP_WAIT(0); }
            __syncthreads();
        }
        cur = nxt;
        pf++; if (pf == 5) pf = 0;
    }
    CP_WAIT(0);
}

// fp32 epilogue (Q and O projections)
__device__ __forceinline__ void epilogue_f32(float acc[4][4][4], float* Ct, int N)
{
    const int lane = threadIdx.x & 31;
    const int wid  = threadIdx.x >> 5;
    const int wm = wid >> 2, wn = wid & 3;
    const int g = lane >> 2, tg = lane & 3;
    #pragma unroll
    for (int mi = 0; mi < 4; mi++) {
        int row = wm * 64 + mi * 16 + g;
        #pragma unroll
        for (int nj = 0; nj < 4; nj++) {
            int col = wn * 32 + nj * 8 + tg * 2;
            float* p0 = Ct + (size_t)row * N + col;
            float* p1 = p0 + (size_t)8 * N;
            p0[0] = acc[mi][nj][0]; p0[1] = acc[mi][nj][1];
            p1[0] = acc[mi][nj][2]; p1[1] = acc[mi][nj][3];
        }
    }
}

// Fused Q/K/V projection: grid (40, TOK/128). bx 0-31: Q (fp32 out);
// bx 32-35: K (rope + hi/lo split via smem staging); bx 36-39: V (hi/lo split).
__global__ void __launch_bounds__(256, 1)
gemm_qkv(const __nv_bfloat16* __restrict__ hh, const __nv_bfloat16* __restrict__ hl,
         const __nv_bfloat16* __restrict__ wqh, const __nv_bfloat16* __restrict__ wql,
         const __nv_bfloat16* __restrict__ wkh, const __nv_bfloat16* __restrict__ wkl,
         const __nv_bfloat16* __restrict__ wvh, const __nv_bfloat16* __restrict__ wvl,
         float* __restrict__ qb,
         __nv_bfloat16* __restrict__ kh, __nv_bfloat16* __restrict__ kl,
         __nv_bfloat16* __restrict__ vh, __nv_bfloat16* __restrict__ vl,
         const int* __restrict__ pos32)
{
    extern __shared__ char smem[];
    const int bx = blockIdx.x;
    const int bm = blockIdx.y << 7;
    const int tid = threadIdx.x;
    const __nv_bfloat16 *bhp, *blp;
    int bn;
    if (bx < 32)      { bhp = wqh; blp = wql; bn = bx << 7; }
    else if (bx < 36) { bhp = wkh; blp = wkl; bn = (bx - 32) << 7; }
    else              { bhp = wvh; blp = wvl; bn = (bx - 36) << 7; }

    float acc[4][4][4];
    gemm_mainloop(hh + (size_t)bm * HID, hl + (size_t)bm * HID,
                  bhp + (size_t)bn * HID, blp + (size_t)bn * HID,
                  HID, smem, acc);

    const int lane = tid & 31;
    const int wid  = tid >> 5;
    const int wm = wid >> 2, wn = wid & 3;
    const int g = lane >> 2, tg = lane & 3;

    if (bx < 32) {
        epilogue_f32(acc, qb + (size_t)bm * QD + bn, QD);
    } else if (bx < 36) {
        // K: stage acc to smem, then rope + hi/lo split
        float* sacc = (float*)smem;     // [128][132]
        __syncthreads();                // mainloop smem reads done in all warps
        #pragma unroll
        for (int mi = 0; mi < 4; mi++) {
            int row = wm * 64 + mi * 16 + g;
            #pragma unroll
            for (int nj = 0; nj < 4; nj++) {
                int col = wn * 32 + nj * 8 + tg * 2;
                sacc[row * 132 + col]     = acc[mi][nj][0];
                sacc[row * 132 + col + 1] = acc[mi][nj][1];
                sacc[(row + 8) * 132 + col]     = acc[mi][nj][2];
                sacc[(row + 8) * 132 + col + 1] = acc[mi][nj][3];
            }
        }
        __syncthreads();
        const bool is64 = (pos32[1] == 0);
        #pragma unroll
        for (int i = 0; i < 32; i++) {
            int idx = tid + (i << 8);           // 0..8191
            int row = idx >> 6;                 // 0..127
            int d   = idx & 63;
            int t   = bm + row;
            int p = is64 ? pos32[2 * t] : pos32[t];
            float invf = powf(1.0e6f, -(float)d * (1.0f / 64.0f));
            float sv, cv;
            sincosf((float)p * invf, &sv, &cv);
            float x1 = sacc[row * 132 + d];
            float x2 = sacc[row * 132 + d + 64];
            float y1 = x1 * cv - x2 * sv;
            float y2 = x2 * cv + x1 * sv;
            __nv_bfloat16 h1 = __float2bfloat16(y1);
            __nv_bfloat16 h2 = __float2bfloat16(y2);
            size_t off = (size_t)t * KVD + bn + d;
            kh[off]      = h1; kl[off]      = __float2bfloat16(y1 - __bfloat162float(h1));
            kh[off + 64] = h2; kl[off + 64] = __float2bfloat16(y2 - __bfloat162float(h2));
        }
    } else {
        // V: split acc directly to bf16 hi/lo
        #pragma unroll
        for (int mi = 0; mi < 4; mi++) {
            int row = wm * 64 + mi * 16 + g;
            #pragma unroll
            for (int nj = 0; nj < 4; nj++) {
                int col = wn * 32 + nj * 8 + tg * 2;
                size_t off0 = (size_t)(bm + row) * KVD + bn + col;
                size_t off1 = off0 + (size_t)8 * KVD;
                float a0 = acc[mi][nj][0], a1 = acc[mi][nj][1];
                uint32_t hp = cvt2bf(a1, a0);
                uint32_t lp = cvt2bf(a1 - bfhiF(hp), a0 - bfloF(hp));
                *(uint32_t*)(vh + off0) = hp;
                *(uint32_t*)(vl + off0) = lp;
                float b0 = acc[mi][nj][2], b1 = acc[mi][nj][3];
                hp = cvt2bf(b1, b0);
                lp = cvt2bf(b1 - bfhiF(hp), b0 - bfloF(hp));
                *(uint32_t*)(vh + off1) = hp;
                *(uint32_t*)(vl + off1) = lp;
            }
        }
    }
}

// Generic NT split GEMM (O-projection)
__global__ void __launch_bounds__(256, 1)
gemm_nt_split(const __nv_bfloat16* __restrict__ Ah, const __nv_bfloat16* __restrict__ Al,
              const __nv_bfloat16* __restrict__ Bh, const __nv_bfloat16* __restrict__ Bl,
              float* __restrict__ C, int N, int K)
{
    extern __shared__ char smem[];
    const int bm = blockIdx.y << 7;
    const int bn = blockIdx.x << 7;
    float acc[4][4][4];
    gemm_mainloop(Ah + (size_t)bm * K, Al + (size_t)bm * K,
                  Bh + (size_t)bn * K, Bl + (size_t)bn * K, K, smem, acc);
    epilogue_f32(acc, C + (size_t)bm * N + bn, N);
}

// ===========================================================================
// Flash attention: mma.sync split-bf16, FMA-pipe exp2, non-causal.
// Q-RoPE fused into the Q-load. Epilogue writes split bf16 hi/lo directly.
// ===========================================================================
#define FSTR 136
#define FA_Q_B (128*FSTR*2)
#define FA_T_B (64*FSTR*2)
#define FA_ST_B (4*FA_T_B)
#define FA_SMEM (2*FA_Q_B + 2*FA_ST_B)    // 208896

__device__ __forceinline__ void fa_load_kv(
    uint32_t stage, const __nv_bfloat16* __restrict__ Kh, const __nv_bfloat16* __restrict__ Kl,
    const __nv_bfloat16* __restrict__ Vh, const __nv_bfloat16* __restrict__ Vl,
    size_t rowbase, int kvoff, int tid)
{
    #pragma unroll
    for (int comp = 0; comp < 4; comp++) {
        const __nv_bfloat16* g = (comp == 0) ? Kh : (comp == 1) ? Kl : (comp == 2) ? Vh : Vl;
        #pragma unroll
        for (int jj = 0; jj < 4; jj++) {
            int cc = tid + (jj << 8);
            int row = cc >> 4, kc = cc & 15;
            cp_async16(stage + comp * FA_T_B + (uint32_t)(row * 272 + kc * 16),
                       g + (rowbase + row) * KVD + kvoff + kc * 8);
        }
    }
}

__global__ void __launch_bounds__(256, 1)
flash_attn_mma(const float* __restrict__ Q, const int* __restrict__ pos32,
               const __nv_bfloat16* __restrict__ Kh, const __nv_bfloat16* __restrict__ Kl,
               const __nv_bfloat16* __restrict__ Vh, const __nv_bfloat16* __restrict__ Vl,
               __nv_bfloat16* __restrict__ ah, __nv_bfloat16* __restrict__ al)
{
    extern __shared__ char smem[];
    uint32_t sb = smem_u32(smem);
    const uint32_t sQH = sb;
    const uint32_t sQL = sb + FA_Q_B;
    const uint32_t sST = sb + 2 * FA_Q_B;

    const int tid = threadIdx.x, lane = tid & 31, w = tid >> 5;
    const int bh = blockIdx.y, b = bh >> 5, h = bh & 31, kvh = h >> 3;
    const int q0 = blockIdx.x << 7;
    const int g = lane >> 2, t = lane & 3;

    // --- Q load + RoPE + scale(1/sqrt(d)*log2e) + hi/lo split into smem ---
    const float qsc = 0.08838834764831843f * 1.4426950408889634f;
    const float* Qg = Q + (size_t)(b * SEQ + q0) * QD + h * HD;
    const bool is64 = (pos32[1] == 0);
    #pragma unroll
    for (int i = 0; i < 8; i++) {
        int idx = tid + (i << 8);
        int row = idx >> 4;
        int d4  = (idx & 15) << 2;
        int tok = b * SEQ + q0 + row;
        int p = is64 ? pos32[2 * tok] : pos32[tok];
        float4 xa = *(const float4*)(Qg + (size_t)row * QD + d4);
        float4 xb = *(const float4*)(Qg + (size_t)row * QD + d4 + 64);
        float ya[4], yb[4];
        const float* x1 = &xa.x;
        const float* x2 = &xb.x;
        #pragma unroll
        for (int j = 0; j < 4; j++) {
            int d = d4 + j;
            float invf = powf(1.0e6f, -(float)d * (1.0f / 64.0f));
            float sv, cv;
            sincosf((float)p * invf, &sv, &cv);
            ya[j] = (x1[j] * cv - x2[j] * sv) * qsc;
            yb[j] = (x2[j] * cv + x1[j] * sv) * qsc;
        }
        uint32_t ha01 = cvt2bf(ya[1], ya[0]);
        uint32_t ha23 = cvt2bf(ya[3], ya[2]);
        uint32_t la01 = cvt2bf(ya[1] - bfhiF(ha01), ya[0] - bfloF(ha01));
        uint32_t la23 = cvt2bf(ya[3] - bfhiF(ha23), ya[2] - bfloF(ha23));
        uint32_t hb01 = cvt2bf(yb[1], yb[0]);
        uint32_t hb23 = cvt2bf(yb[3], yb[2]);
        uint32_t lb01 = cvt2bf(yb[1] - bfhiF(hb01), yb[0] - bfloF(hb01));
        uint32_t lb23 = cvt2bf(yb[3] - bfhiF(hb23), yb[2] - bfloF(hb23));
        uint32_t off1 = (uint32_t)(row * 272 + d4 * 2);
        uint32_t off2 = (uint32_t)(row * 272 + (d4 + 64) * 2);
        *(uint2*)(smem + (sQH - sb) + off1) = make_uint2(ha01, ha23);
        *(uint2*)(smem + (sQL - sb) + off1) = make_uint2(la01, la23);
        *(uint2*)(smem + (sQH - sb) + off2) = make_uint2(hb01, hb23);
        *(uint2*)(smem + (sQL - sb) + off2) = make_uint2(lb01, lb23);
    }

    float m0 = -1e30f, m1 = -1e30f, l0 = 0.f, l1 = 0.f;
    float o[16][4];
    #pragma unroll
    for (int nd = 0; nd < 16; nd++)
        #pragma unroll
        for (int c = 0; c < 4; c++) o[nd][c] = 0.f;

    const size_t kvbase = (size_t)b * SEQ;
    const int kvoff = kvh * HD;

    const uint32_t lA = (uint32_t)(((lane & 15) * FSTR + ((lane >> 4) << 3)) * 2);
    const uint32_t lB = (uint32_t)((((lane & 7) + ((lane >> 4) << 3)) * FSTR
                                    + (((lane >> 3) & 1) << 3)) * 2);
    const uint32_t lV = (uint32_t)((((lane & 7) + (((lane >> 3) & 1) << 3)) * FSTR
                                    + (((lane >> 4) & 1) << 3)) * 2);

    fa_load_kv(sST, Kh, Kl, Vh, Vl, kvbase, kvoff, tid);
    CP_COMMIT();

    for (int kt = 0; kt < SEQ / 64; kt++) {
        if (kt + 1 < SEQ / 64) {
            fa_load_kv(sST + ((kt + 1) & 1) * FA_ST_B, Kh, Kl, Vh, Vl,
                       kvbase + (size_t)(kt + 1) * 64, kvoff, tid);
            CP_COMMIT();
            CP_WAIT(1);
        } else {
            CP_WAIT(0);
        }
        __syncthreads();

        const uint32_t st = sST + (kt & 1) * FA_ST_B;
        const uint32_t sKH = st, sKL = st + FA_T_B, sVH = st + 2*FA_T_B, sVL = st + 3*FA_T_B;

        float s[8][4];
        #pragma unroll
        for (int j = 0; j < 8; j++)
            #pragma unroll
            for (int c = 0; c < 4; c++) s[j][c] = 0.f;

        #pragma unroll
        for (int kk = 0; kk < 8; kk++) {
            uint32_t qh[4], ql[4];
            uint32_t qoff = (uint32_t)((w * 16 * FSTR + kk * 16) * 2);
            ldm4(qh, sQH + qoff + lA);
            ldm4(ql, sQL + qoff + lA);
            #pragma unroll
            for (int nj2 = 0; nj2 < 4; nj2++) {
                uint32_t koff = (uint32_t)((nj2 * 16 * FSTR + kk * 16) * 2);
                uint32_t rh[4], rl[4];
                ldm4(rh, sKH + koff + lB);
                ldm4(rl, sKL + koff + lB);
                mma_bf16(s[nj2*2],   qh, rh);     mma_bf16(s[nj2*2],   qh, rl);
                mma_bf16(s[nj2*2],   ql, rh);
                mma_bf16(s[nj2*2+1], qh, rh + 2); mma_bf16(s[nj2*2+1], qh, rl + 2);
                mma_bf16(s[nj2*2+1], ql, rh + 2);
            }
        }

        float mx0 = -1e30f, mx1 = -1e30f;
        #pragma unroll
        for (int j = 0; j < 8; j++) {
            mx0 = fmaxf(mx0, fmaxf(s[j][0], s[j][1]));
            mx1 = fmaxf(mx1, fmaxf(s[j][2], s[j][3]));
        }
        mx0 = fmaxf(mx0, __shfl_xor_sync(0xffffffffu, mx0, 1));
        mx0 = fmaxf(mx0, __shfl_xor_sync(0xffffffffu, mx0, 2));
        mx1 = fmaxf(mx1, __shfl_xor_sync(0xffffffffu, mx1, 1));
        mx1 = fmaxf(mx1, __shfl_xor_sync(0xffffffffu, mx1, 2));
        float mn0 = fmaxf(m0, mx0), mn1 = fmaxf(m1, mx1);

        // skip-rescale fast path: alpha == 1 exactly when no new max
        bool newmax = (mn0 > m0) || (mn1 > m1);
        if (__any_sync(0xffffffffu, newmax)) {
            float al0 = fast_exp2(m0 - mn0), al1 = fast_exp2(m1 - mn1);
            l0 *= al0; l1 *= al1;
            #pragma unroll
            for (int nd = 0; nd < 16; nd++) {
                o[nd][0] *= al0; o[nd][1] *= al0;
                o[nd][2] *= al1; o[nd][3] *= al1;
            }
        }
        m0 = mn0; m1 = mn1;

        uint32_t ph[4][4], pl[4][4];
        float sum0 = 0.f, sum1 = 0.f;
        #pragma unroll
        for (int j = 0; j < 8; j++) {
            float p00 = fast_exp2(s[j][0] - mn0);
            float p01 = fast_exp2(s[j][1] - mn0);
            float p10 = fast_exp2(s[j][2] - mn1);
            float p11 = fast_exp2(s[j][3] - mn1);
            sum0 += p00 + p01; sum1 += p10 + p11;
            uint32_t hA = cvt2bf(p01, p00);
            uint32_t hB = cvt2bf(p11, p10);
            uint32_t lAp = cvt2bf(p01 - bfhiF(hA), p00 - bfloF(hA));
            uint32_t lBp = cvt2bf(p11 - bfhiF(hB), p10 - bfloF(hB));
            int kk2 = j >> 1, hf = (j & 1) << 1;
            ph[kk2][hf]     = hA;  ph[kk2][hf + 1] = hB;
            pl[kk2][hf]     = lAp; pl[kk2][hf + 1] = lBp;
        }
        sum0 += __shfl_xor_sync(0xffffffffu, sum0, 1);
        sum0 += __shfl_xor_sync(0xffffffffu, sum0, 2);
        sum1 += __shfl_xor_sync(0xffffffffu, sum1, 1);
        sum1 += __shfl_xor_sync(0xffffffffu, sum1, 2);
        l0 += sum0;
        l1 += sum1;

        #pragma unroll
        for (int kk2 = 0; kk2 < 4; kk2++) {
            #pragma unroll
            for (int ndp = 0; ndp < 8; ndp++) {
                uint32_t voff = (uint32_t)((kk2 * 16 * FSTR + ndp * 16) * 2);
                uint32_t vh[4], vl[4];
                ldm4t(vh, sVH + voff + lV);
                ldm4t(vl, sVL + voff + lV);
                mma_bf16(o[ndp*2],   ph[kk2], vh);     mma_bf16(o[ndp*2],   ph[kk2], vl);
                mma_bf16(o[ndp*2],   pl[kk2], vh);
                mma_bf16(o[ndp*2+1], ph[kk2], vh + 2); mma_bf16(o[ndp*2+1], ph[kk2], vl + 2);
                mma_bf16(o[ndp*2+1], pl[kk2], vh + 2);
            }
        }
        __syncthreads();
    }

    float il0 = 1.f / l0, il1 = 1.f / l1;
    size_t rbase = (size_t)(b * SEQ + q0 + w * 16 + g) * QD + h * HD;
    __nv_bfloat16* AH = ah + rbase;
    __nv_bfloat16* AL = al + rbase;
    #pragma unroll
    for (int nd = 0; nd < 16; nd++) {
        int col = nd * 8 + t * 2;
        float a0 = o[nd][0] * il0, a1 = o[nd][1] * il0;
        uint32_t hp = cvt2bf(a1, a0);
        uint32_t lp = cvt2bf(a1 - bfhiF(hp), a0 - bfloF(hp));
        *(uint32_t*)(AH + col) = hp;
        *(uint32_t*)(AL + col) = lp;
        float b0 = o[nd][2] * il1, b1 = o[nd][3] * il1;
        hp = cvt2bf(b1, b0);
        lp = cvt2bf(b1 - bfhiF(hp), b0 - bfloF(hp));
        *(uint32_t*)(AH + (size_t)8 * QD + col) = hp;
        *(uint32_t*)(AL + (size_t)8 * QD + col) = lp;
    }
}

// ---------------------------------------------------------------------------
extern "C" void kernel_launch(void* const* d_in, const int* in_sizes, int n_in,
                              void* d_out, int out_size)
{
    const float* hidden = (const float*)d_in[0];
    const int*   pos    = (const int*)d_in[1];
    const float* Wq     = (const float*)d_in[2];
    const float* Wk     = (const float*)d_in[3];
    const float* Wv     = (const float*)d_in[4];
    const float* Wo     = (const float*)d_in[5];
    float*       out    = (float*)d_out;

    float *qb;
    cudaGetSymbolAddress((void**)&qb, g_q);
    __nv_bfloat16 *hh,*hl,*wqh,*wql,*wkh,*wkl,*wvh,*wvl,*woh,*wol,*ah,*al,*kh,*kl,*vh,*vl;
    cudaGetSymbolAddress((void**)&hh,  g_hh);  cudaGetSymbolAddress((void**)&hl,  g_hl);
    cudaGetSymbolAddress((void**)&wqh, g_wqh); cudaGetSymbolAddress((void**)&wql, g_wql);
    cudaGetSymbolAddress((void**)&wkh, g_wkh); cudaGetSymbolAddress((void**)&wkl, g_wkl);
    cudaGetSymbolAddress((void**)&wvh, g_wvh); cudaGetSymbolAddress((void**)&wvl, g_wvl);
    cudaGetSymbolAddress((void**)&woh, g_woh); cudaGetSymbolAddress((void**)&wol, g_wol);
    cudaGetSymbolAddress((void**)&ah,  g_ah);  cudaGetSymbolAddress((void**)&al,  g_al);
    cudaGetSymbolAddress((void**)&kh,  g_kh);  cudaGetSymbolAddress((void**)&kl,  g_kl);
    cudaGetSymbolAddress((void**)&vh,  g_vh);  cudaGetSymbolAddress((void**)&vl,  g_vl);

    cudaFuncSetAttribute(gemm_qkv, cudaFuncAttributeMaxDynamicSharedMemorySize, GEMM_SMEM);
    cudaFuncSetAttribute(gemm_nt_split, cudaFuncAttributeMaxDynamicSharedMemorySize, GEMM_SMEM);
    cudaFuncSetAttribute(flash_attn_mma, cudaFuncAttributeMaxDynamicSharedMemorySize, FA_SMEM);

    // All input/weight splits in one launch
    split_all_kernel<<<(SPL_N4 + 255)/256, 256>>>(hidden, Wq, Wk, Wv, Wo,
                                                  hh, hl, wqh, wql, wkh, wkl,
                                                  wvh, wvl, woh, wol);

    // Fused Q/K/V projections (128x128, 5-stage, reg-pipelined fragments)
    gemm_qkv<<<dim3(40, TOK/128), 256, GEMM_SMEM>>>(hh, hl, wqh, wql, wkh, wkl, wvh, wvl,
                                                    qb, kh, kl, vh, vl, pos);

    // Flash attention (Q rope fused) -> split bf16 output
    flash_attn_mma<<<dim3(SEQ/128, BATCH*NH), 256, FA_SMEM>>>(qb, pos, kh, kl, vh, vl, ah, al);

    // O projection (128x128, 5-stage, reg-pipelined fragments)
    gemm_nt_split<<<dim3(HID/128, TOK/128), 256, GEMM_SMEM>>>(ah, al, woh, wol, out, HID, QD);
}

// round 11
// speedup vs baseline: 1.0758x; 1.0758x over previous
#include <cuda_runtime.h>
#include <cuda_bf16.h>
#include <math.h>
#include <stdint.h>

// Problem constants
#define BATCH 2
#define SEQ 2048
#define TOK (BATCH*SEQ)          // 4096
#define HID 3584
#define NH 32
#define NKV 4
#define HD 128
#define QD (NH*HD)               // 4096
#define KVD (NKV*HD)             // 512

// fp32 scratch
__device__ float g_q[(size_t)TOK*QD];
// split-bf16 scratch
__device__ __nv_bfloat16 g_hh[(size_t)TOK*HID],  g_hl[(size_t)TOK*HID];
__device__ __nv_bfloat16 g_wqh[(size_t)QD*HID],  g_wql[(size_t)QD*HID];
__device__ __nv_bfloat16 g_wkh[(size_t)KVD*HID], g_wkl[(size_t)KVD*HID];
__device__ __nv_bfloat16 g_wvh[(size_t)KVD*HID], g_wvl[(size_t)KVD*HID];
__device__ __nv_bfloat16 g_woh[(size_t)HID*QD],  g_wol[(size_t)HID*QD];
__device__ __nv_bfloat16 g_ah[(size_t)TOK*QD],   g_al[(size_t)TOK*QD];
__device__ __nv_bfloat16 g_kh[(size_t)TOK*KVD],  g_kl[(size_t)TOK*KVD];
__device__ __nv_bfloat16 g_vh[(size_t)TOK*KVD],  g_vl[(size_t)TOK*KVD];

// ===========================================================================
// PTX helpers
// ===========================================================================
__device__ __forceinline__ uint32_t smem_u32(const void* p) {
    uint32_t a;
    asm("{ .reg .u64 t; cvta.to.shared.u64 t, %1; cvt.u32.u64 %0, t; }" : "=r"(a) : "l"(p));
    return a;
}
__device__ __forceinline__ void cp_async16(uint32_t dst, const void* src) {
    asm volatile("cp.async.cg.shared.global [%0], [%1], 16;" :: "r"(dst), "l"(src) : "memory");
}
#define CP_COMMIT() asm volatile("cp.async.commit_group;" ::: "memory")
#define CP_WAIT(n)  asm volatile("cp.async.wait_group %0;" :: "n"(n) : "memory")

__device__ __forceinline__ void ldm4(uint32_t* r, uint32_t addr) {
    asm volatile("ldmatrix.sync.aligned.m8n8.x4.shared.b16 {%0,%1,%2,%3}, [%4];"
                 : "=r"(r[0]), "=r"(r[1]), "=r"(r[2]), "=r"(r[3]) : "r"(addr));
}
__device__ __forceinline__ void ldm4t(uint32_t* r, uint32_t addr) {
    asm volatile("ldmatrix.sync.aligned.m8n8.x4.trans.shared.b16 {%0,%1,%2,%3}, [%4];"
                 : "=r"(r[0]), "=r"(r[1]), "=r"(r[2]), "=r"(r[3]) : "r"(addr));
}
__device__ __forceinline__ void mma_bf16(float* c, const uint32_t* a, const uint32_t* b) {
    asm volatile("mma.sync.aligned.m16n8k16.row.col.f32.bf16.bf16.f32 "
                 "{%0,%1,%2,%3}, {%4,%5,%6,%7}, {%8,%9}, {%0,%1,%2,%3};"
                 : "+f"(c[0]), "+f"(c[1]), "+f"(c[2]), "+f"(c[3])
                 : "r"(a[0]), "r"(a[1]), "r"(a[2]), "r"(a[3]), "r"(b[0]), "r"(b[1]));
}
__device__ __forceinline__ uint32_t cvt2bf(float hi, float lo) {
    uint32_t r;
    asm("cvt.rn.bf16x2.f32 %0, %1, %2;" : "=r"(r) : "f"(hi), "f"(lo));
    return r;
}
__device__ __forceinline__ float bfloF(uint32_t p) { return __int_as_float(p << 16); }
__device__ __forceinline__ float bfhiF(uint32_t p) { return __int_as_float(p & 0xffff0000u); }

// fast 2^t on the FMA pipe (no MUFU); exp2(0) == 1.0 exactly
__device__ __forceinline__ float fast_exp2(float t) {
    t = fmaxf(t, -120.0f);
    float r = t + 12582912.0f;
    float n = r - 12582912.0f;
    float f = t - n;
    int   ni = __float_as_int(r);
    float p = 1.3392112e-3f;
    p = fmaf(p, f, 9.6183463e-3f);
    p = fmaf(p, f, 5.5503277e-2f);
    p = fmaf(p, f, 2.4022652e-1f);
    p = fmaf(p, f, 6.9314718e-1f);
    p = fmaf(p, f, 1.0f);
    return __int_as_float(__float_as_int(p) + (ni << 23));
}

// ===========================================================================
// Fused split: all five fp32->bf16(hi,lo) splits in one launch.
// ===========================================================================
#define SPL_N0 (TOK*HID)
#define SPL_N1 (SPL_N0 + QD*HID)
#define SPL_N2 (SPL_N1 + KVD*HID)
#define SPL_N3 (SPL_N2 + KVD*HID)
#define SPL_N4 (SPL_N3 + HID*QD)

__global__ void split_all_kernel(
    const float* __restrict__ x0, const float* __restrict__ x1,
    const float* __restrict__ x2, const float* __restrict__ x3,
    const float* __restrict__ x4,
    __nv_bfloat16* __restrict__ h0, __nv_bfloat16* __restrict__ l0,
    __nv_bfloat16* __restrict__ h1, __nv_bfloat16* __restrict__ l1,
    __nv_bfloat16* __restrict__ h2, __nv_bfloat16* __restrict__ l2,
    __nv_bfloat16* __restrict__ h3, __nv_bfloat16* __restrict__ l3,
    __nv_bfloat16* __restrict__ h4, __nv_bfloat16* __restrict__ l4)
{
    int i = blockIdx.x * 256 + threadIdx.x;
    if (i >= SPL_N4) return;
    const float* x; __nv_bfloat16 *h, *l; int off;
    if (i < SPL_N0)      { x = x0; h = h0; l = l0; off = i; }
    else if (i < SPL_N1) { x = x1; h = h1; l = l1; off = i - SPL_N0; }
    else if (i < SPL_N2) { x = x2; h = h2; l = l2; off = i - SPL_N1; }
    else if (i < SPL_N3) { x = x3; h = h3; l = l3; off = i - SPL_N2; }
    else                 { x = x4; h = h4; l = l4; off = i - SPL_N3; }
    float v = x[off];
    __nv_bfloat16 hv = __float2bfloat16(v);
    h[off] = hv;
    l[off] = __float2bfloat16(v - __bfloat162float(hv));
}

// ===========================================================================
// mma.sync split-bf16 GEMM mainloop: 128x128x32 tiles, 2-stage cp.async
// pipeline, 2 CTAs/SM (cross-CTA latency hiding), 8 warps (2x4), warp 64x32,
// 3-term split product. Race-free: refill issued only after a post-compute
// barrier confirms all warps drained the buffer.
// ===========================================================================
#define TSTR 40
#define TILE_B (128*TSTR*2)           // 10240
#define STAGE_B (4*TILE_B)            // 40960
#define GEMM_SMEM (2*STAGE_B)         // 81920 -> 2 CTAs/SM

__device__ __forceinline__ void gemm_issue_loads(
    uint32_t sstage, const __nv_bfloat16* pAh, const __nv_bfloat16* pAl,
    const __nv_bfloat16* pBh, const __nv_bfloat16* pBl, int K, int ko, int tid)
{
    #pragma unroll
    for (int i = 0; i < 2; i++) {
        int c = tid + (i << 8);
        int row = c >> 2;
        int kc  = c & 3;
        uint32_t dst = (uint32_t)(row * TSTR + kc * 8) * 2;
        size_t src = (size_t)row * K + ko + kc * 8;
        cp_async16(sstage + 0*TILE_B + dst, pAh + src);
        cp_async16(sstage + 1*TILE_B + dst, pAl + src);
        cp_async16(sstage + 2*TILE_B + dst, pBh + src);
        cp_async16(sstage + 3*TILE_B + dst, pBl + src);
    }
}

// Fills acc[4][4][4]; after return all cp.asyncs complete; caller must
// __syncthreads before reusing smem.
__device__ __forceinline__ void gemm_mainloop(
    const __nv_bfloat16* __restrict__ pAh, const __nv_bfloat16* __restrict__ pAl,
    const __nv_bfloat16* __restrict__ pBh, const __nv_bfloat16* __restrict__ pBl,
    int K, char* smem, float acc[4][4][4])
{
    uint32_t sbase = smem_u32(smem);
    const int tid  = threadIdx.x;
    const int lane = tid & 31;
    const int wid  = tid >> 5;
    const int wm   = wid >> 2;
    const int wn   = wid & 3;

    const uint32_t laneA = (uint32_t)((lane & 15) * TSTR + ((lane >> 4) << 3)) * 2;
    const uint32_t laneB = (uint32_t)(((lane & 7) + ((lane >> 4) << 3)) * TSTR
                                      + (((lane >> 3) & 1) << 3)) * 2;

    #pragma unroll
    for (int i = 0; i < 4; i++)
        #pragma unroll
        for (int j = 0; j < 4; j++)
            #pragma unroll
            for (int r = 0; r < 4; r++) acc[i][j][r] = 0.f;

    const int KT = K >> 5;
    gemm_issue_loads(sbase, pAh, pAl, pBh, pBl, K, 0, tid);
    CP_COMMIT();
    gemm_issue_loads(sbase + STAGE_B, pAh, pAl, pBh, pBl, K, 32, tid);
    CP_COMMIT();

    for (int kt = 0; kt < KT; kt++) {
        if (kt + 1 < KT) { CP_WAIT(1); } else { CP_WAIT(0); }
        __syncthreads();

        uint32_t st = sbase + (uint32_t)(kt & 1) * STAGE_B;
        uint32_t sAh = st, sAl = st + TILE_B, sBh = st + 2*TILE_B, sBl = st + 3*TILE_B;

        #pragma unroll
        for (int kk = 0; kk < 2; kk++) {
            uint32_t ah[4][4], al[4][4];
            #pragma unroll
            for (int mi = 0; mi < 4; mi++) {
                uint32_t aoff = (uint32_t)(((wm * 64 + mi * 16) * TSTR + kk * 16) * 2);
                ldm4(ah[mi], sAh + aoff + laneA);
                ldm4(al[mi], sAl + aoff + laneA);
            }
            uint32_t bh[4][2], bl[4][2];
            #pragma unroll
            for (int nj2 = 0; nj2 < 2; nj2++) {
                uint32_t boff = (uint32_t)(((wn * 32 + nj2 * 16) * TSTR + kk * 16) * 2);
                uint32_t r[4];
                ldm4(r, sBh + boff + laneB);
                bh[nj2*2][0] = r[0]; bh[nj2*2][1] = r[1];
                bh[nj2*2+1][0] = r[2]; bh[nj2*2+1][1] = r[3];
                ldm4(r, sBl + boff + laneB);
                bl[nj2*2][0] = r[0]; bl[nj2*2][1] = r[1];
                bl[nj2*2+1][0] = r[2]; bl[nj2*2+1][1] = r[3];
            }
            #pragma unroll
            for (int mi = 0; mi < 4; mi++)
                #pragma unroll
                for (int nj = 0; nj < 4; nj++) {
                    mma_bf16(acc[mi][nj], ah[mi], bh[nj]);
                    mma_bf16(acc[mi][nj], ah[mi], bl[nj]);
                    mma_bf16(acc[mi][nj], al[mi], bh[nj]);
                }
        }

        if (kt + 2 < KT) {
            __syncthreads();     // all warps drained buffer (kt&1)
            gemm_issue_loads(st, pAh, pAl, pBh, pBl, K, (kt + 2) << 5, tid);
            CP_COMMIT();
        }
    }
}

// fp32 epilogue (Q and O projections)
__device__ __forceinline__ void epilogue_f32(float acc[4][4][4], float* Ct, int N)
{
    const int lane = threadIdx.x & 31;
    const int wid  = threadIdx.x >> 5;
    const int wm = wid >> 2, wn = wid & 3;
    const int g = lane >> 2, tg = lane & 3;
    #pragma unroll
    for (int mi = 0; mi < 4; mi++) {
        int row = wm * 64 + mi * 16 + g;
        #pragma unroll
        for (int nj = 0; nj < 4; nj++) {
            int col = wn * 32 + nj * 8 + tg * 2;
            float* p0 = Ct + (size_t)row * N + col;
            float* p1 = p0 + (size_t)8 * N;
            p0[0] = acc[mi][nj][0]; p0[1] = acc[mi][nj][1];
            p1[0] = acc[mi][nj][2]; p1[1] = acc[mi][nj][3];
        }
    }
}

// Fused Q/K/V projection: grid (40, TOK/128). bx 0-31: Q (fp32 out);
// bx 32-35: K (rope + hi/lo split via smem staging); bx 36-39: V (hi/lo split).
__global__ void __launch_bounds__(256, 2)
gemm_qkv(const __nv_bfloat16* __restrict__ hh, const __nv_bfloat16* __restrict__ hl,
         const __nv_bfloat16* __restrict__ wqh, const __nv_bfloat16* __restrict__ wql,
         const __nv_bfloat16* __restrict__ wkh, const __nv_bfloat16* __restrict__ wkl,
         const __nv_bfloat16* __restrict__ wvh, const __nv_bfloat16* __restrict__ wvl,
         float* __restrict__ qb,
         __nv_bfloat16* __restrict__ kh, __nv_bfloat16* __restrict__ kl,
         __nv_bfloat16* __restrict__ vh, __nv_bfloat16* __restrict__ vl,
         const int* __restrict__ pos32)
{
    extern __shared__ char smem[];
    const int bx = blockIdx.x;
    const int bm = blockIdx.y << 7;
    const int tid = threadIdx.x;
    const __nv_bfloat16 *bhp, *blp;
    int bn;
    if (bx < 32)      { bhp = wqh; blp = wql; bn = bx << 7; }
    else if (bx < 36) { bhp = wkh; blp = wkl; bn = (bx - 32) << 7; }
    else              { bhp = wvh; blp = wvl; bn = (bx - 36) << 7; }

    float acc[4][4][4];
    gemm_mainloop(hh + (size_t)bm * HID, hl + (size_t)bm * HID,
                  bhp + (size_t)bn * HID, blp + (size_t)bn * HID,
                  HID, smem, acc);

    const int lane = tid & 31;
    const int wid  = tid >> 5;
    const int wm = wid >> 2, wn = wid & 3;
    const int g = lane >> 2, tg = lane & 3;

    if (bx < 32) {
        epilogue_f32(acc, qb + (size_t)bm * QD + bn, QD);
    } else if (bx < 36) {
        // K: stage acc to smem, then rope + hi/lo split
        float* sacc = (float*)smem;     // [128][132] = 67584 B <= 81920
        __syncthreads();                // mainloop smem reads done in all warps
        #pragma unroll
        for (int mi = 0; mi < 4; mi++) {
            int row = wm * 64 + mi * 16 + g;
            #pragma unroll
            for (int nj = 0; nj < 4; nj++) {
                int col = wn * 32 + nj * 8 + tg * 2;
                sacc[row * 132 + col]     = acc[mi][nj][0];
                sacc[row * 132 + col + 1] = acc[mi][nj][1];
                sacc[(row + 8) * 132 + col]     = acc[mi][nj][2];
                sacc[(row + 8) * 132 + col + 1] = acc[mi][nj][3];
            }
        }
        __syncthreads();
        const bool is64 = (pos32[1] == 0);
        #pragma unroll
        for (int i = 0; i < 32; i++) {
            int idx = tid + (i << 8);           // 0..8191
            int row = idx >> 6;                 // 0..127
            int d   = idx & 63;
            int t   = bm + row;
            int p = is64 ? pos32[2 * t] : pos32[t];
            float invf = powf(1.0e6f, -(float)d * (1.0f / 64.0f));
            float sv, cv;
            sincosf((float)p * invf, &sv, &cv);
            float x1 = sacc[row * 132 + d];
            float x2 = sacc[row * 132 + d + 64];
            float y1 = x1 * cv - x2 * sv;
            float y2 = x2 * cv + x1 * sv;
            __nv_bfloat16 h1 = __float2bfloat16(y1);
            __nv_bfloat16 h2 = __float2bfloat16(y2);
            size_t off = (size_t)t * KVD + bn + d;
            kh[off]      = h1; kl[off]      = __float2bfloat16(y1 - __bfloat162float(h1));
            kh[off + 64] = h2; kl[off + 64] = __float2bfloat16(y2 - __bfloat162float(h2));
        }
    } else {
        // V: split acc directly to bf16 hi/lo
        #pragma unroll
        for (int mi = 0; mi < 4; mi++) {
            int row = wm * 64 + mi * 16 + g;
            #pragma unroll
            for (int nj = 0; nj < 4; nj++) {
                int col = wn * 32 + nj * 8 + tg * 2;
                size_t off0 = (size_t)(bm + row) * KVD + bn + col;
                size_t off1 = off0 + (size_t)8 * KVD;
                float a0 = acc[mi][nj][0], a1 = acc[mi][nj][1];
                uint32_t hp = cvt2bf(a1, a0);
                uint32_t lp = cvt2bf(a1 - bfhiF(hp), a0 - bfloF(hp));
                *(uint32_t*)(vh + off0) = hp;
                *(uint32_t*)(vl + off0) = lp;
                float b0 = acc[mi][nj][2], b1 = acc[mi][nj][3];
                hp = cvt2bf(b1, b0);
                lp = cvt2bf(b1 - bfhiF(hp), b0 - bfloF(hp));
                *(uint32_t*)(vh + off1) = hp;
                *(uint32_t*)(vl + off1) = lp;
            }
        }
    }
}

// Generic NT split GEMM (O-projection)
__global__ void __launch_bounds__(256, 2)
gemm_nt_split(const __nv_bfloat16* __restrict__ Ah, const __nv_bfloat16* __restrict__ Al,
              const __nv_bfloat16* __restrict__ Bh, const __nv_bfloat16* __restrict__ Bl,
              float* __restrict__ C, int N, int K)
{
    extern __shared__ char smem[];
    const int bm = blockIdx.y << 7;
    const int bn = blockIdx.x << 7;
    float acc[4][4][4];
    gemm_mainloop(Ah + (size_t)bm * K, Al + (size_t)bm * K,
                  Bh + (size_t)bn * K, Bl + (size_t)bn * K, K, smem, acc);
    epilogue_f32(acc, C + (size_t)bm * N + bn, N);
}

// ===========================================================================
// Flash attention: mma.sync split-bf16, FMA-pipe exp2, non-causal.
// Q-RoPE fused into the Q-load. Epilogue writes split bf16 hi/lo directly.
// ===========================================================================
#define FSTR 136
#define FA_Q_B (128*FSTR*2)
#define FA_T_B (64*FSTR*2)
#define FA_ST_B (4*FA_T_B)
#define FA_SMEM (2*FA_Q_B + 2*FA_ST_B)    // 208896

__device__ __forceinline__ void fa_load_kv(
    uint32_t stage, const __nv_bfloat16* __restrict__ Kh, const __nv_bfloat16* __restrict__ Kl,
    const __nv_bfloat16* __restrict__ Vh, const __nv_bfloat16* __restrict__ Vl,
    size_t rowbase, int kvoff, int tid)
{
    #pragma unroll
    for (int comp = 0; comp < 4; comp++) {
        const __nv_bfloat16* g = (comp == 0) ? Kh : (comp == 1) ? Kl : (comp == 2) ? Vh : Vl;
        #pragma unroll
        for (int jj = 0; jj < 4; jj++) {
            int cc = tid + (jj << 8);
            int row = cc >> 4, kc = cc & 15;
            cp_async16(stage + comp * FA_T_B + (uint32_t)(row * 272 + kc * 16),
                       g + (rowbase + row) * KVD + kvoff + kc * 8);
        }
    }
}

__global__ void __launch_bounds__(256, 1)
flash_attn_mma(const float* __restrict__ Q, const int* __restrict__ pos32,
               const __nv_bfloat16* __restrict__ Kh, const __nv_bfloat16* __restrict__ Kl,
               const __nv_bfloat16* __restrict__ Vh, const __nv_bfloat16* __restrict__ Vl,
               __nv_bfloat16* __restrict__ ah, __nv_bfloat16* __restrict__ al)
{
    extern __shared__ char smem[];
    uint32_t sb = smem_u32(smem);
    const uint32_t sQH = sb;
    const uint32_t sQL = sb + FA_Q_B;
    const uint32_t sST = sb + 2 * FA_Q_B;

    const int tid = threadIdx.x, lane = tid & 31, w = tid >> 5;
    const int bh = blockIdx.y, b = bh >> 5, h = bh & 31, kvh = h >> 3;
    const int q0 = blockIdx.x << 7;
    const int g = lane >> 2, t = lane & 3;

    // --- Q load + RoPE + scale(1/sqrt(d)*log2e) + hi/lo split into smem ---
    const float qsc = 0.08838834764831843f * 1.4426950408889634f;
    const float* Qg = Q + (size_t)(b * SEQ + q0) * QD + h * HD;
    const bool is64 = (pos32[1] == 0);
    #pragma unroll
    for (int i = 0; i < 8; i++) {
        int idx = tid + (i << 8);
        int row = idx >> 4;
        int d4  = (idx & 15) << 2;
        int tok = b * SEQ + q0 + row;
        int p = is64 ? pos32[2 * tok] : pos32[tok];
        float4 xa = *(const float4*)(Qg + (size_t)row * QD + d4);
        float4 xb = *(const float4*)(Qg + (size_t)row * QD + d4 + 64);
        float ya[4], yb[4];
        const float* x1 = &xa.x;
        const float* x2 = &xb.x;
        #pragma unroll
        for (int j = 0; j < 4; j++) {
            int d = d4 + j;
            float invf = powf(1.0e6f, -(float)d * (1.0f / 64.0f));
            float sv, cv;
            sincosf((float)p * invf, &sv, &cv);
            ya[j] = (x1[j] * cv - x2[j] * sv) * qsc;
            yb[j] = (x2[j] * cv + x1[j] * sv) * qsc;
        }
        uint32_t ha01 = cvt2bf(ya[1], ya[0]);
        uint32_t ha23 = cvt2bf(ya[3], ya[2]);
        uint32_t la01 = cvt2bf(ya[1] - bfhiF(ha01), ya[0] - bfloF(ha01));
        uint32_t la23 = cvt2bf(ya[3] - bfhiF(ha23), ya[2] - bfloF(ha23));
        uint32_t hb01 = cvt2bf(yb[1], yb[0]);
        uint32_t hb23 = cvt2bf(yb[3], yb[2]);
        uint32_t lb01 = cvt2bf(yb[1] - bfhiF(hb01), yb[0] - bfloF(hb01));
        uint32_t lb23 = cvt2bf(yb[3] - bfhiF(hb23), yb[2] - bfloF(hb23));
        uint32_t off1 = (uint32_t)(row * 272 + d4 * 2);
        uint32_t off2 = (uint32_t)(row * 272 + (d4 + 64) * 2);
        *(uint2*)(smem + (sQH - sb) + off1) = make_uint2(ha01, ha23);
        *(uint2*)(smem + (sQL - sb) + off1) = make_uint2(la01, la23);
        *(uint2*)(smem + (sQH - sb) + off2) = make_uint2(hb01, hb23);
        *(uint2*)(smem + (sQL - sb) + off2) = make_uint2(lb01, lb23);
    }

    float m0 = -1e30f, m1 = -1e30f, l0 = 0.f, l1 = 0.f;
    float o[16][4];
    #pragma unroll
    for (int nd = 0; nd < 16; nd++)
        #pragma unroll
        for (int c = 0; c < 4; c++) o[nd][c] = 0.f;

    const size_t kvbase = (size_t)b * SEQ;
    const int kvoff = kvh * HD;

    const uint32_t lA = (uint32_t)(((lane & 15) * FSTR + ((lane >> 4) << 3)) * 2);
    const uint32_t lB = (uint32_t)((((lane & 7) + ((lane >> 4) << 3)) * FSTR
                                    + (((lane >> 3) & 1) << 3)) * 2);
    const uint32_t lV = (uint32_t)((((lane & 7) + (((lane >> 3) & 1) << 3)) * FSTR
                                    + (((lane >> 4) & 1) << 3)) * 2);

    fa_load_kv(sST, Kh, Kl, Vh, Vl, kvbase, kvoff, tid);
    CP_COMMIT();

    for (int kt = 0; kt < SEQ / 64; kt++) {
        if (kt + 1 < SEQ / 64) {
            fa_load_kv(sST + ((kt + 1) & 1) * FA_ST_B, Kh, Kl, Vh, Vl,
                       kvbase + (size_t)(kt + 1) * 64, kvoff, tid);
            CP_COMMIT();
            CP_WAIT(1);
        } else {
            CP_WAIT(0);
        }
        __syncthreads();

        const uint32_t st = sST + (kt & 1) * FA_ST_B;
        const uint32_t sKH = st, sKL = st + FA_T_B, sVH = st + 2*FA_T_B, sVL = st + 3*FA_T_B;

        float s[8][4];
        #pragma unroll
        for (int j = 0; j < 8; j++)
            #pragma unroll
            for (int c = 0; c < 4; c++) s[j][c] = 0.f;

        #pragma unroll
        for (int kk = 0; kk < 8; kk++) {
            uint32_t qh[4], ql[4];
            uint32_t qoff = (uint32_t)((w * 16 * FSTR + kk * 16) * 2);
            ldm4(qh, sQH + qoff + lA);
            ldm4(ql, sQL + qoff + lA);
            #pragma unroll
            for (int nj2 = 0; nj2 < 4; nj2++) {
                uint32_t koff = (uint32_t)((nj2 * 16 * FSTR + kk * 16) * 2);
                uint32_t rh[4], rl[4];
                ldm4(rh, sKH + koff + lB);
                ldm4(rl, sKL + koff + lB);
                mma_bf16(s[nj2*2],   qh, rh);     mma_bf16(s[nj2*2],   qh, rl);
                mma_bf16(s[nj2*2],   ql, rh);
                mma_bf16(s[nj2*2+1], qh, rh + 2); mma_bf16(s[nj2*2+1], qh, rl + 2);
                mma_bf16(s[nj2*2+1], ql, rh + 2);
            }
        }

        float mx0 = -1e30f, mx1 = -1e30f;
        #pragma unroll
        for (int j = 0; j < 8; j++) {
            mx0 = fmaxf(mx0, fmaxf(s[j][0], s[j][1]));
            mx1 = fmaxf(mx1, fmaxf(s[j][2], s[j][3]));
        }
        mx0 = fmaxf(mx0, __shfl_xor_sync(0xffffffffu, mx0, 1));
        mx0 = fmaxf(mx0, __shfl_xor_sync(0xffffffffu, mx0, 2));
        mx1 = fmaxf(mx1, __shfl_xor_sync(0xffffffffu, mx1, 1));
        mx1 = fmaxf(mx1, __shfl_xor_sync(0xffffffffu, mx1, 2));
        float mn0 = fmaxf(m0, mx0), mn1 = fmaxf(m1, mx1);

        // skip-rescale fast path: alpha == 1 exactly when no new max
        bool newmax = (mn0 > m0) || (mn1 > m1);
        if (__any_sync(0xffffffffu, newmax)) {
            float al0 = fast_exp2(m0 - mn0), al1 = fast_exp2(m1 - mn1);
            l0 *= al0; l1 *= al1;
            #pragma unroll
            for (int nd = 0; nd < 16; nd++) {
                o[nd][0] *= al0; o[nd][1] *= al0;
                o[nd][2] *= al1; o[nd][3] *= al1;
            }
        }
        m0 = mn0; m1 = mn1;

        uint32_t ph[4][4], pl[4][4];
        float sum0 = 0.f, sum1 = 0.f;
        #pragma unroll
        for (int j = 0; j < 8; j++) {
            float p00 = fast_exp2(s[j][0] - mn0);
            float p01 = fast_exp2(s[j][1] - mn0);
            float p10 = fast_exp2(s[j][2] - mn1);
            float p11 = fast_exp2(s[j][3] - mn1);
            sum0 += p00 + p01; sum1 += p10 + p11;
            uint32_t hA = cvt2bf(p01, p00);
            uint32_t hB = cvt2bf(p11, p10);
            uint32_t lAp = cvt2bf(p01 - bfhiF(hA), p00 - bfloF(hA));
            uint32_t lBp = cvt2bf(p11 - bfhiF(hB), p10 - bfloF(hB));
            int kk2 = j >> 1, hf = (j & 1) << 1;
            ph[kk2][hf]     = hA;  ph[kk2][hf + 1] = hB;
            pl[kk2][hf]     = lAp; pl[kk2][hf + 1] = lBp;
        }
        sum0 += __shfl_xor_sync(0xffffffffu, sum0, 1);
        sum0 += __shfl_xor_sync(0xffffffffu, sum0, 2);
        sum1 += __shfl_xor_sync(0xffffffffu, sum1, 1);
        sum1 += __shfl_xor_sync(0xffffffffu, sum1, 2);
        l0 += sum0;
        l1 += sum1;

        #pragma unroll
        for (int kk2 = 0; kk2 < 4; kk2++) {
            #pragma unroll
            for (int ndp = 0; ndp < 8; ndp++) {
                uint32_t voff = (uint32_t)((kk2 * 16 * FSTR + ndp * 16) * 2);
                uint32_t vh[4], vl[4];
                ldm4t(vh, sVH + voff + lV);
                ldm4t(vl, sVL + voff + lV);
                mma_bf16(o[ndp*2],   ph[kk2], vh);     mma_bf16(o[ndp*2],   ph[kk2], vl);
                mma_bf16(o[ndp*2],   pl[kk2], vh);
                mma_bf16(o[ndp*2+1], ph[kk2], vh + 2); mma_bf16(o[ndp*2+1], ph[kk2], vl + 2);
                mma_bf16(o[ndp*2+1], pl[kk2], vh + 2);
            }
        }
        __syncthreads();
    }

    float il0 = 1.f / l0, il1 = 1.f / l1;
    size_t rbase = (size_t)(b * SEQ + q0 + w * 16 + g) * QD + h * HD;
    __nv_bfloat16* AH = ah + rbase;
    __nv_bfloat16* AL = al + rbase;
    #pragma unroll
    for (int nd = 0; nd < 16; nd++) {
        int col = nd * 8 + t * 2;
        float a0 = o[nd][0] * il0, a1 = o[nd][1] * il0;
        uint32_t hp = cvt2bf(a1, a0);
        uint32_t lp = cvt2bf(a1 - bfhiF(hp), a0 - bfloF(hp));
        *(uint32_t*)(AH + col) = hp;
        *(uint32_t*)(AL + col) = lp;
        float b0 = o[nd][2] * il1, b1 = o[nd][3] * il1;
        hp = cvt2bf(b1, b0);
        lp = cvt2bf(b1 - bfhiF(hp), b0 - bfloF(hp));
        *(uint32_t*)(AH + (size_t)8 * QD + col) = hp;
        *(uint32_t*)(AL + (size_t)8 * QD + col) = lp;
    }
}

// ---------------------------------------------------------------------------
extern "C" void kernel_launch(void* const* d_in, const int* in_sizes, int n_in,
                              void* d_out, int out_size)
{
    const float* hidden = (const float*)d_in[0];
    const int*   pos    = (const int*)d_in[1];
    const float* Wq     = (const float*)d_in[2];
    const float* Wk     = (const float*)d_in[3];
    const float* Wv     = (const float*)d_in[4];
    const float* Wo     = (const float*)d_in[5];
    float*       out    = (float*)d_out;

    float *qb;
    cudaGetSymbolAddress((void**)&qb, g_q);
    __nv_bfloat16 *hh,*hl,*wqh,*wql,*wkh,*wkl,*wvh,*wvl,*woh,*wol,*ah,*al,*kh,*kl,*vh,*vl;
    cudaGetSymbolAddress((void**)&hh,  g_hh);  cudaGetSymbolAddress((void**)&hl,  g_hl);
    cudaGetSymbolAddress((void**)&wqh, g_wqh); cudaGetSymbolAddress((void**)&wql, g_wql);
    cudaGetSymbolAddress((void**)&wkh, g_wkh); cudaGetSymbolAddress((void**)&wkl, g_wkl);
    cudaGetSymbolAddress((void**)&wvh, g_wvh); cudaGetSymbolAddress((void**)&wvl, g_wvl);
    cudaGetSymbolAddress((void**)&woh, g_woh); cudaGetSymbolAddress((void**)&wol, g_wol);
    cudaGetSymbolAddress((void**)&ah,  g_ah);  cudaGetSymbolAddress((void**)&al,  g_al);
    cudaGetSymbolAddress((void**)&kh,  g_kh);  cudaGetSymbolAddress((void**)&kl,  g_kl);
    cudaGetSymbolAddress((void**)&vh,  g_vh);  cudaGetSymbolAddress((void**)&vl,  g_vl);

    cudaFuncSetAttribute(gemm_qkv, cudaFuncAttributeMaxDynamicSharedMemorySize, GEMM_SMEM);
    cudaFuncSetAttribute(gemm_nt_split, cudaFuncAttributeMaxDynamicSharedMemorySize, GEMM_SMEM);
    cudaFuncSetAttribute(flash_attn_mma, cudaFuncAttributeMaxDynamicSharedMemorySize, FA_SMEM);

    // All input/weight splits in one launch
    split_all_kernel<<<(SPL_N4 + 255)/256, 256>>>(hidden, Wq, Wk, Wv, Wo,
                                                  hh, hl, wqh, wql, wkh, wkl,
                                                  wvh, wvl, woh, wol);

    // Fused Q/K/V projections (128x128, 2-stage, 2 CTAs/SM)
    gemm_qkv<<<dim3(40, TOK/128), 256, GEMM_SMEM>>>(hh, hl, wqh, wql, wkh, wkl, wvh, wvl,
                                                    qb, kh, kl, vh, vl, pos);

    // Flash attention (Q rope fused) -> split bf16 output
    flash_attn_mma<<<dim3(SEQ/128, BATCH*NH), 256, FA_SMEM>>>(qb, pos, kh, kl, vh, vl, ah, al);

    // O projection (128x128, 2-stage, 2 CTAs/SM)
    gemm_nt_split<<<dim3(HID/128, TOK/128), 256, GEMM_SMEM>>>(ah, al, woh, wol, out, HID, QD);
}

// round 12
// speedup vs baseline: 1.0771x; 1.0012x over previous
#include <cuda_runtime.h>
#include <cuda_bf16.h>
#include <math.h>
#include <stdint.h>

// Problem constants
#define BATCH 2
#define SEQ 2048
#define TOK (BATCH*SEQ)          // 4096
#define HID 3584
#define NH 32
#define NKV 4
#define HD 128
#define QD (NH*HD)               // 4096
#define KVD (NKV*HD)             // 512

// fp32 scratch
__device__ float g_q[(size_t)TOK*QD];
// split-bf16 scratch
__device__ __nv_bfloat16 g_hh[(size_t)TOK*HID],  g_hl[(size_t)TOK*HID];
__device__ __nv_bfloat16 g_wqh[(size_t)QD*HID],  g_wql[(size_t)QD*HID];
__device__ __nv_bfloat16 g_wkh[(size_t)KVD*HID], g_wkl[(size_t)KVD*HID];
__device__ __nv_bfloat16 g_wvh[(size_t)KVD*HID], g_wvl[(size_t)KVD*HID];
__device__ __nv_bfloat16 g_woh[(size_t)HID*QD],  g_wol[(size_t)HID*QD];
__device__ __nv_bfloat16 g_ah[(size_t)TOK*QD],   g_al[(size_t)TOK*QD];
__device__ __nv_bfloat16 g_kh[(size_t)TOK*KVD],  g_kl[(size_t)TOK*KVD];
__device__ __nv_bfloat16 g_vh[(size_t)TOK*KVD],  g_vl[(size_t)TOK*KVD];

// ===========================================================================
// PTX helpers
// ===========================================================================
__device__ __forceinline__ uint32_t smem_u32(const void* p) {
    uint32_t a;
    asm("{ .reg .u64 t; cvta.to.shared.u64 t, %1; cvt.u32.u64 %0, t; }" : "=r"(a) : "l"(p));
    return a;
}
__device__ __forceinline__ void cp_async16(uint32_t dst, const void* src) {
    asm volatile("cp.async.cg.shared.global [%0], [%1], 16;" :: "r"(dst), "l"(src) : "memory");
}
#define CP_COMMIT() asm volatile("cp.async.commit_group;" ::: "memory")
#define CP_WAIT(n)  asm volatile("cp.async.wait_group %0;" :: "n"(n) : "memory")

__device__ __forceinline__ void ldm4(uint32_t* r, uint32_t addr) {
    asm volatile("ldmatrix.sync.aligned.m8n8.x4.shared.b16 {%0,%1,%2,%3}, [%4];"
                 : "=r"(r[0]), "=r"(r[1]), "=r"(r[2]), "=r"(r[3]) : "r"(addr));
}
__device__ __forceinline__ void ldm4t(uint32_t* r, uint32_t addr) {
    asm volatile("ldmatrix.sync.aligned.m8n8.x4.trans.shared.b16 {%0,%1,%2,%3}, [%4];"
                 : "=r"(r[0]), "=r"(r[1]), "=r"(r[2]), "=r"(r[3]) : "r"(addr));
}
__device__ __forceinline__ void mma_bf16(float* c, const uint32_t* a, const uint32_t* b) {
    asm volatile("mma.sync.aligned.m16n8k16.row.col.f32.bf16.bf16.f32 "
                 "{%0,%1,%2,%3}, {%4,%5,%6,%7}, {%8,%9}, {%0,%1,%2,%3};"
                 : "+f"(c[0]), "+f"(c[1]), "+f"(c[2]), "+f"(c[3])
                 : "r"(a[0]), "r"(a[1]), "r"(a[2]), "r"(a[3]), "r"(b[0]), "r"(b[1]));
}
__device__ __forceinline__ uint32_t cvt2bf(float hi, float lo) {
    uint32_t r;
    asm("cvt.rn.bf16x2.f32 %0, %1, %2;" : "=r"(r) : "f"(hi), "f"(lo));
    return r;
}
__device__ __forceinline__ float bfloF(uint32_t p) { return __int_as_float(p << 16); }
__device__ __forceinline__ float bfhiF(uint32_t p) { return __int_as_float(p & 0xffff0000u); }

// fast 2^t on the FMA pipe (no MUFU); exp2(0) == 1.0 exactly
__device__ __forceinline__ float fast_exp2(float t) {
    t = fmaxf(t, -120.0f);
    float r = t + 12582912.0f;
    float n = r - 12582912.0f;
    float f = t - n;
    int   ni = __float_as_int(r);
    float p = 1.3392112e-3f;
    p = fmaf(p, f, 9.6183463e-3f);
    p = fmaf(p, f, 5.5503277e-2f);
    p = fmaf(p, f, 2.4022652e-1f);
    p = fmaf(p, f, 6.9314718e-1f);
    p = fmaf(p, f, 1.0f);
    return __int_as_float(__float_as_int(p) + (ni << 23));
}

// ===========================================================================
// Fused split: all five fp32->bf16(hi,lo) splits in one launch.
// ===========================================================================
#define SPL_N0 (TOK*HID)
#define SPL_N1 (SPL_N0 + QD*HID)
#define SPL_N2 (SPL_N1 + KVD*HID)
#define SPL_N3 (SPL_N2 + KVD*HID)
#define SPL_N4 (SPL_N3 + HID*QD)

__global__ void split_all_kernel(
    const float* __restrict__ x0, const float* __restrict__ x1,
    const float* __restrict__ x2, const float* __restrict__ x3,
    const float* __restrict__ x4,
    __nv_bfloat16* __restrict__ h0, __nv_bfloat16* __restrict__ l0,
    __nv_bfloat16* __restrict__ h1, __nv_bfloat16* __restrict__ l1,
    __nv_bfloat16* __restrict__ h2, __nv_bfloat16* __restrict__ l2,
    __nv_bfloat16* __restrict__ h3, __nv_bfloat16* __restrict__ l3,
    __nv_bfloat16* __restrict__ h4, __nv_bfloat16* __restrict__ l4)
{
    int i = blockIdx.x * 256 + threadIdx.x;
    if (i >= SPL_N4) return;
    const float* x; __nv_bfloat16 *h, *l; int off;
    if (i < SPL_N0)      { x = x0; h = h0; l = l0; off = i; }
    else if (i < SPL_N1) { x = x1; h = h1; l = l1; off = i - SPL_N0; }
    else if (i < SPL_N2) { x = x2; h = h2; l = l2; off = i - SPL_N1; }
    else if (i < SPL_N3) { x = x3; h = h3; l = l3; off = i - SPL_N2; }
    else                 { x = x4; h = h4; l = l4; off = i - SPL_N3; }
    float v = x[off];
    __nv_bfloat16 hv = __float2bfloat16(v);
    h[off] = hv;
    l[off] = __float2bfloat16(v - __bfloat162float(hv));
}

// ===========================================================================
// mma.sync split-bf16 GEMM mainloop: 128x128x32 tiles, 2-stage cp.async
// pipeline, 2 CTAs/SM, 8 warps (2x4), warp 64x32.
// Term-major MMA ordering: accumulator reuse distance 16 (not 1) to break
// HMMA RAW chains. Per-accumulator addition order unchanged (bit-identical).
// ===========================================================================
#define TSTR 40
#define TILE_B (128*TSTR*2)           // 10240
#define STAGE_B (4*TILE_B)            // 40960
#define GEMM_SMEM (2*STAGE_B)         // 81920 -> 2 CTAs/SM

__device__ __forceinline__ void gemm_issue_loads(
    uint32_t sstage, const __nv_bfloat16* pAh, const __nv_bfloat16* pAl,
    const __nv_bfloat16* pBh, const __nv_bfloat16* pBl, int K, int ko, int tid)
{
    #pragma unroll
    for (int i = 0; i < 2; i++) {
        int c = tid + (i << 8);
        int row = c >> 2;
        int kc  = c & 3;
        uint32_t dst = (uint32_t)(row * TSTR + kc * 8) * 2;
        size_t src = (size_t)row * K + ko + kc * 8;
        cp_async16(sstage + 0*TILE_B + dst, pAh + src);
        cp_async16(sstage + 1*TILE_B + dst, pAl + src);
        cp_async16(sstage + 2*TILE_B + dst, pBh + src);
        cp_async16(sstage + 3*TILE_B + dst, pBl + src);
    }
}

// Fills acc[4][4][4]; after return all cp.asyncs complete; caller must
// __syncthreads before reusing smem.
__device__ __forceinline__ void gemm_mainloop(
    const __nv_bfloat16* __restrict__ pAh, const __nv_bfloat16* __restrict__ pAl,
    const __nv_bfloat16* __restrict__ pBh, const __nv_bfloat16* __restrict__ pBl,
    int K, char* smem, float acc[4][4][4])
{
    uint32_t sbase = smem_u32(smem);
    const int tid  = threadIdx.x;
    const int lane = tid & 31;
    const int wid  = tid >> 5;
    const int wm   = wid >> 2;
    const int wn   = wid & 3;

    const uint32_t laneA = (uint32_t)((lane & 15) * TSTR + ((lane >> 4) << 3)) * 2;
    const uint32_t laneB = (uint32_t)(((lane & 7) + ((lane >> 4) << 3)) * TSTR
                                      + (((lane >> 3) & 1) << 3)) * 2;

    #pragma unroll
    for (int i = 0; i < 4; i++)
        #pragma unroll
        for (int j = 0; j < 4; j++)
            #pragma unroll
            for (int r = 0; r < 4; r++) acc[i][j][r] = 0.f;

    const int KT = K >> 5;
    gemm_issue_loads(sbase, pAh, pAl, pBh, pBl, K, 0, tid);
    CP_COMMIT();
    gemm_issue_loads(sbase + STAGE_B, pAh, pAl, pBh, pBl, K, 32, tid);
    CP_COMMIT();

    for (int kt = 0; kt < KT; kt++) {
        if (kt + 1 < KT) { CP_WAIT(1); } else { CP_WAIT(0); }
        __syncthreads();

        uint32_t st = sbase + (uint32_t)(kt & 1) * STAGE_B;
        uint32_t sAh = st, sAl = st + TILE_B, sBh = st + 2*TILE_B, sBl = st + 3*TILE_B;

        #pragma unroll
        for (int kk = 0; kk < 2; kk++) {
            uint32_t ah[4][4], al[4][4];
            #pragma unroll
            for (int mi = 0; mi < 4; mi++) {
                uint32_t aoff = (uint32_t)(((wm * 64 + mi * 16) * TSTR + kk * 16) * 2);
                ldm4(ah[mi], sAh + aoff + laneA);
                ldm4(al[mi], sAl + aoff + laneA);
            }
            uint32_t bh[4][2], bl[4][2];
            #pragma unroll
            for (int nj2 = 0; nj2 < 2; nj2++) {
                uint32_t boff = (uint32_t)(((wn * 32 + nj2 * 16) * TSTR + kk * 16) * 2);
                uint32_t r[4];
                ldm4(r, sBh + boff + laneB);
                bh[nj2*2][0] = r[0]; bh[nj2*2][1] = r[1];
                bh[nj2*2+1][0] = r[2]; bh[nj2*2+1][1] = r[3];
                ldm4(r, sBl + boff + laneB);
                bl[nj2*2][0] = r[0]; bl[nj2*2][1] = r[1];
                bl[nj2*2+1][0] = r[2]; bl[nj2*2+1][1] = r[3];
            }
            // Term-major: 16 distinct accumulators between reuses.
            // Per-acc addition order preserved: hh, then hl, then lh.
            #pragma unroll
            for (int mi = 0; mi < 4; mi++)
                #pragma unroll
                for (int nj = 0; nj < 4; nj++)
                    mma_bf16(acc[mi][nj], ah[mi], bh[nj]);
            #pragma unroll
            for (int mi = 0; mi < 4; mi++)
                #pragma unroll
                for (int nj = 0; nj < 4; nj++)
                    mma_bf16(acc[mi][nj], ah[mi], bl[nj]);
            #pragma unroll
            for (int mi = 0; mi < 4; mi++)
                #pragma unroll
                for (int nj = 0; nj < 4; nj++)
                    mma_bf16(acc[mi][nj], al[mi], bh[nj]);
        }

        if (kt + 2 < KT) {
            __syncthreads();     // all warps drained buffer (kt&1)
            gemm_issue_loads(st, pAh, pAl, pBh, pBl, K, (kt + 2) << 5, tid);
            CP_COMMIT();
        }
    }
}

// fp32 epilogue (Q and O projections)
__device__ __forceinline__ void epilogue_f32(float acc[4][4][4], float* Ct, int N)
{
    const int lane = threadIdx.x & 31;
    const int wid  = threadIdx.x >> 5;
    const int wm = wid >> 2, wn = wid & 3;
    const int g = lane >> 2, tg = lane & 3;
    #pragma unroll
    for (int mi = 0; mi < 4; mi++) {
        int row = wm * 64 + mi * 16 + g;
        #pragma unroll
        for (int nj = 0; nj < 4; nj++) {
            int col = wn * 32 + nj * 8 + tg * 2;
            float* p0 = Ct + (size_t)row * N + col;
            float* p1 = p0 + (size_t)8 * N;
            p0[0] = acc[mi][nj][0]; p0[1] = acc[mi][nj][1];
            p1[0] = acc[mi][nj][2]; p1[1] = acc[mi][nj][3];
        }
    }
}

// Fused Q/K/V projection: grid (40, TOK/128). bx 0-31: Q (fp32 out);
// bx 32-35: K (rope + hi/lo split via smem staging); bx 36-39: V (hi/lo split).
__global__ void __launch_bounds__(256, 2)
gemm_qkv(const __nv_bfloat16* __restrict__ hh, const __nv_bfloat16* __restrict__ hl,
         const __nv_bfloat16* __restrict__ wqh, const __nv_bfloat16* __restrict__ wql,
         const __nv_bfloat16* __restrict__ wkh, const __nv_bfloat16* __restrict__ wkl,
         const __nv_bfloat16* __restrict__ wvh, const __nv_bfloat16* __restrict__ wvl,
         float* __restrict__ qb,
         __nv_bfloat16* __restrict__ kh, __nv_bfloat16* __restrict__ kl,
         __nv_bfloat16* __restrict__ vh, __nv_bfloat16* __restrict__ vl,
         const int* __restrict__ pos32)
{
    extern __shared__ char smem[];
    const int bx = blockIdx.x;
    const int bm = blockIdx.y << 7;
    const int tid = threadIdx.x;
    const __nv_bfloat16 *bhp, *blp;
    int bn;
    if (bx < 32)      { bhp = wqh; blp = wql; bn = bx << 7; }
    else if (bx < 36) { bhp = wkh; blp = wkl; bn = (bx - 32) << 7; }
    else              { bhp = wvh; blp = wvl; bn = (bx - 36) << 7; }

    float acc[4][4][4];
    gemm_mainloop(hh + (size_t)bm * HID, hl + (size_t)bm * HID,
                  bhp + (size_t)bn * HID, blp + (size_t)bn * HID,
                  HID, smem, acc);

    const int lane = tid & 31;
    const int wid  = tid >> 5;
    const int wm = wid >> 2, wn = wid & 3;
    const int g = lane >> 2, tg = lane & 3;

    if (bx < 32) {
        epilogue_f32(acc, qb + (size_t)bm * QD + bn, QD);
    } else if (bx < 36) {
        // K: stage acc to smem, then rope + hi/lo split
        float* sacc = (float*)smem;     // [128][132] = 67584 B <= 81920
        __syncthreads();                // mainloop smem reads done in all warps
        #pragma unroll
        for (int mi = 0; mi < 4; mi++) {
            int row = wm * 64 + mi * 16 + g;
            #pragma unroll
            for (int nj = 0; nj < 4; nj++) {
                int col = wn * 32 + nj * 8 + tg * 2;
                sacc[row * 132 + col]     = acc[mi][nj][0];
                sacc[row * 132 + col + 1] = acc[mi][nj][1];
                sacc[(row + 8) * 132 + col]     = acc[mi][nj][2];
                sacc[(row + 8) * 132 + col + 1] = acc[mi][nj][3];
            }
        }
        __syncthreads();
        const bool is64 = (pos32[1] == 0);
        #pragma unroll
        for (int i = 0; i < 32; i++) {
            int idx = tid + (i << 8);           // 0..8191
            int row = idx >> 6;                 // 0..127
            int d   = idx & 63;
            int t   = bm + row;
            int p = is64 ? pos32[2 * t] : pos32[t];
            float invf = powf(1.0e6f, -(float)d * (1.0f / 64.0f));
            float sv, cv;
            sincosf((float)p * invf, &sv, &cv);
            float x1 = sacc[row * 132 + d];
            float x2 = sacc[row * 132 + d + 64];
            float y1 = x1 * cv - x2 * sv;
            float y2 = x2 * cv + x1 * sv;
            __nv_bfloat16 h1 = __float2bfloat16(y1);
            __nv_bfloat16 h2 = __float2bfloat16(y2);
            size_t off = (size_t)t * KVD + bn + d;
            kh[off]      = h1; kl[off]      = __float2bfloat16(y1 - __bfloat162float(h1));
            kh[off + 64] = h2; kl[off + 64] = __float2bfloat16(y2 - __bfloat162float(h2));
        }
    } else {
        // V: split acc directly to bf16 hi/lo
        #pragma unroll
        for (int mi = 0; mi < 4; mi++) {
            int row = wm * 64 + mi * 16 + g;
            #pragma unroll
            for (int nj = 0; nj < 4; nj++) {
                int col = wn * 32 + nj * 8 + tg * 2;
                size_t off0 = (size_t)(bm + row) * KVD + bn + col;
                size_t off1 = off0 + (size_t)8 * KVD;
                float a0 = acc[mi][nj][0], a1 = acc[mi][nj][1];
                uint32_t hp = cvt2bf(a1, a0);
                uint32_t lp = cvt2bf(a1 - bfhiF(hp), a0 - bfloF(hp));
                *(uint32_t*)(vh + off0) = hp;
                *(uint32_t*)(vl + off0) = lp;
                float b0 = acc[mi][nj][2], b1 = acc[mi][nj][3];
                hp = cvt2bf(b1, b0);
                lp = cvt2bf(b1 - bfhiF(hp), b0 - bfloF(hp));
                *(uint32_t*)(vh + off1) = hp;
                *(uint32_t*)(vl + off1) = lp;
            }
        }
    }
}

// Generic NT split GEMM (O-projection)
__global__ void __launch_bounds__(256, 2)
gemm_nt_split(const __nv_bfloat16* __restrict__ Ah, const __nv_bfloat16* __restrict__ Al,
              const __nv_bfloat16* __restrict__ Bh, const __nv_bfloat16* __restrict__ Bl,
              float* __restrict__ C, int N, int K)
{
    extern __shared__ char smem[];
    const int bm = blockIdx.y << 7;
    const int bn = blockIdx.x << 7;
    float acc[4][4][4];
    gemm_mainloop(Ah + (size_t)bm * K, Al + (size_t)bm * K,
                  Bh + (size_t)bn * K, Bl + (size_t)bn * K, K, smem, acc);
    epilogue_f32(acc, C + (size_t)bm * N + bn, N);
}

// ===========================================================================
// Flash attention: mma.sync split-bf16, FMA-pipe exp2, non-causal.
// Q-RoPE fused into the Q-load. Epilogue writes split bf16 hi/lo directly.
// MMA pairs interleaved across the two output columns (reuse distance 2).
// ===========================================================================
#define FSTR 136
#define FA_Q_B (128*FSTR*2)
#define FA_T_B (64*FSTR*2)
#define FA_ST_B (4*FA_T_B)
#define FA_SMEM (2*FA_Q_B + 2*FA_ST_B)    // 208896

__device__ __forceinline__ void fa_load_kv(
    uint32_t stage, const __nv_bfloat16* __restrict__ Kh, const __nv_bfloat16* __restrict__ Kl,
    const __nv_bfloat16* __restrict__ Vh, const __nv_bfloat16* __restrict__ Vl,
    size_t rowbase, int kvoff, int tid)
{
    #pragma unroll
    for (int comp = 0; comp < 4; comp++) {
        const __nv_bfloat16* g = (comp == 0) ? Kh : (comp == 1) ? Kl : (comp == 2) ? Vh : Vl;
        #pragma unroll
        for (int jj = 0; jj < 4; jj++) {
            int cc = tid + (jj << 8);
            int row = cc >> 4, kc = cc & 15;
            cp_async16(stage + comp * FA_T_B + (uint32_t)(row * 272 + kc * 16),
                       g + (rowbase + row) * KVD + kvoff + kc * 8);
        }
    }
}

__global__ void __launch_bounds__(256, 1)
flash_attn_mma(const float* __restrict__ Q, const int* __restrict__ pos32,
               const __nv_bfloat16* __restrict__ Kh, const __nv_bfloat16* __restrict__ Kl,
               const __nv_bfloat16* __restrict__ Vh, const __nv_bfloat16* __restrict__ Vl,
               __nv_bfloat16* __restrict__ ah, __nv_bfloat16* __restrict__ al)
{
    extern __shared__ char smem[];
    uint32_t sb = smem_u32(smem);
    const uint32_t sQH = sb;
    const uint32_t sQL = sb + FA_Q_B;
    const uint32_t sST = sb + 2 * FA_Q_B;

    const int tid = threadIdx.x, lane = tid & 31, w = tid >> 5;
    const int bh = blockIdx.y, b = bh >> 5, h = bh & 31, kvh = h >> 3;
    const int q0 = blockIdx.x << 7;
    const int g = lane >> 2, t = lane & 3;

    // --- Q load + RoPE + scale(1/sqrt(d)*log2e) + hi/lo split into smem ---
    const float qsc = 0.08838834764831843f * 1.4426950408889634f;
    const float* Qg = Q + (size_t)(b * SEQ + q0) * QD + h * HD;
    const bool is64 = (pos32[1] == 0);
    #pragma unroll
    for (int i = 0; i < 8; i++) {
        int idx = tid + (i << 8);
        int row = idx >> 4;
        int d4  = (idx & 15) << 2;
        int tok = b * SEQ + q0 + row;
        int p = is64 ? pos32[2 * tok] : pos32[tok];
        float4 xa = *(const float4*)(Qg + (size_t)row * QD + d4);
        float4 xb = *(const float4*)(Qg + (size_t)row * QD + d4 + 64);
        float ya[4], yb[4];
        const float* x1 = &xa.x;
        const float* x2 = &xb.x;
        #pragma unroll
        for (int j = 0; j < 4; j++) {
            int d = d4 + j;
            float invf = powf(1.0e6f, -(float)d * (1.0f / 64.0f));
            float sv, cv;
            sincosf((float)p * invf, &sv, &cv);
            ya[j] = (x1[j] * cv - x2[j] * sv) * qsc;
            yb[j] = (x2[j] * cv + x1[j] * sv) * qsc;
        }
        uint32_t ha01 = cvt2bf(ya[1], ya[0]);
        uint32_t ha23 = cvt2bf(ya[3], ya[2]);
        uint32_t la01 = cvt2bf(ya[1] - bfhiF(ha01), ya[0] - bfloF(ha01));
        uint32_t la23 = cvt2bf(ya[3] - bfhiF(ha23), ya[2] - bfloF(ha23));
        uint32_t hb01 = cvt2bf(yb[1], yb[0]);
        uint32_t hb23 = cvt2bf(yb[3], yb[2]);
        uint32_t lb01 = cvt2bf(yb[1] - bfhiF(hb01), yb[0] - bfloF(hb01));
        uint32_t lb23 = cvt2bf(yb[3] - bfhiF(hb23), yb[2] - bfloF(hb23));
        uint32_t off1 = (uint32_t)(row * 272 + d4 * 2);
        uint32_t off2 = (uint32_t)(row * 272 + (d4 + 64) * 2);
        *(uint2*)(smem + (sQH - sb) + off1) = make_uint2(ha01, ha23);
        *(uint2*)(smem + (sQL - sb) + off1) = make_uint2(la01, la23);
        *(uint2*)(smem + (sQH - sb) + off2) = make_uint2(hb01, hb23);
        *(uint2*)(smem + (sQL - sb) + off2) = make_uint2(lb01, lb23);
    }

    float m0 = -1e30f, m1 = -1e30f, l0 = 0.f, l1 = 0.f;
    float o[16][4];
    #pragma unroll
    for (int nd = 0; nd < 16; nd++)
        #pragma unroll
        for (int c = 0; c < 4; c++) o[nd][c] = 0.f;

    const size_t kvbase = (size_t)b * SEQ;
    const int kvoff = kvh * HD;

    const uint32_t lA = (uint32_t)(((lane & 15) * FSTR + ((lane >> 4) << 3)) * 2);
    const uint32_t lB = (uint32_t)((((lane & 7) + ((lane >> 4) << 3)) * FSTR
                                    + (((lane >> 3) & 1) << 3)) * 2);
    const uint32_t lV = (uint32_t)((((lane & 7) + (((lane >> 3) & 1) << 3)) * FSTR
                                    + (((lane >> 4) & 1) << 3)) * 2);

    fa_load_kv(sST, Kh, Kl, Vh, Vl, kvbase, kvoff, tid);
    CP_COMMIT();

    for (int kt = 0; kt < SEQ / 64; kt++) {
        if (kt + 1 < SEQ / 64) {
            fa_load_kv(sST + ((kt + 1) & 1) * FA_ST_B, Kh, Kl, Vh, Vl,
                       kvbase + (size_t)(kt + 1) * 64, kvoff, tid);
            CP_COMMIT();
            CP_WAIT(1);
        } else {
            CP_WAIT(0);
        }
        __syncthreads();

        const uint32_t st = sST + (kt & 1) * FA_ST_B;
        const uint32_t sKH = st, sKL = st + FA_T_B, sVH = st + 2*FA_T_B, sVL = st + 3*FA_T_B;

        float s[8][4];
        #pragma unroll
        for (int j = 0; j < 8; j++)
            #pragma unroll
            for (int c = 0; c < 4; c++) s[j][c] = 0.f;

        #pragma unroll
        for (int kk = 0; kk < 8; kk++) {
            uint32_t qh[4], ql[4];
            uint32_t qoff = (uint32_t)((w * 16 * FSTR + kk * 16) * 2);
            ldm4(qh, sQH + qoff + lA);
            ldm4(ql, sQL + qoff + lA);
            #pragma unroll
            for (int nj2 = 0; nj2 < 4; nj2++) {
                uint32_t koff = (uint32_t)((nj2 * 16 * FSTR + kk * 16) * 2);
                uint32_t rh[4], rl[4];
                ldm4(rh, sKH + koff + lB);
                ldm4(rl, sKL + koff + lB);
                // interleave the two output columns: reuse distance 2
                mma_bf16(s[nj2*2],   qh, rh);     mma_bf16(s[nj2*2+1], qh, rh + 2);
                mma_bf16(s[nj2*2],   qh, rl);     mma_bf16(s[nj2*2+1], qh, rl + 2);
                mma_bf16(s[nj2*2],   ql, rh);     mma_bf16(s[nj2*2+1], ql, rh + 2);
            }
        }

        float mx0 = -1e30f, mx1 = -1e30f;
        #pragma unroll
        for (int j = 0; j < 8; j++) {
            mx0 = fmaxf(mx0, fmaxf(s[j][0], s[j][1]));
            mx1 = fmaxf(mx1, fmaxf(s[j][2], s[j][3]));
        }
        mx0 = fmaxf(mx0, __shfl_xor_sync(0xffffffffu, mx0, 1));
        mx0 = fmaxf(mx0, __shfl_xor_sync(0xffffffffu, mx0, 2));
        mx1 = fmaxf(mx1, __shfl_xor_sync(0xffffffffu, mx1, 1));
        mx1 = fmaxf(mx1, __shfl_xor_sync(0xffffffffu, mx1, 2));
        float mn0 = fmaxf(m0, mx0), mn1 = fmaxf(m1, mx1);

        // skip-rescale fast path: alpha == 1 exactly when no new max
        bool newmax = (mn0 > m0) || (mn1 > m1);
        if (__any_sync(0xffffffffu, newmax)) {
            float al0 = fast_exp2(m0 - mn0), al1 = fast_exp2(m1 - mn1);
            l0 *= al0; l1 *= al1;
            #pragma unroll
            for (int nd = 0; nd < 16; nd++) {
                o[nd][0] *= al0; o[nd][1] *= al0;
                o[nd][2] *= al1; o[nd][3] *= al1;
            }
        }
        m0 = mn0; m1 = mn1;

        uint32_t ph[4][4], pl[4][4];
        float sum0 = 0.f, sum1 = 0.f;
        #pragma unroll
        for (int j = 0; j < 8; j++) {
            float p00 = fast_exp2(s[j][0] - mn0);
            float p01 = fast_exp2(s[j][1] - mn0);
            float p10 = fast_exp2(s[j][2] - mn1);
            float p11 = fast_exp2(s[j][3] - mn1);
            sum0 += p00 + p01; sum1 += p10 + p11;
            uint32_t hA = cvt2bf(p01, p00);
            uint32_t hB = cvt2bf(p11, p10);
            uint32_t lAp = cvt2bf(p01 - bfhiF(hA), p00 - bfloF(hA));
            uint32_t lBp = cvt2bf(p11 - bfhiF(hB), p10 - bfloF(hB));
            int kk2 = j >> 1, hf = (j & 1) << 1;
            ph[kk2][hf]     = hA;  ph[kk2][hf + 1] = hB;
            pl[kk2][hf]     = lAp; pl[kk2][hf + 1] = lBp;
        }
        sum0 += __shfl_xor_sync(0xffffffffu, sum0, 1);
        sum0 += __shfl_xor_sync(0xffffffffu, sum0, 2);
        sum1 += __shfl_xor_sync(0xffffffffu, sum1, 1);
        sum1 += __shfl_xor_sync(0xffffffffu, sum1, 2);
        l0 += sum0;
        l1 += sum1;

        #pragma unroll
        for (int kk2 = 0; kk2 < 4; kk2++) {
            #pragma unroll
            for (int ndp = 0; ndp < 8; ndp++) {
                uint32_t voff = (uint32_t)((kk2 * 16 * FSTR + ndp * 16) * 2);
                uint32_t vh[4], vl[4];
                ldm4t(vh, sVH + voff + lV);
                ldm4t(vl, sVL + voff + lV);
                // interleave the two output columns: reuse distance 2
                mma_bf16(o[ndp*2],   ph[kk2], vh);     mma_bf16(o[ndp*2+1], ph[kk2], vh + 2);
                mma_bf16(o[ndp*2],   ph[kk2], vl);     mma_bf16(o[ndp*2+1], ph[kk2], vl + 2);
                mma_bf16(o[ndp*2],   pl[kk2], vh);     mma_bf16(o[ndp*2+1], pl[kk2], vh + 2);
            }
        }
        __syncthreads();
    }

    float il0 = 1.f / l0, il1 = 1.f / l1;
    size_t rbase = (size_t)(b * SEQ + q0 + w * 16 + g) * QD + h * HD;
    __nv_bfloat16* AH = ah + rbase;
    __nv_bfloat16* AL = al + rbase;
    #pragma unroll
    for (int nd = 0; nd < 16; nd++) {
        int col = nd * 8 + t * 2;
        float a0 = o[nd][0] * il0, a1 = o[nd][1] * il0;
        uint32_t hp = cvt2bf(a1, a0);
        uint32_t lp = cvt2bf(a1 - bfhiF(hp), a0 - bfloF(hp));
        *(uint32_t*)(AH + col) = hp;
        *(uint32_t*)(AL + col) = lp;
        float b0 = o[nd][2] * il1, b1 = o[nd][3] * il1;
        hp = cvt2bf(b1, b0);
        lp = cvt2bf(b1 - bfhiF(hp), b0 - bfloF(hp));
        *(uint32_t*)(AH + (size_t)8 * QD + col) = hp;
        *(uint32_t*)(AL + (size_t)8 * QD + col) = lp;
    }
}

// ---------------------------------------------------------------------------
extern "C" void kernel_launch(void* const* d_in, const int* in_sizes, int n_in,
                              void* d_out, int out_size)
{
    const float* hidden = (const float*)d_in[0];
    const int*   pos    = (const int*)d_in[1];
    const float* Wq     = (const float*)d_in[2];
    const float* Wk     = (const float*)d_in[3];
    const float* Wv     = (const float*)d_in[4];
    const float* Wo     = (const float*)d_in[5];
    float*       out    = (float*)d_out;

    float *qb;
    cudaGetSymbolAddress((void**)&qb, g_q);
    __nv_bfloat16 *hh,*hl,*wqh,*wql,*wkh,*wkl,*wvh,*wvl,*woh,*wol,*ah,*al,*kh,*kl,*vh,*vl;
    cudaGetSymbolAddress((void**)&hh,  g_hh);  cudaGetSymbolAddress((void**)&hl,  g_hl);
    cudaGetSymbolAddress((void**)&wqh, g_wqh); cudaGetSymbolAddress((void**)&wql, g_wql);
    cudaGetSymbolAddress((void**)&wkh, g_wkh); cudaGetSymbolAddress((void**)&wkl, g_wkl);
    cudaGetSymbolAddress((void**)&wvh, g_wvh); cudaGetSymbolAddress((void**)&wvl, g_wvl);
    cudaGetSymbolAddress((void**)&woh, g_woh); cudaGetSymbolAddress((void**)&wol, g_wol);
    cudaGetSymbolAddress((void**)&ah,  g_ah);  cudaGetSymbolAddress((void**)&al,  g_al);
    cudaGetSymbolAddress((void**)&kh,  g_kh);  cudaGetSymbolAddress((void**)&kl,  g_kl);
    cudaGetSymbolAddress((void**)&vh,  g_vh);  cudaGetSymbolAddress((void**)&vl,  g_vl);

    cudaFuncSetAttribute(gemm_qkv, cudaFuncAttributeMaxDynamicSharedMemorySize, GEMM_SMEM);
    cudaFuncSetAttribute(gemm_nt_split, cudaFuncAttributeMaxDynamicSharedMemorySize, GEMM_SMEM);
    cudaFuncSetAttribute(flash_attn_mma, cudaFuncAttributeMaxDynamicSharedMemorySize, FA_SMEM);

    // All input/weight splits in one launch
    split_all_kernel<<<(SPL_N4 + 255)/256, 256>>>(hidden, Wq, Wk, Wv, Wo,
                                                  hh, hl, wqh, wql, wkh, wkl,
                                                  wvh, wvl, woh, wol);

    // Fused Q/K/V projections (128x128, 2-stage, 2 CTAs/SM, term-major MMA)
    gemm_qkv<<<dim3(40, TOK/128), 256, GEMM_SMEM>>>(hh, hl, wqh, wql, wkh, wkl, wvh, wvl,
                                                    qb, kh, kl, vh, vl, pos);

    // Flash attention (Q rope fused) -> split bf16 output
    flash_attn_mma<<<dim3(SEQ/128, BATCH*NH), 256, FA_SMEM>>>(qb, pos, kh, kl, vh, vl, ah, al);

    // O projection (128x128, 2-stage, 2 CTAs/SM, term-major MMA)
    gemm_nt_split<<<dim3(HID/128, TOK/128), 256, GEMM_SMEM>>>(ah, al, woh, wol, out, HID, QD);
}

// round 13
// speedup vs baseline: 1.3334x; 1.2379x over previous
#include <cuda_runtime.h>
#include <cuda_bf16.h>
#include <cuda_fp16.h>
#include <math.h>
#include <stdint.h>

// Problem constants
#define BATCH 2
#define SEQ 2048
#define TOK (BATCH*SEQ)          // 4096
#define HID 3584
#define NH 32
#define NKV 4
#define HD 128
#define QD (NH*HD)               // 4096
#define KVD (NKV*HD)             // 512

// fp32 scratch
__device__ float g_q[(size_t)TOK*QD];
// fp16 scratch: activations split hi/lo, weights single-rounded
__device__ __half g_hh[(size_t)TOK*HID], g_hl[(size_t)TOK*HID];
__device__ __half g_wq[(size_t)QD*HID];
__device__ __half g_wk[(size_t)KVD*HID];
__device__ __half g_wv[(size_t)KVD*HID];
__device__ __half g_wo[(size_t)HID*QD];
__device__ __half g_ah[(size_t)TOK*QD],  g_al[(size_t)TOK*QD];
__device__ __half g_kh[(size_t)TOK*KVD], g_kl[(size_t)TOK*KVD];
__device__ __half g_vh[(size_t)TOK*KVD], g_vl[(size_t)TOK*KVD];

// ===========================================================================
// PTX helpers
// ===========================================================================
__device__ __forceinline__ uint32_t smem_u32(const void* p) {
    uint32_t a;
    asm("{ .reg .u64 t; cvta.to.shared.u64 t, %1; cvt.u32.u64 %0, t; }" : "=r"(a) : "l"(p));
    return a;
}
__device__ __forceinline__ void cp_async16(uint32_t dst, const void* src) {
    asm volatile("cp.async.cg.shared.global [%0], [%1], 16;" :: "r"(dst), "l"(src) : "memory");
}
#define CP_COMMIT() asm volatile("cp.async.commit_group;" ::: "memory")
#define CP_WAIT(n)  asm volatile("cp.async.wait_group %0;" :: "n"(n) : "memory")

__device__ __forceinline__ void ldm4(uint32_t* r, uint32_t addr) {
    asm volatile("ldmatrix.sync.aligned.m8n8.x4.shared.b16 {%0,%1,%2,%3}, [%4];"
                 : "=r"(r[0]), "=r"(r[1]), "=r"(r[2]), "=r"(r[3]) : "r"(addr));
}
__device__ __forceinline__ void ldm4t(uint32_t* r, uint32_t addr) {
    asm volatile("ldmatrix.sync.aligned.m8n8.x4.trans.shared.b16 {%0,%1,%2,%3}, [%4];"
                 : "=r"(r[0]), "=r"(r[1]), "=r"(r[2]), "=r"(r[3]) : "r"(addr));
}
__device__ __forceinline__ void mma_f16(float* c, const uint32_t* a, const uint32_t* b) {
    asm volatile("mma.sync.aligned.m16n8k16.row.col.f32.f16.f16.f32 "
                 "{%0,%1,%2,%3}, {%4,%5,%6,%7}, {%8,%9}, {%0,%1,%2,%3};"
                 : "+f"(c[0]), "+f"(c[1]), "+f"(c[2]), "+f"(c[3])
                 : "r"(a[0]), "r"(a[1]), "r"(a[2]), "r"(a[3]), "r"(b[0]), "r"(b[1]));
}
// pack two fp16 from floats: high half <- hi, low half <- lo
__device__ __forceinline__ uint32_t cvt2h(float hi, float lo) {
    uint32_t r;
    asm("cvt.rn.f16x2.f32 %0, %1, %2;" : "=r"(r) : "f"(hi), "f"(lo));
    return r;
}
__device__ __forceinline__ float hloF(uint32_t p) {
    return __half2float(__ushort_as_half((unsigned short)(p & 0xffffu)));
}
__device__ __forceinline__ float hhiF(uint32_t p) {
    return __half2float(__ushort_as_half((unsigned short)(p >> 16)));
}

// fast 2^t on the FMA pipe (no MUFU); exp2(0) == 1.0 exactly
__device__ __forceinline__ float fast_exp2(float t) {
    t = fmaxf(t, -120.0f);
    float r = t + 12582912.0f;
    float n = r - 12582912.0f;
    float f = t - n;
    int   ni = __float_as_int(r);
    float p = 1.3392112e-3f;
    p = fmaf(p, f, 9.6183463e-3f);
    p = fmaf(p, f, 5.5503277e-2f);
    p = fmaf(p, f, 2.4022652e-1f);
    p = fmaf(p, f, 6.9314718e-1f);
    p = fmaf(p, f, 1.0f);
    return __int_as_float(__float_as_int(p) + (ni << 23));
}

// ===========================================================================
// Fused split: hidden -> fp16 hi/lo; weights -> single-rounded fp16.
// ===========================================================================
#define SPL_N0 (TOK*HID)
#define SPL_N1 (SPL_N0 + QD*HID)
#define SPL_N2 (SPL_N1 + KVD*HID)
#define SPL_N3 (SPL_N2 + KVD*HID)
#define SPL_N4 (SPL_N3 + HID*QD)

__global__ void split_all_kernel(
    const float* __restrict__ x0, const float* __restrict__ x1,
    const float* __restrict__ x2, const float* __restrict__ x3,
    const float* __restrict__ x4,
    __half* __restrict__ hh, __half* __restrict__ hl,
    __half* __restrict__ wq, __half* __restrict__ wk,
    __half* __restrict__ wv, __half* __restrict__ wo)
{
    int i = blockIdx.x * 256 + threadIdx.x;
    if (i >= SPL_N4) return;
    if (i < SPL_N0) {
        float v = x0[i];
        __half h = __float2half(v);
        hh[i] = h;
        hl[i] = __float2half(v - __half2float(h));
    } else if (i < SPL_N1) {
        int off = i - SPL_N0; wq[off] = __float2half(x1[off]);
    } else if (i < SPL_N2) {
        int off = i - SPL_N1; wk[off] = __float2half(x2[off]);
    } else if (i < SPL_N3) {
        int off = i - SPL_N2; wv[off] = __float2half(x3[off]);
    } else {
        int off = i - SPL_N3; wo[off] = __float2half(x4[off]);
    }
}

// ===========================================================================
// mma.sync fp16 mixed-precision GEMM: C = (Ah+Al) * B^T, 128x128x32 tiles,
// 2-stage cp.async, 2 CTAs/SM, 8 warps (2x4), warp 64x32, 2 MMA terms
// (Ah*B then Al*B; per-acc order fixed).
// ===========================================================================
#define TSTR 40
#define TILE_B (128*TSTR*2)           // 10240
#define STAGE_B (3*TILE_B)            // 30720 (Ah, Al, B)
#define GEMM_SMEM 67584               // max(2*STAGE_B=61440, K-epilogue 67584)

__device__ __forceinline__ void gemm_issue_loads(
    uint32_t sstage, const __half* pAh, const __half* pAl,
    const __half* pB, int K, int ko, int tid)
{
    #pragma unroll
    for (int i = 0; i < 2; i++) {
        int c = tid + (i << 8);
        int row = c >> 2;
        int kc  = c & 3;
        uint32_t dst = (uint32_t)(row * TSTR + kc * 8) * 2;
        size_t src = (size_t)row * K + ko + kc * 8;
        cp_async16(sstage + 0*TILE_B + dst, pAh + src);
        cp_async16(sstage + 1*TILE_B + dst, pAl + src);
        cp_async16(sstage + 2*TILE_B + dst, pB  + src);
    }
}

// Fills acc[4][4][4]; after return all cp.asyncs complete; caller must
// __syncthreads before reusing smem.
__device__ __forceinline__ void gemm_mainloop(
    const __half* __restrict__ pAh, const __half* __restrict__ pAl,
    const __half* __restrict__ pB,
    int K, char* smem, float acc[4][4][4])
{
    uint32_t sbase = smem_u32(smem);
    const int tid  = threadIdx.x;
    const int lane = tid & 31;
    const int wid  = tid >> 5;
    const int wm   = wid >> 2;
    const int wn   = wid & 3;

    const uint32_t laneA = (uint32_t)((lane & 15) * TSTR + ((lane >> 4) << 3)) * 2;
    const uint32_t laneB = (uint32_t)(((lane & 7) + ((lane >> 4) << 3)) * TSTR
                                      + (((lane >> 3) & 1) << 3)) * 2;

    #pragma unroll
    for (int i = 0; i < 4; i++)
        #pragma unroll
        for (int j = 0; j < 4; j++)
            #pragma unroll
            for (int r = 0; r < 4; r++) acc[i][j][r] = 0.f;

    const int KT = K >> 5;
    gemm_issue_loads(sbase, pAh, pAl, pB, K, 0, tid);
    CP_COMMIT();
    gemm_issue_loads(sbase + STAGE_B, pAh, pAl, pB, K, 32, tid);
    CP_COMMIT();

    for (int kt = 0; kt < KT; kt++) {
        if (kt + 1 < KT) { CP_WAIT(1); } else { CP_WAIT(0); }
        __syncthreads();

        uint32_t st = sbase + (uint32_t)(kt & 1) * STAGE_B;
        uint32_t sAh = st, sAl = st + TILE_B, sB = st + 2*TILE_B;

        #pragma unroll
        for (int kk = 0; kk < 2; kk++) {
            uint32_t ah[4][4], al[4][4];
            #pragma unroll
            for (int mi = 0; mi < 4; mi++) {
                uint32_t aoff = (uint32_t)(((wm * 64 + mi * 16) * TSTR + kk * 16) * 2);
                ldm4(ah[mi], sAh + aoff + laneA);
                ldm4(al[mi], sAl + aoff + laneA);
            }
            uint32_t b[4][2];
            #pragma unroll
            for (int nj2 = 0; nj2 < 2; nj2++) {
                uint32_t boff = (uint32_t)(((wn * 32 + nj2 * 16) * TSTR + kk * 16) * 2);
                uint32_t r[4];
                ldm4(r, sB + boff + laneB);
                b[nj2*2][0] = r[0]; b[nj2*2][1] = r[1];
                b[nj2*2+1][0] = r[2]; b[nj2*2+1][1] = r[3];
            }
            // Per-acc order fixed: Ah*B then Al*B.
            #pragma unroll
            for (int mi = 0; mi < 4; mi++)
                #pragma unroll
                for (int nj = 0; nj < 4; nj++)
                    mma_f16(acc[mi][nj], ah[mi], b[nj]);
            #pragma unroll
            for (int mi = 0; mi < 4; mi++)
                #pragma unroll
                for (int nj = 0; nj < 4; nj++)
                    mma_f16(acc[mi][nj], al[mi], b[nj]);
        }

        if (kt + 2 < KT) {
            __syncthreads();     // all warps drained buffer (kt&1)
            gemm_issue_loads(st, pAh, pAl, pB, K, (kt + 2) << 5, tid);
            CP_COMMIT();
        }
    }
}

// fp32 epilogue (Q and O projections)
__device__ __forceinline__ void epilogue_f32(float acc[4][4][4], float* Ct, int N)
{
    const int lane = threadIdx.x & 31;
    const int wid  = threadIdx.x >> 5;
    const int wm = wid >> 2, wn = wid & 3;
    const int g = lane >> 2, tg = lane & 3;
    #pragma unroll
    for (int mi = 0; mi < 4; mi++) {
        int row = wm * 64 + mi * 16 + g;
        #pragma unroll
        for (int nj = 0; nj < 4; nj++) {
            int col = wn * 32 + nj * 8 + tg * 2;
            float* p0 = Ct + (size_t)row * N + col;
            float* p1 = p0 + (size_t)8 * N;
            p0[0] = acc[mi][nj][0]; p0[1] = acc[mi][nj][1];
            p1[0] = acc[mi][nj][2]; p1[1] = acc[mi][nj][3];
        }
    }
}

// Fused Q/K/V projection: grid (40, TOK/128). bx 0-31: Q (fp32 out);
// bx 32-35: K (rope + fp16 hi/lo split via smem staging); bx 36-39: V (split).
__global__ void __launch_bounds__(256, 2)
gemm_qkv(const __half* __restrict__ hh, const __half* __restrict__ hl,
         const __half* __restrict__ wq, const __half* __restrict__ wk,
         const __half* __restrict__ wv,
         float* __restrict__ qb,
         __half* __restrict__ kh, __half* __restrict__ kl,
         __half* __restrict__ vh, __half* __restrict__ vl,
         const int* __restrict__ pos32)
{
    extern __shared__ char smem[];
    const int bx = blockIdx.x;
    const int bm = blockIdx.y << 7;
    const int tid = threadIdx.x;
    const __half* bp;
    int bn;
    if (bx < 32)      { bp = wq; bn = bx << 7; }
    else if (bx < 36) { bp = wk; bn = (bx - 32) << 7; }
    else              { bp = wv; bn = (bx - 36) << 7; }

    float acc[4][4][4];
    gemm_mainloop(hh + (size_t)bm * HID, hl + (size_t)bm * HID,
                  bp + (size_t)bn * HID, HID, smem, acc);

    const int lane = tid & 31;
    const int wid  = tid >> 5;
    const int wm = wid >> 2, wn = wid & 3;
    const int g = lane >> 2, tg = lane & 3;

    if (bx < 32) {
        epilogue_f32(acc, qb + (size_t)bm * QD + bn, QD);
    } else if (bx < 36) {
        // K: stage acc to smem, then rope + fp16 hi/lo split
        float* sacc = (float*)smem;     // [128][132] = 67584 B
        __syncthreads();                // mainloop smem reads done in all warps
        #pragma unroll
        for (int mi = 0; mi < 4; mi++) {
            int row = wm * 64 + mi * 16 + g;
            #pragma unroll
            for (int nj = 0; nj < 4; nj++) {
                int col = wn * 32 + nj * 8 + tg * 2;
                sacc[row * 132 + col]     = acc[mi][nj][0];
                sacc[row * 132 + col + 1] = acc[mi][nj][1];
                sacc[(row + 8) * 132 + col]     = acc[mi][nj][2];
                sacc[(row + 8) * 132 + col + 1] = acc[mi][nj][3];
            }
        }
        __syncthreads();
        const bool is64 = (pos32[1] == 0);
        #pragma unroll
        for (int i = 0; i < 32; i++) {
            int idx = tid + (i << 8);           // 0..8191
            int row = idx >> 6;                 // 0..127
            int d   = idx & 63;
            int t   = bm + row;
            int p = is64 ? pos32[2 * t] : pos32[t];
            float invf = powf(1.0e6f, -(float)d * (1.0f / 64.0f));
            float sv, cv;
            sincosf((float)p * invf, &sv, &cv);
            float x1 = sacc[row * 132 + d];
            float x2 = sacc[row * 132 + d + 64];
            float y1 = x1 * cv - x2 * sv;
            float y2 = x2 * cv + x1 * sv;
            __half h1 = __float2half(y1);
            __half h2 = __float2half(y2);
            size_t off = (size_t)t * KVD + bn + d;
            kh[off]      = h1; kl[off]      = __float2half(y1 - __half2float(h1));
            kh[off + 64] = h2; kl[off + 64] = __float2half(y2 - __half2float(h2));
        }
    } else {
        // V: split acc directly to fp16 hi/lo
        #pragma unroll
        for (int mi = 0; mi < 4; mi++) {
            int row = wm * 64 + mi * 16 + g;
            #pragma unroll
            for (int nj = 0; nj < 4; nj++) {
                int col = wn * 32 + nj * 8 + tg * 2;
                size_t off0 = (size_t)(bm + row) * KVD + bn + col;
                size_t off1 = off0 + (size_t)8 * KVD;
                float a0 = acc[mi][nj][0], a1 = acc[mi][nj][1];
                uint32_t hp = cvt2h(a1, a0);
                uint32_t lp = cvt2h(a1 - hhiF(hp), a0 - hloF(hp));
                *(uint32_t*)(vh + off0) = hp;
                *(uint32_t*)(vl + off0) = lp;
                float b0 = acc[mi][nj][2], b1 = acc[mi][nj][3];
                hp = cvt2h(b1, b0);
                lp = cvt2h(b1 - hhiF(hp), b0 - hloF(hp));
                *(uint32_t*)(vh + off1) = hp;
                *(uint32_t*)(vl + off1) = lp;
            }
        }
    }
}

// O-projection: A = attn-out split fp16 (ah, al), B = Wo single fp16
__global__ void __launch_bounds__(256, 2)
gemm_nt_split(const __half* __restrict__ Ah, const __half* __restrict__ Al,
              const __half* __restrict__ B,
              float* __restrict__ C, int N, int K)
{
    extern __shared__ char smem[];
    const int bm = blockIdx.y << 7;
    const int bn = blockIdx.x << 7;
    float acc[4][4][4];
    gemm_mainloop(Ah + (size_t)bm * K, Al + (size_t)bm * K,
                  B + (size_t)bn * K, K, smem, acc);
    epilogue_f32(acc, C + (size_t)bm * N + bn, N);
}

// ===========================================================================
// Flash attention: fp16 mma, FMA-pipe exp2, non-causal.
// QK: Q hi/lo x K hi/lo, 3 terms. PV: P single-rounded fp16 x V hi/lo, 2 terms.
// Q-RoPE fused into Q-load. Epilogue writes fp16 hi/lo (feeds O-proj).
// ===========================================================================
#define FSTR 136
#define FA_Q_B (128*FSTR*2)
#define FA_T_B (64*FSTR*2)
#define FA_ST_B (4*FA_T_B)
#define FA_SMEM (2*FA_Q_B + 2*FA_ST_B)    // 208896

__device__ __forceinline__ void fa_load_kv(
    uint32_t stage, const __half* __restrict__ Kh, const __half* __restrict__ Kl,
    const __half* __restrict__ Vh, const __half* __restrict__ Vl,
    size_t rowbase, int kvoff, int tid)
{
    #pragma unroll
    for (int comp = 0; comp < 4; comp++) {
        const __half* g = (comp == 0) ? Kh : (comp == 1) ? Kl : (comp == 2) ? Vh : Vl;
        #pragma unroll
        for (int jj = 0; jj < 4; jj++) {
            int cc = tid + (jj << 8);
            int row = cc >> 4, kc = cc & 15;
            cp_async16(stage + comp * FA_T_B + (uint32_t)(row * 272 + kc * 16),
                       g + (rowbase + row) * KVD + kvoff + kc * 8);
        }
    }
}

__global__ void __launch_bounds__(256, 1)
flash_attn_mma(const float* __restrict__ Q, const int* __restrict__ pos32,
               const __half* __restrict__ Kh, const __half* __restrict__ Kl,
               const __half* __restrict__ Vh, const __half* __restrict__ Vl,
               __half* __restrict__ ah, __half* __restrict__ al)
{
    extern __shared__ char smem[];
    uint32_t sb = smem_u32(smem);
    const uint32_t sQH = sb;
    const uint32_t sQL = sb + FA_Q_B;
    const uint32_t sST = sb + 2 * FA_Q_B;

    const int tid = threadIdx.x, lane = tid & 31, w = tid >> 5;
    const int bh = blockIdx.y, b = bh >> 5, h = bh & 31, kvh = h >> 3;
    const int q0 = blockIdx.x << 7;
    const int g = lane >> 2, t = lane & 3;

    // --- Q load + RoPE + scale(1/sqrt(d)*log2e) + fp16 hi/lo split ---
    const float qsc = 0.08838834764831843f * 1.4426950408889634f;
    const float* Qg = Q + (size_t)(b * SEQ + q0) * QD + h * HD;
    const bool is64 = (pos32[1] == 0);
    #pragma unroll
    for (int i = 0; i < 8; i++) {
        int idx = tid + (i << 8);
        int row = idx >> 4;
        int d4  = (idx & 15) << 2;
        int tok = b * SEQ + q0 + row;
        int p = is64 ? pos32[2 * tok] : pos32[tok];
        float4 xa = *(const float4*)(Qg + (size_t)row * QD + d4);
        float4 xb = *(const float4*)(Qg + (size_t)row * QD + d4 + 64);
        float ya[4], yb[4];
        const float* x1 = &xa.x;
        const float* x2 = &xb.x;
        #pragma unroll
        for (int j = 0; j < 4; j++) {
            int d = d4 + j;
            float invf = powf(1.0e6f, -(float)d * (1.0f / 64.0f));
            float sv, cv;
            sincosf((float)p * invf, &sv, &cv);
            ya[j] = (x1[j] * cv - x2[j] * sv) * qsc;
            yb[j] = (x2[j] * cv + x1[j] * sv) * qsc;
        }
        uint32_t ha01 = cvt2h(ya[1], ya[0]);
        uint32_t ha23 = cvt2h(ya[3], ya[2]);
        uint32_t la01 = cvt2h(ya[1] - hhiF(ha01), ya[0] - hloF(ha01));
        uint32_t la23 = cvt2h(ya[3] - hhiF(ha23), ya[2] - hloF(ha23));
        uint32_t hb01 = cvt2h(yb[1], yb[0]);
        uint32_t hb23 = cvt2h(yb[3], yb[2]);
        uint32_t lb01 = cvt2h(yb[1] - hhiF(hb01), yb[0] - hloF(hb01));
        uint32_t lb23 = cvt2h(yb[3] - hhiF(hb23), yb[2] - hloF(hb23));
        uint32_t off1 = (uint32_t)(row * 272 + d4 * 2);
        uint32_t off2 = (uint32_t)(row * 272 + (d4 + 64) * 2);
        *(uint2*)(smem + (sQH - sb) + off1) = make_uint2(ha01, ha23);
        *(uint2*)(smem + (sQL - sb) + off1) = make_uint2(la01, la23);
        *(uint2*)(smem + (sQH - sb) + off2) = make_uint2(hb01, hb23);
        *(uint2*)(smem + (sQL - sb) + off2) = make_uint2(lb01, lb23);
    }

    float m0 = -1e30f, m1 = -1e30f, l0 = 0.f, l1 = 0.f;
    float o[16][4];
    #pragma unroll
    for (int nd = 0; nd < 16; nd++)
        #pragma unroll
        for (int c = 0; c < 4; c++) o[nd][c] = 0.f;

    const size_t kvbase = (size_t)b * SEQ;
    const int kvoff = kvh * HD;

    const uint32_t lA = (uint32_t)(((lane & 15) * FSTR + ((lane >> 4) << 3)) * 2);
    const uint32_t lB = (uint32_t)((((lane & 7) + ((lane >> 4) << 3)) * FSTR
                                    + (((lane >> 3) & 1) << 3)) * 2);
    const uint32_t lV = (uint32_t)((((lane & 7) + (((lane >> 3) & 1) << 3)) * FSTR
                                    + (((lane >> 4) & 1) << 3)) * 2);

    fa_load_kv(sST, Kh, Kl, Vh, Vl, kvbase, kvoff, tid);
    CP_COMMIT();

    for (int kt = 0; kt < SEQ / 64; kt++) {
        if (kt + 1 < SEQ / 64) {
            fa_load_kv(sST + ((kt + 1) & 1) * FA_ST_B, Kh, Kl, Vh, Vl,
                       kvbase + (size_t)(kt + 1) * 64, kvoff, tid);
            CP_COMMIT();
            CP_WAIT(1);
        } else {
            CP_WAIT(0);
        }
        __syncthreads();

        const uint32_t st = sST + (kt & 1) * FA_ST_B;
        const uint32_t sKH = st, sKL = st + FA_T_B, sVH = st + 2*FA_T_B, sVL = st + 3*FA_T_B;

        float s[8][4];
        #pragma unroll
        for (int j = 0; j < 8; j++)
            #pragma unroll
            for (int c = 0; c < 4; c++) s[j][c] = 0.f;

        #pragma unroll
        for (int kk = 0; kk < 8; kk++) {
            uint32_t qh[4], ql[4];
            uint32_t qoff = (uint32_t)((w * 16 * FSTR + kk * 16) * 2);
            ldm4(qh, sQH + qoff + lA);
            ldm4(ql, sQL + qoff + lA);
            #pragma unroll
            for (int nj2 = 0; nj2 < 4; nj2++) {
                uint32_t koff = (uint32_t)((nj2 * 16 * FSTR + kk * 16) * 2);
                uint32_t rh[4], rl[4];
                ldm4(rh, sKH + koff + lB);
                ldm4(rl, sKL + koff + lB);
                mma_f16(s[nj2*2],   qh, rh);     mma_f16(s[nj2*2+1], qh, rh + 2);
                mma_f16(s[nj2*2],   qh, rl);     mma_f16(s[nj2*2+1], qh, rl + 2);
                mma_f16(s[nj2*2],   ql, rh);     mma_f16(s[nj2*2+1], ql, rh + 2);
            }
        }

        float mx0 = -1e30f, mx1 = -1e30f;
        #pragma unroll
        for (int j = 0; j < 8; j++) {
            mx0 = fmaxf(mx0, fmaxf(s[j][0], s[j][1]));
            mx1 = fmaxf(mx1, fmaxf(s[j][2], s[j][3]));
        }
        mx0 = fmaxf(mx0, __shfl_xor_sync(0xffffffffu, mx0, 1));
        mx0 = fmaxf(mx0, __shfl_xor_sync(0xffffffffu, mx0, 2));
        mx1 = fmaxf(mx1, __shfl_xor_sync(0xffffffffu, mx1, 1));
        mx1 = fmaxf(mx1, __shfl_xor_sync(0xffffffffu, mx1, 2));
        float mn0 = fmaxf(m0, mx0), mn1 = fmaxf(m1, mx1);

        // skip-rescale fast path: alpha == 1 exactly when no new max
        bool newmax = (mn0 > m0) || (mn1 > m1);
        if (__any_sync(0xffffffffu, newmax)) {
            float al0 = fast_exp2(m0 - mn0), al1 = fast_exp2(m1 - mn1);
            l0 *= al0; l1 *= al1;
            #pragma unroll
            for (int nd = 0; nd < 16; nd++) {
                o[nd][0] *= al0; o[nd][1] *= al0;
                o[nd][2] *= al1; o[nd][3] *= al1;
            }
        }
        m0 = mn0; m1 = mn1;

        // P: single-rounded fp16 (l sums use unrounded fp32 values)
        uint32_t pf[4][4];
        float sum0 = 0.f, sum1 = 0.f;
        #pragma unroll
        for (int j = 0; j < 8; j++) {
            float p00 = fast_exp2(s[j][0] - mn0);
            float p01 = fast_exp2(s[j][1] - mn0);
            float p10 = fast_exp2(s[j][2] - mn1);
            float p11 = fast_exp2(s[j][3] - mn1);
            sum0 += p00 + p01; sum1 += p10 + p11;
            int kk2 = j >> 1, hf = (j & 1) << 1;
            pf[kk2][hf]     = cvt2h(p01, p00);
            pf[kk2][hf + 1] = cvt2h(p11, p10);
        }
        sum0 += __shfl_xor_sync(0xffffffffu, sum0, 1);
        sum0 += __shfl_xor_sync(0xffffffffu, sum0, 2);
        sum1 += __shfl_xor_sync(0xffffffffu, sum1, 1);
        sum1 += __shfl_xor_sync(0xffffffffu, sum1, 2);
        l0 += sum0;
        l1 += sum1;

        #pragma unroll
        for (int kk2 = 0; kk2 < 4; kk2++) {
            #pragma unroll
            for (int ndp = 0; ndp < 8; ndp++) {
                uint32_t voff = (uint32_t)((kk2 * 16 * FSTR + ndp * 16) * 2);
                uint32_t vh[4], vl[4];
                ldm4t(vh, sVH + voff + lV);
                ldm4t(vl, sVL + voff + lV);
                mma_f16(o[ndp*2], pf[kk2], vh);   mma_f16(o[ndp*2+1], pf[kk2], vh + 2);
                mma_f16(o[ndp*2], pf[kk2], vl);   mma_f16(o[ndp*2+1], pf[kk2], vl + 2);
            }
        }
        __syncthreads();
    }

    float il0 = 1.f / l0, il1 = 1.f / l1;
    size_t rbase = (size_t)(b * SEQ + q0 + w * 16 + g) * QD + h * HD;
    __half* AH = ah + rbase;
    __half* AL = al + rbase;
    #pragma unroll
    for (int nd = 0; nd < 16; nd++) {
        int col = nd * 8 + t * 2;
        float a0 = o[nd][0] * il0, a1 = o[nd][1] * il0;
        uint32_t hp = cvt2h(a1, a0);
        uint32_t lp = cvt2h(a1 - hhiF(hp), a0 - hloF(hp));
        *(uint32_t*)(AH + col) = hp;
        *(uint32_t*)(AL + col) = lp;
        float b0 = o[nd][2] * il1, b1 = o[nd][3] * il1;
        hp = cvt2h(b1, b0);
        lp = cvt2h(b1 - hhiF(hp), b0 - hloF(hp));
        *(uint32_t*)(AH + (size_t)8 * QD + col) = hp;
        *(uint32_t*)(AL + (size_t)8 * QD + col) = lp;
    }
}

// ---------------------------------------------------------------------------
extern "C" void kernel_launch(void* const* d_in, const int* in_sizes, int n_in,
                              void* d_out, int out_size)
{
    const float* hidden = (const float*)d_in[0];
    const int*   pos    = (const int*)d_in[1];
    const float* Wq     = (const float*)d_in[2];
    const float* Wk     = (const float*)d_in[3];
    const float* Wv     = (const float*)d_in[4];
    const float* Wo     = (const float*)d_in[5];
    float*       out    = (float*)d_out;

    float *qb;
    cudaGetSymbolAddress((void**)&qb, g_q);
    __half *hh,*hl,*wq,*wk,*wv,*wo,*ah,*al,*kh,*kl,*vh,*vl;
    cudaGetSymbolAddress((void**)&hh, g_hh); cudaGetSymbolAddress((void**)&hl, g_hl);
    cudaGetSymbolAddress((void**)&wq, g_wq); cudaGetSymbolAddress((void**)&wk, g_wk);
    cudaGetSymbolAddress((void**)&wv, g_wv); cudaGetSymbolAddress((void**)&wo, g_wo);
    cudaGetSymbolAddress((void**)&ah, g_ah); cudaGetSymbolAddress((void**)&al, g_al);
    cudaGetSymbolAddress((void**)&kh, g_kh); cudaGetSymbolAddress((void**)&kl, g_kl);
    cudaGetSymbolAddress((void**)&vh, g_vh); cudaGetSymbolAddress((void**)&vl, g_vl);

    cudaFuncSetAttribute(gemm_qkv, cudaFuncAttributeMaxDynamicSharedMemorySize, GEMM_SMEM);
    cudaFuncSetAttribute(gemm_nt_split, cudaFuncAttributeMaxDynamicSharedMemorySize, GEMM_SMEM);
    cudaFuncSetAttribute(flash_attn_mma, cudaFuncAttributeMaxDynamicSharedMemorySize, FA_SMEM);

    // Splits: hidden -> fp16 hi/lo; weights -> single fp16
    split_all_kernel<<<(SPL_N4 + 255)/256, 256>>>(hidden, Wq, Wk, Wv, Wo,
                                                  hh, hl, wq, wk, wv, wo);

    // Fused Q/K/V projections (128x128, 2-stage, 2 CTAs/SM, 2-term fp16)
    gemm_qkv<<<dim3(40, TOK/128), 256, GEMM_SMEM>>>(hh, hl, wq, wk, wv,
                                                    qb, kh, kl, vh, vl, pos);

    // Flash attention (Q rope fused) -> fp16 hi/lo output
    flash_attn_mma<<<dim3(SEQ/128, BATCH*NH), 256, FA_SMEM>>>(qb, pos, kh, kl, vh, vl, ah, al);

    // O projection (2-term fp16)
    gemm_nt_split<<<dim3(HID/128, TOK/128), 256, GEMM_SMEM>>>(ah, al, wo, out, HID, QD);
}

// round 14
// speedup vs baseline: 1.6163x; 1.2122x over previous
#include <cuda_runtime.h>
#include <cuda_bf16.h>
#include <cuda_fp16.h>
#include <math.h>
#include <stdint.h>

// Problem constants
#define BATCH 2
#define SEQ 2048
#define TOK (BATCH*SEQ)          // 4096
#define HID 3584
#define NH 32
#define NKV 4
#define HD 128
#define QD (NH*HD)               // 4096
#define KVD (NKV*HD)             // 512

// fp32 scratch
__device__ float g_q[(size_t)TOK*QD];
// fp16 scratch
__device__ __half g_hh[(size_t)TOK*HID], g_hl[(size_t)TOK*HID];
__device__ __half g_wq[(size_t)QD*HID];
__device__ __half g_wk[(size_t)KVD*HID];
__device__ __half g_wv[(size_t)KVD*HID];
__device__ __half g_wo[(size_t)HID*QD];
__device__ __half g_ah[(size_t)TOK*QD],  g_al[(size_t)TOK*QD];
__device__ __half g_k1[(size_t)TOK*KVD];                      // K single fp16
__device__ __half g_vh[(size_t)TOK*KVD], g_vl[(size_t)TOK*KVD];

// ===========================================================================
// PTX helpers
// ===========================================================================
__device__ __forceinline__ uint32_t smem_u32(const void* p) {
    uint32_t a;
    asm("{ .reg .u64 t; cvta.to.shared.u64 t, %1; cvt.u32.u64 %0, t; }" : "=r"(a) : "l"(p));
    return a;
}
__device__ __forceinline__ void cp_async16(uint32_t dst, const void* src) {
    asm volatile("cp.async.cg.shared.global [%0], [%1], 16;" :: "r"(dst), "l"(src) : "memory");
}
#define CP_COMMIT() asm volatile("cp.async.commit_group;" ::: "memory")
#define CP_WAIT(n)  asm volatile("cp.async.wait_group %0;" :: "n"(n) : "memory")

__device__ __forceinline__ void ldm4(uint32_t* r, uint32_t addr) {
    asm volatile("ldmatrix.sync.aligned.m8n8.x4.shared.b16 {%0,%1,%2,%3}, [%4];"
                 : "=r"(r[0]), "=r"(r[1]), "=r"(r[2]), "=r"(r[3]) : "r"(addr));
}
__device__ __forceinline__ void ldm4t(uint32_t* r, uint32_t addr) {
    asm volatile("ldmatrix.sync.aligned.m8n8.x4.trans.shared.b16 {%0,%1,%2,%3}, [%4];"
                 : "=r"(r[0]), "=r"(r[1]), "=r"(r[2]), "=r"(r[3]) : "r"(addr));
}
__device__ __forceinline__ void mma_f16(float* c, const uint32_t* a, const uint32_t* b) {
    asm volatile("mma.sync.aligned.m16n8k16.row.col.f32.f16.f16.f32 "
                 "{%0,%1,%2,%3}, {%4,%5,%6,%7}, {%8,%9}, {%0,%1,%2,%3};"
                 : "+f"(c[0]), "+f"(c[1]), "+f"(c[2]), "+f"(c[3])
                 : "r"(a[0]), "r"(a[1]), "r"(a[2]), "r"(a[3]), "r"(b[0]), "r"(b[1]));
}
__device__ __forceinline__ uint32_t cvt2h(float hi, float lo) {
    uint32_t r;
    asm("cvt.rn.f16x2.f32 %0, %1, %2;" : "=r"(r) : "f"(hi), "f"(lo));
    return r;
}
__device__ __forceinline__ float hloF(uint32_t p) {
    return __half2float(__ushort_as_half((unsigned short)(p & 0xffffu)));
}
__device__ __forceinline__ float hhiF(uint32_t p) {
    return __half2float(__ushort_as_half((unsigned short)(p >> 16)));
}

// fast 2^t on the FMA pipe (no MUFU); exp2(0) == 1.0 exactly
__device__ __forceinline__ float fast_exp2(float t) {
    t = fmaxf(t, -120.0f);
    float r = t + 12582912.0f;
    float n = r - 12582912.0f;
    float f = t - n;
    int   ni = __float_as_int(r);
    float p = 1.3392112e-3f;
    p = fmaf(p, f, 9.6183463e-3f);
    p = fmaf(p, f, 5.5503277e-2f);
    p = fmaf(p, f, 2.4022652e-1f);
    p = fmaf(p, f, 6.9314718e-1f);
    p = fmaf(p, f, 1.0f);
    return __int_as_float(__float_as_int(p) + (ni << 23));
}

// ===========================================================================
// Fused split: hidden -> fp16 hi/lo; weights -> single-rounded fp16.
// ===========================================================================
#define SPL_N0 (TOK*HID)
#define SPL_N1 (SPL_N0 + QD*HID)
#define SPL_N2 (SPL_N1 + KVD*HID)
#define SPL_N3 (SPL_N2 + KVD*HID)
#define SPL_N4 (SPL_N3 + HID*QD)

__global__ void split_all_kernel(
    const float* __restrict__ x0, const float* __restrict__ x1,
    const float* __restrict__ x2, const float* __restrict__ x3,
    const float* __restrict__ x4,
    __half* __restrict__ hh, __half* __restrict__ hl,
    __half* __restrict__ wq, __half* __restrict__ wk,
    __half* __restrict__ wv, __half* __restrict__ wo)
{
    int i = blockIdx.x * 256 + threadIdx.x;
    if (i >= SPL_N4) return;
    if (i < SPL_N0) {
        float v = x0[i];
        __half h = __float2half(v);
        hh[i] = h;
        hl[i] = __float2half(v - __half2float(h));
    } else if (i < SPL_N1) {
        int off = i - SPL_N0; wq[off] = __float2half(x1[off]);
    } else if (i < SPL_N2) {
        int off = i - SPL_N1; wk[off] = __float2half(x2[off]);
    } else if (i < SPL_N3) {
        int off = i - SPL_N2; wv[off] = __float2half(x3[off]);
    } else {
        int off = i - SPL_N3; wo[off] = __float2half(x4[off]);
    }
}

// ===========================================================================
// mma.sync fp16 mixed-precision GEMM: C = (Ah+Al) * B^T, 128x128x32 tiles,
// 3-stage cp.async, single barrier per kt, 2 CTAs/SM, 8 warps, warp 64x32.
// Refill of stage (kt+2)%3 == (kt-1)%3 is safe after top-of-kt barrier.
// ===========================================================================
#define TSTR 40
#define TILE_B (128*TSTR*2)           // 10240
#define STAGE_B (3*TILE_B)            // 30720 (Ah, Al, B)
#define GEMM_SMEM (3*STAGE_B)         // 92160/CTA -> 2 CTAs/SM (184320/SM)

__device__ __forceinline__ void gemm_issue_loads(
    uint32_t sstage, const __half* pAh, const __half* pAl,
    const __half* pB, int K, int ko, int tid)
{
    #pragma unroll
    for (int i = 0; i < 2; i++) {
        int c = tid + (i << 8);
        int row = c >> 2;
        int kc  = c & 3;
        uint32_t dst = (uint32_t)(row * TSTR + kc * 8) * 2;
        size_t src = (size_t)row * K + ko + kc * 8;
        cp_async16(sstage + 0*TILE_B + dst, pAh + src);
        cp_async16(sstage + 1*TILE_B + dst, pAl + src);
        cp_async16(sstage + 2*TILE_B + dst, pB  + src);
    }
}

__device__ __forceinline__ void gemm_mainloop(
    const __half* __restrict__ pAh, const __half* __restrict__ pAl,
    const __half* __restrict__ pB,
    int K, char* smem, float acc[4][4][4])
{
    uint32_t sbase = smem_u32(smem);
    const int tid  = threadIdx.x;
    const int lane = tid & 31;
    const int wid  = tid >> 5;
    const int wm   = wid >> 2;
    const int wn   = wid & 3;

    const uint32_t laneA = (uint32_t)((lane & 15) * TSTR + ((lane >> 4) << 3)) * 2;
    const uint32_t laneB = (uint32_t)(((lane & 7) + ((lane >> 4) << 3)) * TSTR
                                      + (((lane >> 3) & 1) << 3)) * 2;

    #pragma unroll
    for (int i = 0; i < 4; i++)
        #pragma unroll
        for (int j = 0; j < 4; j++)
            #pragma unroll
            for (int r = 0; r < 4; r++) acc[i][j][r] = 0.f;

    const int KT = K >> 5;
    gemm_issue_loads(sbase, pAh, pAl, pB, K, 0, tid);
    CP_COMMIT();
    gemm_issue_loads(sbase + STAGE_B, pAh, pAl, pB, K, 32, tid);
    CP_COMMIT();

    int cur = 0, pf = 2;
    for (int kt = 0; kt < KT; kt++) {
        if (kt + 1 < KT) { CP_WAIT(1); } else { CP_WAIT(0); }
        __syncthreads();

        uint32_t st = sbase + (uint32_t)cur * STAGE_B;
        uint32_t sAh = st, sAl = st + TILE_B, sB = st + 2*TILE_B;

        #pragma unroll
        for (int kk = 0; kk < 2; kk++) {
            uint32_t ah[4][4], al[4][4];
            #pragma unroll
            for (int mi = 0; mi < 4; mi++) {
                uint32_t aoff = (uint32_t)(((wm * 64 + mi * 16) * TSTR + kk * 16) * 2);
                ldm4(ah[mi], sAh + aoff + laneA);
                ldm4(al[mi], sAl + aoff + laneA);
            }
            uint32_t b[4][2];
            #pragma unroll
            for (int nj2 = 0; nj2 < 2; nj2++) {
                uint32_t boff = (uint32_t)(((wn * 32 + nj2 * 16) * TSTR + kk * 16) * 2);
                uint32_t r[4];
                ldm4(r, sB + boff + laneB);
                b[nj2*2][0] = r[0]; b[nj2*2][1] = r[1];
                b[nj2*2+1][0] = r[2]; b[nj2*2+1][1] = r[3];
            }
            // Per-acc order fixed: Ah*B then Al*B.
            #pragma unroll
            for (int mi = 0; mi < 4; mi++)
                #pragma unroll
                for (int nj = 0; nj < 4; nj++)
                    mma_f16(acc[mi][nj], ah[mi], b[nj]);
            #pragma unroll
            for (int mi = 0; mi < 4; mi++)
                #pragma unroll
                for (int nj = 0; nj < 4; nj++)
                    mma_f16(acc[mi][nj], al[mi], b[nj]);
        }

        // refill stage (kt+2)%3 == (kt-1)%3: drained (all warps passed the
        // top-of-kt barrier only after finishing compute on kt-1)
        if (kt + 2 < KT) {
            gemm_issue_loads(sbase + (uint32_t)pf * STAGE_B,
                             pAh, pAl, pB, K, (kt + 2) << 5, tid);
            CP_COMMIT();
        }
        cur++; if (cur == 3) cur = 0;
        pf++;  if (pf == 3)  pf = 0;
    }
}

// fp32 epilogue (Q and O projections)
__device__ __forceinline__ void epilogue_f32(float acc[4][4][4], float* Ct, int N)
{
    const int lane = threadIdx.x & 31;
    const int wid  = threadIdx.x >> 5;
    const int wm = wid >> 2, wn = wid & 3;
    const int g = lane >> 2, tg = lane & 3;
    #pragma unroll
    for (int mi = 0; mi < 4; mi++) {
        int row = wm * 64 + mi * 16 + g;
        #pragma unroll
        for (int nj = 0; nj < 4; nj++) {
            int col = wn * 32 + nj * 8 + tg * 2;
            float* p0 = Ct + (size_t)row * N + col;
            float* p1 = p0 + (size_t)8 * N;
            p0[0] = acc[mi][nj][0]; p0[1] = acc[mi][nj][1];
            p1[0] = acc[mi][nj][2]; p1[1] = acc[mi][nj][3];
        }
    }
}

// Fused Q/K/V projection: grid (40, TOK/128). bx 0-31: Q (fp32 out);
// bx 32-35: K (rope + single fp16 via smem staging); bx 36-39: V (hi/lo split).
__global__ void __launch_bounds__(256, 2)
gemm_qkv(const __half* __restrict__ hh, const __half* __restrict__ hl,
         const __half* __restrict__ wq, const __half* __restrict__ wk,
         const __half* __restrict__ wv,
         float* __restrict__ qb,
         __half* __restrict__ k1,
         __half* __restrict__ vh, __half* __restrict__ vl,
         const int* __restrict__ pos32)
{
    extern __shared__ char smem[];
    const int bx = blockIdx.x;
    const int bm = blockIdx.y << 7;
    const int tid = threadIdx.x;
    const __half* bp;
    int bn;
    if (bx < 32)      { bp = wq; bn = bx << 7; }
    else if (bx < 36) { bp = wk; bn = (bx - 32) << 7; }
    else              { bp = wv; bn = (bx - 36) << 7; }

    float acc[4][4][4];
    gemm_mainloop(hh + (size_t)bm * HID, hl + (size_t)bm * HID,
                  bp + (size_t)bn * HID, HID, smem, acc);

    const int lane = tid & 31;
    const int wid  = tid >> 5;
    const int wm = wid >> 2, wn = wid & 3;
    const int g = lane >> 2, tg = lane & 3;

    if (bx < 32) {
        epilogue_f32(acc, qb + (size_t)bm * QD + bn, QD);
    } else if (bx < 36) {
        // K: stage acc to smem, then rope + single fp16 round
        float* sacc = (float*)smem;     // [128][132] = 67584 B <= 92160
        __syncthreads();                // mainloop smem reads done in all warps
        #pragma unroll
        for (int mi = 0; mi < 4; mi++) {
            int row = wm * 64 + mi * 16 + g;
            #pragma unroll
            for (int nj = 0; nj < 4; nj++) {
                int col = wn * 32 + nj * 8 + tg * 2;
                sacc[row * 132 + col]     = acc[mi][nj][0];
                sacc[row * 132 + col + 1] = acc[mi][nj][1];
                sacc[(row + 8) * 132 + col]     = acc[mi][nj][2];
                sacc[(row + 8) * 132 + col + 1] = acc[mi][nj][3];
            }
        }
        __syncthreads();
        const bool is64 = (pos32[1] == 0);
        #pragma unroll
        for (int i = 0; i < 32; i++) {
            int idx = tid + (i << 8);           // 0..8191
            int row = idx >> 6;                 // 0..127
            int d   = idx & 63;
            int t   = bm + row;
            int p = is64 ? pos32[2 * t] : pos32[t];
            float invf = powf(1.0e6f, -(float)d * (1.0f / 64.0f));
            float sv, cv;
            sincosf((float)p * invf, &sv, &cv);
            float x1 = sacc[row * 132 + d];
            float x2 = sacc[row * 132 + d + 64];
            size_t off = (size_t)t * KVD + bn + d;
            k1[off]      = __float2half(x1 * cv - x2 * sv);
            k1[off + 64] = __float2half(x2 * cv + x1 * sv);
        }
    } else {
        // V: split acc to fp16 hi/lo
        #pragma unroll
        for (int mi = 0; mi < 4; mi++) {
            int row = wm * 64 + mi * 16 + g;
            #pragma unroll
            for (int nj = 0; nj < 4; nj++) {
                int col = wn * 32 + nj * 8 + tg * 2;
                size_t off0 = (size_t)(bm + row) * KVD + bn + col;
                size_t off1 = off0 + (size_t)8 * KVD;
                float a0 = acc[mi][nj][0], a1 = acc[mi][nj][1];
                uint32_t hp = cvt2h(a1, a0);
                uint32_t lp = cvt2h(a1 - hhiF(hp), a0 - hloF(hp));
                *(uint32_t*)(vh + off0) = hp;
                *(uint32_t*)(vl + off0) = lp;
                float b0 = acc[mi][nj][2], b1 = acc[mi][nj][3];
                hp = cvt2h(b1, b0);
                lp = cvt2h(b1 - hhiF(hp), b0 - hloF(hp));
                *(uint32_t*)(vh + off1) = hp;
                *(uint32_t*)(vl + off1) = lp;
            }
        }
    }
}

// O-projection
__global__ void __launch_bounds__(256, 2)
gemm_nt_split(const __half* __restrict__ Ah, const __half* __restrict__ Al,
              const __half* __restrict__ B,
              float* __restrict__ C, int N, int K)
{
    extern __shared__ char smem[];
    const int bm = blockIdx.y << 7;
    const int bn = blockIdx.x << 7;
    float acc[4][4][4];
    gemm_mainloop(Ah + (size_t)bm * K, Al + (size_t)bm * K,
                  B + (size_t)bn * K, K, smem, acc);
    epilogue_f32(acc, C + (size_t)bm * N + bn, N);
}

// ===========================================================================
// Flash attention: fp16 mma, FMA-pipe exp2, non-causal.
// QK: Q hi/lo x K single, 2 terms. PV: P single fp16 x V hi/lo, 2 terms.
// Q-RoPE fused into Q-load. Epilogue writes fp16 hi/lo (feeds O-proj).
// ===========================================================================
#define FSTR 136
#define FA_Q_B (128*FSTR*2)
#define FA_T_B (64*FSTR*2)
#define FA_ST_B (3*FA_T_B)                // K, Vh, Vl
#define FA_SMEM (2*FA_Q_B + 2*FA_ST_B)    // 174080

__device__ __forceinline__ void fa_load_kv(
    uint32_t stage, const __half* __restrict__ K1,
    const __half* __restrict__ Vh, const __half* __restrict__ Vl,
    size_t rowbase, int kvoff, int tid)
{
    #pragma unroll
    for (int comp = 0; comp < 3; comp++) {
        const __half* g = (comp == 0) ? K1 : (comp == 1) ? Vh : Vl;
        #pragma unroll
        for (int jj = 0; jj < 4; jj++) {
            int cc = tid + (jj << 8);
            int row = cc >> 4, kc = cc & 15;
            cp_async16(stage + comp * FA_T_B + (uint32_t)(row * 272 + kc * 16),
                       g + (rowbase + row) * KVD + kvoff + kc * 8);
        }
    }
}

__global__ void __launch_bounds__(256, 1)
flash_attn_mma(const float* __restrict__ Q, const int* __restrict__ pos32,
               const __half* __restrict__ K1,
               const __half* __restrict__ Vh, const __half* __restrict__ Vl,
               __half* __restrict__ ah, __half* __restrict__ al)
{
    extern __shared__ char smem[];
    uint32_t sb = smem_u32(smem);
    const uint32_t sQH = sb;
    const uint32_t sQL = sb + FA_Q_B;
    const uint32_t sST = sb + 2 * FA_Q_B;

    const int tid = threadIdx.x, lane = tid & 31, w = tid >> 5;
    const int bh = blockIdx.y, b = bh >> 5, h = bh & 31, kvh = h >> 3;
    const int q0 = blockIdx.x << 7;
    const int g = lane >> 2, t = lane & 3;

    // --- Q load + RoPE + scale(1/sqrt(d)*log2e) + fp16 hi/lo split ---
    const float qsc = 0.08838834764831843f * 1.4426950408889634f;
    const float* Qg = Q + (size_t)(b * SEQ + q0) * QD + h * HD;
    const bool is64 = (pos32[1] == 0);
    #pragma unroll
    for (int i = 0; i < 8; i++) {
        int idx = tid + (i << 8);
        int row = idx >> 4;
        int d4  = (idx & 15) << 2;
        int tok = b * SEQ + q0 + row;
        int p = is64 ? pos32[2 * tok] : pos32[tok];
        float4 xa = *(const float4*)(Qg + (size_t)row * QD + d4);
        float4 xb = *(const float4*)(Qg + (size_t)row * QD + d4 + 64);
        float ya[4], yb[4];
        const float* x1 = &xa.x;
        const float* x2 = &xb.x;
        #pragma unroll
        for (int j = 0; j < 4; j++) {
            int d = d4 + j;
            float invf = powf(1.0e6f, -(float)d * (1.0f / 64.0f));
            float sv, cv;
            sincosf((float)p * invf, &sv, &cv);
            ya[j] = (x1[j] * cv - x2[j] * sv) * qsc;
            yb[j] = (x2[j] * cv + x1[j] * sv) * qsc;
        }
        uint32_t ha01 = cvt2h(ya[1], ya[0]);
        uint32_t ha23 = cvt2h(ya[3], ya[2]);
        uint32_t la01 = cvt2h(ya[1] - hhiF(ha01), ya[0] - hloF(ha01));
        uint32_t la23 = cvt2h(ya[3] - hhiF(ha23), ya[2] - hloF(ha23));
        uint32_t hb01 = cvt2h(yb[1], yb[0]);
        uint32_t hb23 = cvt2h(yb[3], yb[2]);
        uint32_t lb01 = cvt2h(yb[1] - hhiF(hb01), yb[0] - hloF(hb01));
        uint32_t lb23 = cvt2h(yb[3] - hhiF(hb23), yb[2] - hloF(hb23));
        uint32_t off1 = (uint32_t)(row * 272 + d4 * 2);
        uint32_t off2 = (uint32_t)(row * 272 + (d4 + 64) * 2);
        *(uint2*)(smem + (sQH - sb) + off1) = make_uint2(ha01, ha23);
        *(uint2*)(smem + (sQL - sb) + off1) = make_uint2(la01, la23);
        *(uint2*)(smem + (sQH - sb) + off2) = make_uint2(hb01, hb23);
        *(uint2*)(smem + (sQL - sb) + off2) = make_uint2(lb01, lb23);
    }

    float m0 = -1e30f, m1 = -1e30f, l0 = 0.f, l1 = 0.f;
    float o[16][4];
    #pragma unroll
    for (int nd = 0; nd < 16; nd++)
        #pragma unroll
        for (int c = 0; c < 4; c++) o[nd][c] = 0.f;

    const size_t kvbase = (size_t)b * SEQ;
    const int kvoff = kvh * HD;

    const uint32_t lA = (uint32_t)(((lane & 15) * FSTR + ((lane >> 4) << 3)) * 2);
    const uint32_t lB = (uint32_t)((((lane & 7) + ((lane >> 4) << 3)) * FSTR
                                    + (((lane >> 3) & 1) << 3)) * 2);
    const uint32_t lV = (uint32_t)((((lane & 7) + (((lane >> 3) & 1) << 3)) * FSTR
                                    + (((lane >> 4) & 1) << 3)) * 2);

    fa_load_kv(sST, K1, Vh, Vl, kvbase, kvoff, tid);
    CP_COMMIT();

    for (int kt = 0; kt < SEQ / 64; kt++) {
        if (kt + 1 < SEQ / 64) {
            fa_load_kv(sST + ((kt + 1) & 1) * FA_ST_B, K1, Vh, Vl,
                       kvbase + (size_t)(kt + 1) * 64, kvoff, tid);
            CP_COMMIT();
            CP_WAIT(1);
        } else {
            CP_WAIT(0);
        }
        __syncthreads();

        const uint32_t st = sST + (kt & 1) * FA_ST_B;
        const uint32_t sK = st, sVH = st + FA_T_B, sVL = st + 2*FA_T_B;

        float s[8][4];
        #pragma unroll
        for (int j = 0; j < 8; j++)
            #pragma unroll
            for (int c = 0; c < 4; c++) s[j][c] = 0.f;

        #pragma unroll
        for (int kk = 0; kk < 8; kk++) {
            uint32_t qh[4], ql[4];
            uint32_t qoff = (uint32_t)((w * 16 * FSTR + kk * 16) * 2);
            ldm4(qh, sQH + qoff + lA);
            ldm4(ql, sQL + qoff + lA);
            #pragma unroll
            for (int nj2 = 0; nj2 < 4; nj2++) {
                uint32_t koff = (uint32_t)((nj2 * 16 * FSTR + kk * 16) * 2);
                uint32_t rk[4];
                ldm4(rk, sK + koff + lB);
                mma_f16(s[nj2*2],   qh, rk);     mma_f16(s[nj2*2+1], qh, rk + 2);
                mma_f16(s[nj2*2],   ql, rk);     mma_f16(s[nj2*2+1], ql, rk + 2);
            }
        }

        float mx0 = -1e30f, mx1 = -1e30f;
        #pragma unroll
        for (int j = 0; j < 8; j++) {
            mx0 = fmaxf(mx0, fmaxf(s[j][0], s[j][1]));
            mx1 = fmaxf(mx1, fmaxf(s[j][2], s[j][3]));
        }
        mx0 = fmaxf(mx0, __shfl_xor_sync(0xffffffffu, mx0, 1));
        mx0 = fmaxf(mx0, __shfl_xor_sync(0xffffffffu, mx0, 2));
        mx1 = fmaxf(mx1, __shfl_xor_sync(0xffffffffu, mx1, 1));
        mx1 = fmaxf(mx1, __shfl_xor_sync(0xffffffffu, mx1, 2));
        float mn0 = fmaxf(m0, mx0), mn1 = fmaxf(m1, mx1);

        // skip-rescale fast path: alpha == 1 exactly when no new max
        bool newmax = (mn0 > m0) || (mn1 > m1);
        if (__any_sync(0xffffffffu, newmax)) {
            float al0 = fast_exp2(m0 - mn0), al1 = fast_exp2(m1 - mn1);
            l0 *= al0; l1 *= al1;
            #pragma unroll
            for (int nd = 0; nd < 16; nd++) {
                o[nd][0] *= al0; o[nd][1] *= al0;
                o[nd][2] *= al1; o[nd][3] *= al1;
            }
        }
        m0 = mn0; m1 = mn1;

        // P: single-rounded fp16 (l sums use unrounded fp32 values)
        uint32_t pf[4][4];
        float sum0 = 0.f, sum1 = 0.f;
        #pragma unroll
        for (int j = 0; j < 8; j++) {
            float p00 = fast_exp2(s[j][0] - mn0);
            float p01 = fast_exp2(s[j][1] - mn0);
            float p10 = fast_exp2(s[j][2] - mn1);
            float p11 = fast_exp2(s[j][3] - mn1);
            sum0 += p00 + p01; sum1 += p10 + p11;
            int kk2 = j >> 1, hf = (j & 1) << 1;
            pf[kk2][hf]     = cvt2h(p01, p00);
            pf[kk2][hf + 1] = cvt2h(p11, p10);
        }
        sum0 += __shfl_xor_sync(0xffffffffu, sum0, 1);
        sum0 += __shfl_xor_sync(0xffffffffu, sum0, 2);
        sum1 += __shfl_xor_sync(0xffffffffu, sum1, 1);
        sum1 += __shfl_xor_sync(0xffffffffu, sum1, 2);
        l0 += sum0;
        l1 += sum1;

        #pragma unroll
        for (int kk2 = 0; kk2 < 4; kk2++) {
            #pragma unroll
            for (int ndp = 0; ndp < 8; ndp++) {
                uint32_t voff = (uint32_t)((kk2 * 16 * FSTR + ndp * 16) * 2);
                uint32_t vh[4], vl[4];
                ldm4t(vh, sVH + voff + lV);
                ldm4t(vl, sVL + voff + lV);
                mma_f16(o[ndp*2], pf[kk2], vh);   mma_f16(o[ndp*2+1], pf[kk2], vh + 2);
                mma_f16(o[ndp*2], pf[kk2], vl);   mma_f16(o[ndp*2+1], pf[kk2], vl + 2);
            }
        }
        __syncthreads();
    }

    float il0 = 1.f / l0, il1 = 1.f / l1;
    size_t rbase = (size_t)(b * SEQ + q0 + w * 16 + g) * QD + h * HD;
    __half* AH = ah + rbase;
    __half* AL = al + rbase;
    #pragma unroll
    for (int nd = 0; nd < 16; nd++) {
        int col = nd * 8 + t * 2;
        float a0 = o[nd][0] * il0, a1 = o[nd][1] * il0;
        uint32_t hp = cvt2h(a1, a0);
        uint32_t lp = cvt2h(a1 - hhiF(hp), a0 - hloF(hp));
        *(uint32_t*)(AH + col) = hp;
        *(uint32_t*)(AL + col) = lp;
        float b0 = o[nd][2] * il1, b1 = o[nd][3] * il1;
        hp = cvt2h(b1, b0);
        lp = cvt2h(b1 - hhiF(hp), b0 - hloF(hp));
        *(uint32_t*)(AH + (size_t)8 * QD + col) = hp;
        *(uint32_t*)(AL + (size_t)8 * QD + col) = lp;
    }
}

// ---------------------------------------------------------------------------
extern "C" void kernel_launch(void* const* d_in, const int* in_sizes, int n_in,
                              void* d_out, int out_size)
{
    const float* hidden = (const float*)d_in[0];
    const int*   pos    = (const int*)d_in[1];
    const float* Wq     = (const float*)d_in[2];
    const float* Wk     = (const float*)d_in[3];
    const float* Wv     = (const float*)d_in[4];
    const float* Wo     = (const float*)d_in[5];
    float*       out    = (float*)d_out;

    float *qb;
    cudaGetSymbolAddress((void**)&qb, g_q);
    __half *hh,*hl,*wq,*wk,*wv,*wo,*ah,*al,*k1,*vh,*vl;
    cudaGetSymbolAddress((void**)&hh, g_hh); cudaGetSymbolAddress((void**)&hl, g_hl);
    cudaGetSymbolAddress((void**)&wq, g_wq); cudaGetSymbolAddress((void**)&wk, g_wk);
    cudaGetSymbolAddress((void**)&wv, g_wv); cudaGetSymbolAddress((void**)&wo, g_wo);
    cudaGetSymbolAddress((void**)&ah, g_ah); cudaGetSymbolAddress((void**)&al, g_al);
    cudaGetSymbolAddress((void**)&k1, g_k1);
    cudaGetSymbolAddress((void**)&vh, g_vh); cudaGetSymbolAddress((void**)&vl, g_vl);

    cudaFuncSetAttribute(gemm_qkv, cudaFuncAttributeMaxDynamicSharedMemorySize, GEMM_SMEM);
    cudaFuncSetAttribute(gemm_nt_split, cudaFuncAttributeMaxDynamicSharedMemorySize, GEMM_SMEM);
    cudaFuncSetAttribute(flash_attn_mma, cudaFuncAttributeMaxDynamicSharedMemorySize, FA_SMEM);

    // Splits: hidden -> fp16 hi/lo; weights -> single fp16
    split_all_kernel<<<(SPL_N4 + 255)/256, 256>>>(hidden, Wq, Wk, Wv, Wo,
                                                  hh, hl, wq, wk, wv, wo);

    // Fused Q/K/V projections (128x128, 3-stage single-sync, 2 CTAs/SM)
    gemm_qkv<<<dim3(40, TOK/128), 256, GEMM_SMEM>>>(hh, hl, wq, wk, wv,
                                                    qb, k1, vh, vl, pos);

    // Flash attention (Q rope fused, K single / V hi/lo) -> fp16 hi/lo out
    flash_attn_mma<<<dim3(SEQ/128, BATCH*NH), 256, FA_SMEM>>>(qb, pos, k1, vh, vl, ah, al);

    // O projection (2-term fp16)
    gemm_nt_split<<<dim3(HID/128, TOK/128), 256, GEMM_SMEM>>>(ah, al, wo, out, HID, QD);
}

// round 15
// speedup vs baseline: 1.9564x; 1.2104x over previous
#include <cuda_runtime.h>
#include <cuda_bf16.h>
#include <cuda_fp16.h>
#include <math.h>
#include <stdint.h>

// Problem constants
#define BATCH 2
#define SEQ 2048
#define TOK (BATCH*SEQ)          // 4096
#define HID 3584
#define NH 32
#define NKV 4
#define HD 128
#define QD (NH*HD)               // 4096
#define KVD (NKV*HD)             // 512

// fp32 scratch
__device__ float g_q[(size_t)TOK*QD];
// fp16 scratch
__device__ __half g_hh[(size_t)TOK*HID], g_hl[(size_t)TOK*HID];
__device__ __half g_wq[(size_t)QD*HID];
__device__ __half g_wk[(size_t)KVD*HID];
__device__ __half g_wv[(size_t)KVD*HID];
__device__ __half g_wo[(size_t)HID*QD];
__device__ __half g_a1[(size_t)TOK*QD];      // attn out, single fp16
__device__ __half g_k1[(size_t)TOK*KVD];     // K single fp16
__device__ __half g_v1[(size_t)TOK*KVD];     // V single fp16

// ===========================================================================
// PTX helpers
// ===========================================================================
__device__ __forceinline__ uint32_t smem_u32(const void* p) {
    uint32_t a;
    asm("{ .reg .u64 t; cvta.to.shared.u64 t, %1; cvt.u32.u64 %0, t; }" : "=r"(a) : "l"(p));
    return a;
}
__device__ __forceinline__ void cp_async16(uint32_t dst, const void* src) {
    asm volatile("cp.async.cg.shared.global [%0], [%1], 16;" :: "r"(dst), "l"(src) : "memory");
}
#define CP_COMMIT() asm volatile("cp.async.commit_group;" ::: "memory")
#define CP_WAIT(n)  asm volatile("cp.async.wait_group %0;" :: "n"(n) : "memory")

__device__ __forceinline__ void ldm4(uint32_t* r, uint32_t addr) {
    asm volatile("ldmatrix.sync.aligned.m8n8.x4.shared.b16 {%0,%1,%2,%3}, [%4];"
                 : "=r"(r[0]), "=r"(r[1]), "=r"(r[2]), "=r"(r[3]) : "r"(addr));
}
__device__ __forceinline__ void ldm4t(uint32_t* r, uint32_t addr) {
    asm volatile("ldmatrix.sync.aligned.m8n8.x4.trans.shared.b16 {%0,%1,%2,%3}, [%4];"
                 : "=r"(r[0]), "=r"(r[1]), "=r"(r[2]), "=r"(r[3]) : "r"(addr));
}
__device__ __forceinline__ void mma_f16(float* c, const uint32_t* a, const uint32_t* b) {
    asm volatile("mma.sync.aligned.m16n8k16.row.col.f32.f16.f16.f32 "
                 "{%0,%1,%2,%3}, {%4,%5,%6,%7}, {%8,%9}, {%0,%1,%2,%3};"
                 : "+f"(c[0]), "+f"(c[1]), "+f"(c[2]), "+f"(c[3])
                 : "r"(a[0]), "r"(a[1]), "r"(a[2]), "r"(a[3]), "r"(b[0]), "r"(b[1]));
}
__device__ __forceinline__ uint32_t cvt2h(float hi, float lo) {
    uint32_t r;
    asm("cvt.rn.f16x2.f32 %0, %1, %2;" : "=r"(r) : "f"(hi), "f"(lo));
    return r;
}
__device__ __forceinline__ float hloF(uint32_t p) {
    return __half2float(__ushort_as_half((unsigned short)(p & 0xffffu)));
}
__device__ __forceinline__ float hhiF(uint32_t p) {
    return __half2float(__ushort_as_half((unsigned short)(p >> 16)));
}

// fast 2^t on the FMA pipe (no MUFU); exp2(0) == 1.0 exactly
__device__ __forceinline__ float fast_exp2(float t) {
    t = fmaxf(t, -120.0f);
    float r = t + 12582912.0f;
    float n = r - 12582912.0f;
    float f = t - n;
    int   ni = __float_as_int(r);
    float p = 1.3392112e-3f;
    p = fmaf(p, f, 9.6183463e-3f);
    p = fmaf(p, f, 5.5503277e-2f);
    p = fmaf(p, f, 2.4022652e-1f);
    p = fmaf(p, f, 6.9314718e-1f);
    p = fmaf(p, f, 1.0f);
    return __int_as_float(__float_as_int(p) + (ni << 23));
}

// ===========================================================================
// Fused split: hidden -> fp16 hi/lo; weights -> single-rounded fp16.
// ===========================================================================
#define SPL_N0 (TOK*HID)
#define SPL_N1 (SPL_N0 + QD*HID)
#define SPL_N2 (SPL_N1 + KVD*HID)
#define SPL_N3 (SPL_N2 + KVD*HID)
#define SPL_N4 (SPL_N3 + HID*QD)

__global__ void split_all_kernel(
    const float* __restrict__ x0, const float* __restrict__ x1,
    const float* __restrict__ x2, const float* __restrict__ x3,
    const float* __restrict__ x4,
    __half* __restrict__ hh, __half* __restrict__ hl,
    __half* __restrict__ wq, __half* __restrict__ wk,
    __half* __restrict__ wv, __half* __restrict__ wo)
{
    int i = blockIdx.x * 256 + threadIdx.x;
    if (i >= SPL_N4) return;
    if (i < SPL_N0) {
        float v = x0[i];
        __half h = __float2half(v);
        hh[i] = h;
        hl[i] = __float2half(v - __half2float(h));
    } else if (i < SPL_N1) {
        int off = i - SPL_N0; wq[off] = __float2half(x1[off]);
    } else if (i < SPL_N2) {
        int off = i - SPL_N1; wk[off] = __float2half(x2[off]);
    } else if (i < SPL_N3) {
        int off = i - SPL_N2; wv[off] = __float2half(x3[off]);
    } else {
        int off = i - SPL_N3; wo[off] = __float2half(x4[off]);
    }
}

// ===========================================================================
// mma.sync fp16 GEMM mainloop, templated on SPLIT_A:
//   SPLIT_A: C = (Ah+Al)*B^T (2 terms);  else C = A*B^T (1 term).
// 128x128x32 tiles, 3-stage cp.async, single barrier per kt, 2 CTAs/SM.
// ===========================================================================
#define TSTR 40
#define TILE_B (128*TSTR*2)           // 10240

template<bool SPLIT_A>
__device__ __forceinline__ void gemm_issue_loads(
    uint32_t sstage, const __half* pAh, const __half* pAl,
    const __half* pB, int K, int ko, int tid)
{
    constexpr uint32_t BOFF = SPLIT_A ? 2u*TILE_B : 1u*TILE_B;
    #pragma unroll
    for (int i = 0; i < 2; i++) {
        int c = tid + (i << 8);
        int row = c >> 2;
        int kc  = c & 3;
        uint32_t dst = (uint32_t)(row * TSTR + kc * 8) * 2;
        size_t src = (size_t)row * K + ko + kc * 8;
        cp_async16(sstage + dst, pAh + src);
        if (SPLIT_A) cp_async16(sstage + TILE_B + dst, pAl + src);
        cp_async16(sstage + BOFF + dst, pB + src);
    }
}

template<bool SPLIT_A>
__device__ __forceinline__ void gemm_mainloop(
    const __half* __restrict__ pAh, const __half* __restrict__ pAl,
    const __half* __restrict__ pB,
    int K, char* smem, float acc[4][4][4])
{
    constexpr uint32_t STB  = (SPLIT_A ? 3u : 2u) * TILE_B;
    constexpr uint32_t BOFF = SPLIT_A ? 2u*TILE_B : 1u*TILE_B;
    uint32_t sbase = smem_u32(smem);
    const int tid  = threadIdx.x;
    const int lane = tid & 31;
    const int wid  = tid >> 5;
    const int wm   = wid >> 2;
    const int wn   = wid & 3;

    const uint32_t laneA = (uint32_t)((lane & 15) * TSTR + ((lane >> 4) << 3)) * 2;
    const uint32_t laneB = (uint32_t)(((lane & 7) + ((lane >> 4) << 3)) * TSTR
                                      + (((lane >> 3) & 1) << 3)) * 2;

    #pragma unroll
    for (int i = 0; i < 4; i++)
        #pragma unroll
        for (int j = 0; j < 4; j++)
            #pragma unroll
            for (int r = 0; r < 4; r++) acc[i][j][r] = 0.f;

    const int KT = K >> 5;
    gemm_issue_loads<SPLIT_A>(sbase, pAh, pAl, pB, K, 0, tid);
    CP_COMMIT();
    gemm_issue_loads<SPLIT_A>(sbase + STB, pAh, pAl, pB, K, 32, tid);
    CP_COMMIT();

    int cur = 0, pf = 2;
    for (int kt = 0; kt < KT; kt++) {
        if (kt + 1 < KT) { CP_WAIT(1); } else { CP_WAIT(0); }
        __syncthreads();

        uint32_t st = sbase + (uint32_t)cur * STB;

        #pragma unroll
        for (int kk = 0; kk < 2; kk++) {
            uint32_t ah[4][4], al[4][4];
            #pragma unroll
            for (int mi = 0; mi < 4; mi++) {
                uint32_t aoff = (uint32_t)(((wm * 64 + mi * 16) * TSTR + kk * 16) * 2);
                ldm4(ah[mi], st + aoff + laneA);
                if (SPLIT_A) ldm4(al[mi], st + TILE_B + aoff + laneA);
            }
            uint32_t b[4][2];
            #pragma unroll
            for (int nj2 = 0; nj2 < 2; nj2++) {
                uint32_t boff = (uint32_t)(((wn * 32 + nj2 * 16) * TSTR + kk * 16) * 2);
                uint32_t r[4];
                ldm4(r, st + BOFF + boff + laneB);
                b[nj2*2][0] = r[0]; b[nj2*2][1] = r[1];
                b[nj2*2+1][0] = r[2]; b[nj2*2+1][1] = r[3];
            }
            #pragma unroll
            for (int mi = 0; mi < 4; mi++)
                #pragma unroll
                for (int nj = 0; nj < 4; nj++)
                    mma_f16(acc[mi][nj], ah[mi], b[nj]);
            if (SPLIT_A) {
                #pragma unroll
                for (int mi = 0; mi < 4; mi++)
                    #pragma unroll
                    for (int nj = 0; nj < 4; nj++)
                        mma_f16(acc[mi][nj], al[mi], b[nj]);
            }
        }

        // refill stage (kt+2)%3 == (kt-1)%3: drained after top-of-kt barrier
        if (kt + 2 < KT) {
            gemm_issue_loads<SPLIT_A>(sbase + (uint32_t)pf * STB,
                                      pAh, pAl, pB, K, (kt + 2) << 5, tid);
            CP_COMMIT();
        }
        cur++; if (cur == 3) cur = 0;
        pf++;  if (pf == 3)  pf = 0;
    }
}

#define GEMM3_SMEM (3*3*TILE_B)       // 92160 (split-A path; >= K epi 67584)
#define GEMM2_SMEM (3*2*TILE_B)       // 61440 (single-A path)

// fp32 epilogue (Q and O projections)
__device__ __forceinline__ void epilogue_f32(float acc[4][4][4], float* Ct, int N)
{
    const int lane = threadIdx.x & 31;
    const int wid  = threadIdx.x >> 5;
    const int wm = wid >> 2, wn = wid & 3;
    const int g = lane >> 2, tg = lane & 3;
    #pragma unroll
    for (int mi = 0; mi < 4; mi++) {
        int row = wm * 64 + mi * 16 + g;
        #pragma unroll
        for (int nj = 0; nj < 4; nj++) {
            int col = wn * 32 + nj * 8 + tg * 2;
            float* p0 = Ct + (size_t)row * N + col;
            float* p1 = p0 + (size_t)8 * N;
            p0[0] = acc[mi][nj][0]; p0[1] = acc[mi][nj][1];
            p1[0] = acc[mi][nj][2]; p1[1] = acc[mi][nj][3];
        }
    }
}

// Fused Q/K/V projection: grid (40, TOK/128). bx 0-31: Q (fp32 out);
// bx 32-35: K (rope + single fp16); bx 36-39: V (single fp16).
__global__ void __launch_bounds__(256, 2)
gemm_qkv(const __half* __restrict__ hh, const __half* __restrict__ hl,
         const __half* __restrict__ wq, const __half* __restrict__ wk,
         const __half* __restrict__ wv,
         float* __restrict__ qb,
         __half* __restrict__ k1, __half* __restrict__ v1,
         const int* __restrict__ pos32)
{
    extern __shared__ char smem[];
    const int bx = blockIdx.x;
    const int bm = blockIdx.y << 7;
    const int tid = threadIdx.x;
    const __half* bp;
    int bn;
    if (bx < 32)      { bp = wq; bn = bx << 7; }
    else if (bx < 36) { bp = wk; bn = (bx - 32) << 7; }
    else              { bp = wv; bn = (bx - 36) << 7; }

    float acc[4][4][4];
    gemm_mainloop<true>(hh + (size_t)bm * HID, hl + (size_t)bm * HID,
                        bp + (size_t)bn * HID, HID, smem, acc);

    const int lane = tid & 31;
    const int wid  = tid >> 5;
    const int wm = wid >> 2, wn = wid & 3;
    const int g = lane >> 2, tg = lane & 3;

    if (bx < 32) {
        epilogue_f32(acc, qb + (size_t)bm * QD + bn, QD);
    } else if (bx < 36) {
        // K: stage acc to smem, then rope + single fp16 round
        float* sacc = (float*)smem;     // [128][132] = 67584 B <= 92160
        __syncthreads();
        #pragma unroll
        for (int mi = 0; mi < 4; mi++) {
            int row = wm * 64 + mi * 16 + g;
            #pragma unroll
            for (int nj = 0; nj < 4; nj++) {
                int col = wn * 32 + nj * 8 + tg * 2;
                sacc[row * 132 + col]     = acc[mi][nj][0];
                sacc[row * 132 + col + 1] = acc[mi][nj][1];
                sacc[(row + 8) * 132 + col]     = acc[mi][nj][2];
                sacc[(row + 8) * 132 + col + 1] = acc[mi][nj][3];
            }
        }
        __syncthreads();
        const bool is64 = (pos32[1] == 0);
        #pragma unroll
        for (int i = 0; i < 32; i++) {
            int idx = tid + (i << 8);
            int row = idx >> 6;
            int d   = idx & 63;
            int t   = bm + row;
            int p = is64 ? pos32[2 * t] : pos32[t];
            float invf = powf(1.0e6f, -(float)d * (1.0f / 64.0f));
            float sv, cv;
            sincosf((float)p * invf, &sv, &cv);
            float x1 = sacc[row * 132 + d];
            float x2 = sacc[row * 132 + d + 64];
            size_t off = (size_t)t * KVD + bn + d;
            k1[off]      = __float2half(x1 * cv - x2 * sv);
            k1[off + 64] = __float2half(x2 * cv + x1 * sv);
        }
    } else {
        // V: single fp16 round
        #pragma unroll
        for (int mi = 0; mi < 4; mi++) {
            int row = wm * 64 + mi * 16 + g;
            #pragma unroll
            for (int nj = 0; nj < 4; nj++) {
                int col = wn * 32 + nj * 8 + tg * 2;
                size_t off0 = (size_t)(bm + row) * KVD + bn + col;
                size_t off1 = off0 + (size_t)8 * KVD;
                *(uint32_t*)(v1 + off0) = cvt2h(acc[mi][nj][1], acc[mi][nj][0]);
                *(uint32_t*)(v1 + off1) = cvt2h(acc[mi][nj][3], acc[mi][nj][2]);
            }
        }
    }
}

// O-projection: single-term fp16 (A = attn out single, B = Wo single)
__global__ void __launch_bounds__(256, 2)
gemm_nt_single(const __half* __restrict__ A, const __half* __restrict__ B,
               float* __restrict__ C, int N, int K)
{
    extern __shared__ char smem[];
    const int bm = blockIdx.y << 7;
    const int bn = blockIdx.x << 7;
    float acc[4][4][4];
    gemm_mainloop<false>(A + (size_t)bm * K, nullptr,
                         B + (size_t)bn * K, K, smem, acc);
    epilogue_f32(acc, C + (size_t)bm * N + bn, N);
}

// ===========================================================================
// Flash attention: fp16 mma, FMA-pipe exp2, non-causal.
// QK: Q hi/lo x K single (2 terms). PV: P single x V single (1 term).
// Q-RoPE fused into Q-load. Epilogue writes single fp16 (feeds O-proj).
// ===========================================================================
#define FSTR 136
#define FA_Q_B (128*FSTR*2)
#define FA_T_B (64*FSTR*2)
#define FA_ST_B (2*FA_T_B)                // K, V
#define FA_SMEM (2*FA_Q_B + 2*FA_ST_B)    // 139264

__device__ __forceinline__ void fa_load_kv(
    uint32_t stage, const __half* __restrict__ K1, const __half* __restrict__ V1,
    size_t rowbase, int kvoff, int tid)
{
    #pragma unroll
    for (int comp = 0; comp < 2; comp++) {
        const __half* g = (comp == 0) ? K1 : V1;
        #pragma unroll
        for (int jj = 0; jj < 4; jj++) {
            int cc = tid + (jj << 8);
            int row = cc >> 4, kc = cc & 15;
            cp_async16(stage + comp * FA_T_B + (uint32_t)(row * 272 + kc * 16),
                       g + (rowbase + row) * KVD + kvoff + kc * 8);
        }
    }
}

__global__ void __launch_bounds__(256, 1)
flash_attn_mma(const float* __restrict__ Q, const int* __restrict__ pos32,
               const __half* __restrict__ K1, const __half* __restrict__ V1,
               __half* __restrict__ a1)
{
    extern __shared__ char smem[];
    uint32_t sb = smem_u32(smem);
    const uint32_t sQH = sb;
    const uint32_t sQL = sb + FA_Q_B;
    const uint32_t sST = sb + 2 * FA_Q_B;

    const int tid = threadIdx.x, lane = tid & 31, w = tid >> 5;
    const int bh = blockIdx.y, b = bh >> 5, h = bh & 31, kvh = h >> 3;
    const int q0 = blockIdx.x << 7;
    const int g = lane >> 2, t = lane & 3;

    // --- Q load + RoPE + scale(1/sqrt(d)*log2e) + fp16 hi/lo split ---
    const float qsc = 0.08838834764831843f * 1.4426950408889634f;
    const float* Qg = Q + (size_t)(b * SEQ + q0) * QD + h * HD;
    const bool is64 = (pos32[1] == 0);
    #pragma unroll
    for (int i = 0; i < 8; i++) {
        int idx = tid + (i << 8);
        int row = idx >> 4;
        int d4  = (idx & 15) << 2;
        int tok = b * SEQ + q0 + row;
        int p = is64 ? pos32[2 * tok] : pos32[tok];
        float4 xa = *(const float4*)(Qg + (size_t)row * QD + d4);
        float4 xb = *(const float4*)(Qg + (size_t)row * QD + d4 + 64);
        float ya[4], yb[4];
        const float* x1 = &xa.x;
        const float* x2 = &xb.x;
        #pragma unroll
        for (int j = 0; j < 4; j++) {
            int d = d4 + j;
            float invf = powf(1.0e6f, -(float)d * (1.0f / 64.0f));
            float sv, cv;
            sincosf((float)p * invf, &sv, &cv);
            ya[j] = (x1[j] * cv - x2[j] * sv) * qsc;
            yb[j] = (x2[j] * cv + x1[j] * sv) * qsc;
        }
        uint32_t ha01 = cvt2h(ya[1], ya[0]);
        uint32_t ha23 = cvt2h(ya[3], ya[2]);
        uint32_t la01 = cvt2h(ya[1] - hhiF(ha01), ya[0] - hloF(ha01));
        uint32_t la23 = cvt2h(ya[3] - hhiF(ha23), ya[2] - hloF(ha23));
        uint32_t hb01 = cvt2h(yb[1], yb[0]);
        uint32_t hb23 = cvt2h(yb[3], yb[2]);
        uint32_t lb01 = cvt2h(yb[1] - hhiF(hb01), yb[0] - hloF(hb01));
        uint32_t lb23 = cvt2h(yb[3] - hhiF(hb23), yb[2] - hloF(hb23));
        uint32_t off1 = (uint32_t)(row * 272 + d4 * 2);
        uint32_t off2 = (uint32_t)(row * 272 + (d4 + 64) * 2);
        *(uint2*)(smem + (sQH - sb) + off1) = make_uint2(ha01, ha23);
        *(uint2*)(smem + (sQL - sb) + off1) = make_uint2(la01, la23);
        *(uint2*)(smem + (sQH - sb) + off2) = make_uint2(hb01, hb23);
        *(uint2*)(smem + (sQL - sb) + off2) = make_uint2(lb01, lb23);
    }

    float m0 = -1e30f, m1 = -1e30f, l0 = 0.f, l1 = 0.f;
    float o[16][4];
    #pragma unroll
    for (int nd = 0; nd < 16; nd++)
        #pragma unroll
        for (int c = 0; c < 4; c++) o[nd][c] = 0.f;

    const size_t kvbase = (size_t)b * SEQ;
    const int kvoff = kvh * HD;

    const uint32_t lA = (uint32_t)(((lane & 15) * FSTR + ((lane >> 4) << 3)) * 2);
    const uint32_t lB = (uint32_t)((((lane & 7) + ((lane >> 4) << 3)) * FSTR
                                    + (((lane >> 3) & 1) << 3)) * 2);
    const uint32_t lV = (uint32_t)((((lane & 7) + (((lane >> 3) & 1) << 3)) * FSTR
                                    + (((lane >> 4) & 1) << 3)) * 2);

    fa_load_kv(sST, K1, V1, kvbase, kvoff, tid);
    CP_COMMIT();

    for (int kt = 0; kt < SEQ / 64; kt++) {
        if (kt + 1 < SEQ / 64) {
            fa_load_kv(sST + ((kt + 1) & 1) * FA_ST_B, K1, V1,
                       kvbase + (size_t)(kt + 1) * 64, kvoff, tid);
            CP_COMMIT();
            CP_WAIT(1);
        } else {
            CP_WAIT(0);
        }
        __syncthreads();

        const uint32_t st = sST + (kt & 1) * FA_ST_B;
        const uint32_t sK = st, sV = st + FA_T_B;

        float s[8][4];
        #pragma unroll
        for (int j = 0; j < 8; j++)
            #pragma unroll
            for (int c = 0; c < 4; c++) s[j][c] = 0.f;

        #pragma unroll
        for (int kk = 0; kk < 8; kk++) {
            uint32_t qh[4], ql[4];
            uint32_t qoff = (uint32_t)((w * 16 * FSTR + kk * 16) * 2);
            ldm4(qh, sQH + qoff + lA);
            ldm4(ql, sQL + qoff + lA);
            #pragma unroll
            for (int nj2 = 0; nj2 < 4; nj2++) {
                uint32_t koff = (uint32_t)((nj2 * 16 * FSTR + kk * 16) * 2);
                uint32_t rk[4];
                ldm4(rk, sK + koff + lB);
                mma_f16(s[nj2*2],   qh, rk);     mma_f16(s[nj2*2+1], qh, rk + 2);
                mma_f16(s[nj2*2],   ql, rk);     mma_f16(s[nj2*2+1], ql, rk + 2);
            }
        }

        float mx0 = -1e30f, mx1 = -1e30f;
        #pragma unroll
        for (int j = 0; j < 8; j++) {
            mx0 = fmaxf(mx0, fmaxf(s[j][0], s[j][1]));
            mx1 = fmaxf(mx1, fmaxf(s[j][2], s[j][3]));
        }
        mx0 = fmaxf(mx0, __shfl_xor_sync(0xffffffffu, mx0, 1));
        mx0 = fmaxf(mx0, __shfl_xor_sync(0xffffffffu, mx0, 2));
        mx1 = fmaxf(mx1, __shfl_xor_sync(0xffffffffu, mx1, 1));
        mx1 = fmaxf(mx1, __shfl_xor_sync(0xffffffffu, mx1, 2));
        float mn0 = fmaxf(m0, mx0), mn1 = fmaxf(m1, mx1);

        bool newmax = (mn0 > m0) || (mn1 > m1);
        if (__any_sync(0xffffffffu, newmax)) {
            float al0 = fast_exp2(m0 - mn0), al1 = fast_exp2(m1 - mn1);
            l0 *= al0; l1 *= al1;
            #pragma unroll
            for (int nd = 0; nd < 16; nd++) {
                o[nd][0] *= al0; o[nd][1] *= al0;
                o[nd][2] *= al1; o[nd][3] *= al1;
            }
        }
        m0 = mn0; m1 = mn1;

        uint32_t pf[4][4];
        float sum0 = 0.f, sum1 = 0.f;
        #pragma unroll
        for (int j = 0; j < 8; j++) {
            float p00 = fast_exp2(s[j][0] - mn0);
            float p01 = fast_exp2(s[j][1] - mn0);
            float p10 = fast_exp2(s[j][2] - mn1);
            float p11 = fast_exp2(s[j][3] - mn1);
            sum0 += p00 + p01; sum1 += p10 + p11;
            int kk2 = j >> 1, hf = (j & 1) << 1;
            pf[kk2][hf]     = cvt2h(p01, p00);
            pf[kk2][hf + 1] = cvt2h(p11, p10);
        }
        sum0 += __shfl_xor_sync(0xffffffffu, sum0, 1);
        sum0 += __shfl_xor_sync(0xffffffffu, sum0, 2);
        sum1 += __shfl_xor_sync(0xffffffffu, sum1, 1);
        sum1 += __shfl_xor_sync(0xffffffffu, sum1, 2);
        l0 += sum0;
        l1 += sum1;

        #pragma unroll
        for (int kk2 = 0; kk2 < 4; kk2++) {
            #pragma unroll
            for (int ndp = 0; ndp < 8; ndp++) {
                uint32_t voff = (uint32_t)((kk2 * 16 * FSTR + ndp * 16) * 2);
                uint32_t v[4];
                ldm4t(v, sV + voff + lV);
                mma_f16(o[ndp*2], pf[kk2], v);   mma_f16(o[ndp*2+1], pf[kk2], v + 2);
            }
        }
        __syncthreads();
    }

    float il0 = 1.f / l0, il1 = 1.f / l1;
    size_t rbase = (size_t)(b * SEQ + q0 + w * 16 + g) * QD + h * HD;
    __half* A1 = a1 + rbase;
    #pragma unroll
    for (int nd = 0; nd < 16; nd++) {
        int col = nd * 8 + t * 2;
        *(uint32_t*)(A1 + col) = cvt2h(o[nd][1] * il0, o[nd][0] * il0);
        *(uint32_t*)(A1 + (size_t)8 * QD + col) = cvt2h(o[nd][3] * il1, o[nd][2] * il1);
    }
}

// ---------------------------------------------------------------------------
extern "C" void kernel_launch(void* const* d_in, const int* in_sizes, int n_in,
                              void* d_out, int out_size)
{
    const float* hidden = (const float*)d_in[0];
    const int*   pos    = (const int*)d_in[1];
    const float* Wq     = (const float*)d_in[2];
    const float* Wk     = (const float*)d_in[3];
    const float* Wv     = (const float*)d_in[4];
    const float* Wo     = (const float*)d_in[5];
    float*       out    = (float*)d_out;

    float *qb;
    cudaGetSymbolAddress((void**)&qb, g_q);
    __half *hh,*hl,*wq,*wk,*wv,*wo,*a1,*k1,*v1;
    cudaGetSymbolAddress((void**)&hh, g_hh); cudaGetSymbolAddress((void**)&hl, g_hl);
    cudaGetSymbolAddress((void**)&wq, g_wq); cudaGetSymbolAddress((void**)&wk, g_wk);
    cudaGetSymbolAddress((void**)&wv, g_wv); cudaGetSymbolAddress((void**)&wo, g_wo);
    cudaGetSymbolAddress((void**)&a1, g_a1);
    cudaGetSymbolAddress((void**)&k1, g_k1);
    cudaGetSymbolAddress((void**)&v1, g_v1);

    cudaFuncSetAttribute(gemm_qkv, cudaFuncAttributeMaxDynamicSharedMemorySize, GEMM3_SMEM);
    cudaFuncSetAttribute(gemm_nt_single, cudaFuncAttributeMaxDynamicSharedMemorySize, GEMM2_SMEM);
    cudaFuncSetAttribute(flash_attn_mma, cudaFuncAttributeMaxDynamicSharedMemorySize, FA_SMEM);

    // Splits: hidden -> fp16 hi/lo; weights -> single fp16
    split_all_kernel<<<(SPL_N4 + 255)/256, 256>>>(hidden, Wq, Wk, Wv, Wo,
                                                  hh, hl, wq, wk, wv, wo);

    // Fused Q/K/V projections (2-term A, single-rounded K/V epilogues)
    gemm_qkv<<<dim3(40, TOK/128), 256, GEMM3_SMEM>>>(hh, hl, wq, wk, wv,
                                                     qb, k1, v1, pos);

    // Flash attention (Q rope fused; QK 2-term, PV 1-term) -> single fp16 out
    flash_attn_mma<<<dim3(SEQ/128, BATCH*NH), 256, FA_SMEM>>>(qb, pos, k1, v1, a1);

    // O projection (1-term fp16)
    gemm_nt_single<<<dim3(HID/128, TOK/128), 256, GEMM2_SMEM>>>(a1, wo, out, HID, QD);
}

// round 16
// speedup vs baseline: 2.3899x; 1.2216x over previous
#include <cuda_runtime.h>
#include <cuda_bf16.h>
#include <cuda_fp16.h>
#include <math.h>
#include <stdint.h>

// Problem constants
#define BATCH 2
#define SEQ 2048
#define TOK (BATCH*SEQ)          // 4096
#define HID 3584
#define NH 32
#define NKV 4
#define HD 128
#define QD (NH*HD)               // 4096
#define KVD (NKV*HD)             // 512

// fp32 scratch
__device__ float g_q[(size_t)TOK*QD];
// fp16 scratch (all single-rounded except flash-internal Q split)
__device__ __half g_h1[(size_t)TOK*HID];     // hidden single fp16
__device__ __half g_wq[(size_t)QD*HID];
__device__ __half g_wk[(size_t)KVD*HID];
__device__ __half g_wv[(size_t)KVD*HID];
__device__ __half g_wo[(size_t)HID*QD];
__device__ __half g_a1[(size_t)TOK*QD];      // attn out single fp16
__device__ __half g_k1[(size_t)TOK*KVD];     // K single fp16
__device__ __half g_v1[(size_t)TOK*KVD];     // V single fp16

// ===========================================================================
// PTX helpers
// ===========================================================================
__device__ __forceinline__ uint32_t smem_u32(const void* p) {
    uint32_t a;
    asm("{ .reg .u64 t; cvta.to.shared.u64 t, %1; cvt.u32.u64 %0, t; }" : "=r"(a) : "l"(p));
    return a;
}
__device__ __forceinline__ void cp_async16(uint32_t dst, const void* src) {
    asm volatile("cp.async.cg.shared.global [%0], [%1], 16;" :: "r"(dst), "l"(src) : "memory");
}
#define CP_COMMIT() asm volatile("cp.async.commit_group;" ::: "memory")
#define CP_WAIT(n)  asm volatile("cp.async.wait_group %0;" :: "n"(n) : "memory")

__device__ __forceinline__ void ldm4(uint32_t* r, uint32_t addr) {
    asm volatile("ldmatrix.sync.aligned.m8n8.x4.shared.b16 {%0,%1,%2,%3}, [%4];"
                 : "=r"(r[0]), "=r"(r[1]), "=r"(r[2]), "=r"(r[3]) : "r"(addr));
}
__device__ __forceinline__ void ldm4t(uint32_t* r, uint32_t addr) {
    asm volatile("ldmatrix.sync.aligned.m8n8.x4.trans.shared.b16 {%0,%1,%2,%3}, [%4];"
                 : "=r"(r[0]), "=r"(r[1]), "=r"(r[2]), "=r"(r[3]) : "r"(addr));
}
__device__ __forceinline__ void mma_f16(float* c, const uint32_t* a, const uint32_t* b) {
    asm volatile("mma.sync.aligned.m16n8k16.row.col.f32.f16.f16.f32 "
                 "{%0,%1,%2,%3}, {%4,%5,%6,%7}, {%8,%9}, {%0,%1,%2,%3};"
                 : "+f"(c[0]), "+f"(c[1]), "+f"(c[2]), "+f"(c[3])
                 : "r"(a[0]), "r"(a[1]), "r"(a[2]), "r"(a[3]), "r"(b[0]), "r"(b[1]));
}
__device__ __forceinline__ uint32_t cvt2h(float hi, float lo) {
    uint32_t r;
    asm("cvt.rn.f16x2.f32 %0, %1, %2;" : "=r"(r) : "f"(hi), "f"(lo));
    return r;
}
__device__ __forceinline__ float hloF(uint32_t p) {
    return __half2float(__ushort_as_half((unsigned short)(p & 0xffffu)));
}
__device__ __forceinline__ float hhiF(uint32_t p) {
    return __half2float(__ushort_as_half((unsigned short)(p >> 16)));
}

// fast 2^t on the FMA pipe (no MUFU); exp2(0) == 1.0 exactly
__device__ __forceinline__ float fast_exp2(float t) {
    t = fmaxf(t, -120.0f);
    float r = t + 12582912.0f;
    float n = r - 12582912.0f;
    float f = t - n;
    int   ni = __float_as_int(r);
    float p = 1.3392112e-3f;
    p = fmaf(p, f, 9.6183463e-3f);
    p = fmaf(p, f, 5.5503277e-2f);
    p = fmaf(p, f, 2.4022652e-1f);
    p = fmaf(p, f, 6.9314718e-1f);
    p = fmaf(p, f, 1.0f);
    return __int_as_float(__float_as_int(p) + (ni << 23));
}

// ===========================================================================
// Fused split: all five fp32 -> single-rounded fp16.
// ===========================================================================
#define SPL_N0 (TOK*HID)
#define SPL_N1 (SPL_N0 + QD*HID)
#define SPL_N2 (SPL_N1 + KVD*HID)
#define SPL_N3 (SPL_N2 + KVD*HID)
#define SPL_N4 (SPL_N3 + HID*QD)

__global__ void split_all_kernel(
    const float* __restrict__ x0, const float* __restrict__ x1,
    const float* __restrict__ x2, const float* __restrict__ x3,
    const float* __restrict__ x4,
    __half* __restrict__ h1,
    __half* __restrict__ wq, __half* __restrict__ wk,
    __half* __restrict__ wv, __half* __restrict__ wo)
{
    int i = blockIdx.x * 256 + threadIdx.x;
    if (i >= SPL_N4) return;
    if (i < SPL_N0) {
        h1[i] = __float2half(x0[i]);
    } else if (i < SPL_N1) {
        int off = i - SPL_N0; wq[off] = __float2half(x1[off]);
    } else if (i < SPL_N2) {
        int off = i - SPL_N1; wk[off] = __float2half(x2[off]);
    } else if (i < SPL_N3) {
        int off = i - SPL_N2; wv[off] = __float2half(x3[off]);
    } else {
        int off = i - SPL_N3; wo[off] = __float2half(x4[off]);
    }
}

// ===========================================================================
// mma.sync fp16 GEMM mainloop (single-term): C = A * B^T.
// 128x128x32 tiles, 3-stage cp.async, single barrier per kt, 2 CTAs/SM.
// ===========================================================================
#define TSTR 40
#define TILE_B (128*TSTR*2)           // 10240
#define STAGE_B (2*TILE_B)            // 20480 (A, B)
#define GEMM_SMEM_MIN (3*STAGE_B)     // 61440
#define GEMMQ_SMEM 67584              // max(61440, K-epilogue 67584)

__device__ __forceinline__ void gemm_issue_loads(
    uint32_t sstage, const __half* pA, const __half* pB, int K, int ko, int tid)
{
    #pragma unroll
    for (int i = 0; i < 2; i++) {
        int c = tid + (i << 8);
        int row = c >> 2;
        int kc  = c & 3;
        uint32_t dst = (uint32_t)(row * TSTR + kc * 8) * 2;
        size_t src = (size_t)row * K + ko + kc * 8;
        cp_async16(sstage + dst, pA + src);
        cp_async16(sstage + TILE_B + dst, pB + src);
    }
}

__device__ __forceinline__ void gemm_mainloop(
    const __half* __restrict__ pA, const __half* __restrict__ pB,
    int K, char* smem, float acc[4][4][4])
{
    uint32_t sbase = smem_u32(smem);
    const int tid  = threadIdx.x;
    const int lane = tid & 31;
    const int wid  = tid >> 5;
    const int wm   = wid >> 2;
    const int wn   = wid & 3;

    const uint32_t laneA = (uint32_t)((lane & 15) * TSTR + ((lane >> 4) << 3)) * 2;
    const uint32_t laneB = (uint32_t)(((lane & 7) + ((lane >> 4) << 3)) * TSTR
                                      + (((lane >> 3) & 1) << 3)) * 2;

    #pragma unroll
    for (int i = 0; i < 4; i++)
        #pragma unroll
        for (int j = 0; j < 4; j++)
            #pragma unroll
            for (int r = 0; r < 4; r++) acc[i][j][r] = 0.f;

    const int KT = K >> 5;
    gemm_issue_loads(sbase, pA, pB, K, 0, tid);
    CP_COMMIT();
    gemm_issue_loads(sbase + STAGE_B, pA, pB, K, 32, tid);
    CP_COMMIT();

    int cur = 0, pf = 2;
    for (int kt = 0; kt < KT; kt++) {
        if (kt + 1 < KT) { CP_WAIT(1); } else { CP_WAIT(0); }
        __syncthreads();

        uint32_t st = sbase + (uint32_t)cur * STAGE_B;

        #pragma unroll
        for (int kk = 0; kk < 2; kk++) {
            uint32_t a[4][4];
            #pragma unroll
            for (int mi = 0; mi < 4; mi++) {
                uint32_t aoff = (uint32_t)(((wm * 64 + mi * 16) * TSTR + kk * 16) * 2);
                ldm4(a[mi], st + aoff + laneA);
            }
            uint32_t b[4][2];
            #pragma unroll
            for (int nj2 = 0; nj2 < 2; nj2++) {
                uint32_t boff = (uint32_t)(((wn * 32 + nj2 * 16) * TSTR + kk * 16) * 2);
                uint32_t r[4];
                ldm4(r, st + TILE_B + boff + laneB);
                b[nj2*2][0] = r[0]; b[nj2*2][1] = r[1];
                b[nj2*2+1][0] = r[2]; b[nj2*2+1][1] = r[3];
            }
            #pragma unroll
            for (int mi = 0; mi < 4; mi++)
                #pragma unroll
                for (int nj = 0; nj < 4; nj++)
                    mma_f16(acc[mi][nj], a[mi], b[nj]);
        }

        // refill stage (kt+2)%3 == (kt-1)%3: drained after top-of-kt barrier
        if (kt + 2 < KT) {
            gemm_issue_loads(sbase + (uint32_t)pf * STAGE_B, pA, pB, K,
                             (kt + 2) << 5, tid);
            CP_COMMIT();
        }
        cur++; if (cur == 3) cur = 0;
        pf++;  if (pf == 3)  pf = 0;
    }
}

// fp32 epilogue (Q and O projections)
__device__ __forceinline__ void epilogue_f32(float acc[4][4][4], float* Ct, int N)
{
    const int lane = threadIdx.x & 31;
    const int wid  = threadIdx.x >> 5;
    const int wm = wid >> 2, wn = wid & 3;
    const int g = lane >> 2, tg = lane & 3;
    #pragma unroll
    for (int mi = 0; mi < 4; mi++) {
        int row = wm * 64 + mi * 16 + g;
        #pragma unroll
        for (int nj = 0; nj < 4; nj++) {
            int col = wn * 32 + nj * 8 + tg * 2;
            float* p0 = Ct + (size_t)row * N + col;
            float* p1 = p0 + (size_t)8 * N;
            p0[0] = acc[mi][nj][0]; p0[1] = acc[mi][nj][1];
            p1[0] = acc[mi][nj][2]; p1[1] = acc[mi][nj][3];
        }
    }
}

// Fused Q/K/V projection: grid (40, TOK/128). bx 0-31: Q (fp32 out);
// bx 32-35: K (rope + single fp16); bx 36-39: V (single fp16).
__global__ void __launch_bounds__(256, 2)
gemm_qkv(const __half* __restrict__ h1,
         const __half* __restrict__ wq, const __half* __restrict__ wk,
         const __half* __restrict__ wv,
         float* __restrict__ qb,
         __half* __restrict__ k1, __half* __restrict__ v1,
         const int* __restrict__ pos32)
{
    extern __shared__ char smem[];
    const int bx = blockIdx.x;
    const int bm = blockIdx.y << 7;
    const int tid = threadIdx.x;
    const __half* bp;
    int bn;
    if (bx < 32)      { bp = wq; bn = bx << 7; }
    else if (bx < 36) { bp = wk; bn = (bx - 32) << 7; }
    else              { bp = wv; bn = (bx - 36) << 7; }

    float acc[4][4][4];
    gemm_mainloop(h1 + (size_t)bm * HID, bp + (size_t)bn * HID, HID, smem, acc);

    const int lane = tid & 31;
    const int wid  = tid >> 5;
    const int wm = wid >> 2, wn = wid & 3;
    const int g = lane >> 2, tg = lane & 3;

    if (bx < 32) {
        epilogue_f32(acc, qb + (size_t)bm * QD + bn, QD);
    } else if (bx < 36) {
        // K: stage acc to smem, then rope + single fp16 round
        float* sacc = (float*)smem;     // [128][132] = 67584 B
        __syncthreads();
        #pragma unroll
        for (int mi = 0; mi < 4; mi++) {
            int row = wm * 64 + mi * 16 + g;
            #pragma unroll
            for (int nj = 0; nj < 4; nj++) {
                int col = wn * 32 + nj * 8 + tg * 2;
                sacc[row * 132 + col]     = acc[mi][nj][0];
                sacc[row * 132 + col + 1] = acc[mi][nj][1];
                sacc[(row + 8) * 132 + col]     = acc[mi][nj][2];
                sacc[(row + 8) * 132 + col + 1] = acc[mi][nj][3];
            }
        }
        __syncthreads();
        const bool is64 = (pos32[1] == 0);
        #pragma unroll
        for (int i = 0; i < 32; i++) {
            int idx = tid + (i << 8);
            int row = idx >> 6;
            int d   = idx & 63;
            int t   = bm + row;
            int p = is64 ? pos32[2 * t] : pos32[t];
            float invf = powf(1.0e6f, -(float)d * (1.0f / 64.0f));
            float sv, cv;
            sincosf((float)p * invf, &sv, &cv);
            float x1 = sacc[row * 132 + d];
            float x2 = sacc[row * 132 + d + 64];
            size_t off = (size_t)t * KVD + bn + d;
            k1[off]      = __float2half(x1 * cv - x2 * sv);
            k1[off + 64] = __float2half(x2 * cv + x1 * sv);
        }
    } else {
        // V: single fp16 round
        #pragma unroll
        for (int mi = 0; mi < 4; mi++) {
            int row = wm * 64 + mi * 16 + g;
            #pragma unroll
            for (int nj = 0; nj < 4; nj++) {
                int col = wn * 32 + nj * 8 + tg * 2;
                size_t off0 = (size_t)(bm + row) * KVD + bn + col;
                size_t off1 = off0 + (size_t)8 * KVD;
                *(uint32_t*)(v1 + off0) = cvt2h(acc[mi][nj][1], acc[mi][nj][0]);
                *(uint32_t*)(v1 + off1) = cvt2h(acc[mi][nj][3], acc[mi][nj][2]);
            }
        }
    }
}

// O-projection: single-term fp16
__global__ void __launch_bounds__(256, 2)
gemm_nt_single(const __half* __restrict__ A, const __half* __restrict__ B,
               float* __restrict__ C, int N, int K)
{
    extern __shared__ char smem[];
    const int bm = blockIdx.y << 7;
    const int bn = blockIdx.x << 7;
    float acc[4][4][4];
    gemm_mainloop(A + (size_t)bm * K, B + (size_t)bn * K, K, smem, acc);
    epilogue_f32(acc, C + (size_t)bm * N + bn, N);
}

// ===========================================================================
// Flash attention: fp16 mma, FMA-pipe exp2, non-causal.
// QK: Q hi/lo x K single (2 terms). PV: P single x V single (1 term).
// Q-RoPE fused into Q-load. Epilogue writes single fp16 (feeds O-proj).
// ===========================================================================
#define FSTR 136
#define FA_Q_B (128*FSTR*2)
#define FA_T_B (64*FSTR*2)
#define FA_ST_B (2*FA_T_B)                // K, V
#define FA_SMEM (2*FA_Q_B + 2*FA_ST_B)    // 139264

__device__ __forceinline__ void fa_load_kv(
    uint32_t stage, const __half* __restrict__ K1, const __half* __restrict__ V1,
    size_t rowbase, int kvoff, int tid)
{
    #pragma unroll
    for (int comp = 0; comp < 2; comp++) {
        const __half* g = (comp == 0) ? K1 : V1;
        #pragma unroll
        for (int jj = 0; jj < 4; jj++) {
            int cc = tid + (jj << 8);
            int row = cc >> 4, kc = cc & 15;
            cp_async16(stage + comp * FA_T_B + (uint32_t)(row * 272 + kc * 16),
                       g + (rowbase + row) * KVD + kvoff + kc * 8);
        }
    }
}

__global__ void __launch_bounds__(256, 1)
flash_attn_mma(const float* __restrict__ Q, const int* __restrict__ pos32,
               const __half* __restrict__ K1, const __half* __restrict__ V1,
               __half* __restrict__ a1)
{
    extern __shared__ char smem[];
    uint32_t sb = smem_u32(smem);
    const uint32_t sQH = sb;
    const uint32_t sQL = sb + FA_Q_B;
    const uint32_t sST = sb + 2 * FA_Q_B;

    const int tid = threadIdx.x, lane = tid & 31, w = tid >> 5;
    const int bh = blockIdx.y, b = bh >> 5, h = bh & 31, kvh = h >> 3;
    const int q0 = blockIdx.x << 7;
    const int g = lane >> 2, t = lane & 3;

    // --- Q load + RoPE + scale(1/sqrt(d)*log2e) + fp16 hi/lo split ---
    const float qsc = 0.08838834764831843f * 1.4426950408889634f;
    const float* Qg = Q + (size_t)(b * SEQ + q0) * QD + h * HD;
    const bool is64 = (pos32[1] == 0);
    #pragma unroll
    for (int i = 0; i < 8; i++) {
        int idx = tid + (i << 8);
        int row = idx >> 4;
        int d4  = (idx & 15) << 2;
        int tok = b * SEQ + q0 + row;
        int p = is64 ? pos32[2 * tok] : pos32[tok];
        float4 xa = *(const float4*)(Qg + (size_t)row * QD + d4);
        float4 xb = *(const float4*)(Qg + (size_t)row * QD + d4 + 64);
        float ya[4], yb[4];
        const float* x1 = &xa.x;
        const float* x2 = &xb.x;
        #pragma unroll
        for (int j = 0; j < 4; j++) {
            int d = d4 + j;
            float invf = powf(1.0e6f, -(float)d * (1.0f / 64.0f));
            float sv, cv;
            sincosf((float)p * invf, &sv, &cv);
            ya[j] = (x1[j] * cv - x2[j] * sv) * qsc;
            yb[j] = (x2[j] * cv + x1[j] * sv) * qsc;
        }
        uint32_t ha01 = cvt2h(ya[1], ya[0]);
        uint32_t ha23 = cvt2h(ya[3], ya[2]);
        uint32_t la01 = cvt2h(ya[1] - hhiF(ha01), ya[0] - hloF(ha01));
        uint32_t la23 = cvt2h(ya[3] - hhiF(ha23), ya[2] - hloF(ha23));
        uint32_t hb01 = cvt2h(yb[1], yb[0]);
        uint32_t hb23 = cvt2h(yb[3], yb[2]);
        uint32_t lb01 = cvt2h(yb[1] - hhiF(hb01), yb[0] - hloF(hb01));
        uint32_t lb23 = cvt2h(yb[3] - hhiF(hb23), yb[2] - hloF(hb23));
        uint32_t off1 = (uint32_t)(row * 272 + d4 * 2);
        uint32_t off2 = (uint32_t)(row * 272 + (d4 + 64) * 2);
        *(uint2*)(smem + (sQH - sb) + off1) = make_uint2(ha01, ha23);
        *(uint2*)(smem + (sQL - sb) + off1) = make_uint2(la01, la23);
        *(uint2*)(smem + (sQH - sb) + off2) = make_uint2(hb01, hb23);
        *(uint2*)(smem + (sQL - sb) + off2) = make_uint2(lb01, lb23);
    }

    float m0 = -1e30f, m1 = -1e30f, l0 = 0.f, l1 = 0.f;
    float o[16][4];
    #pragma unroll
    for (int nd = 0; nd < 16; nd++)
        #pragma unroll
        for (int c = 0; c < 4; c++) o[nd][c] = 0.f;

    const size_t kvbase = (size_t)b * SEQ;
    const int kvoff = kvh * HD;

    const uint32_t lA = (uint32_t)(((lane & 15) * FSTR + ((lane >> 4) << 3)) * 2);
    const uint32_t lB = (uint32_t)((((lane & 7) + ((lane >> 4) << 3)) * FSTR
                                    + (((lane >> 3) & 1) << 3)) * 2);
    const uint32_t lV = (uint32_t)((((lane & 7) + (((lane >> 3) & 1) << 3)) * FSTR
                                    + (((lane >> 4) & 1) << 3)) * 2);

    fa_load_kv(sST, K1, V1, kvbase, kvoff, tid);
    CP_COMMIT();

    for (int kt = 0; kt < SEQ / 64; kt++) {
        if (kt + 1 < SEQ / 64) {
            fa_load_kv(sST + ((kt + 1) & 1) * FA_ST_B, K1, V1,
                       kvbase + (size_t)(kt + 1) * 64, kvoff, tid);
            CP_COMMIT();
            CP_WAIT(1);
        } else {
            CP_WAIT(0);
        }
        __syncthreads();

        const uint32_t st = sST + (kt & 1) * FA_ST_B;
        const uint32_t sK = st, sV = st + FA_T_B;

        float s[8][4];
        #pragma unroll
        for (int j = 0; j < 8; j++)
            #pragma unroll
            for (int c = 0; c < 4; c++) s[j][c] = 0.f;

        #pragma unroll
        for (int kk = 0; kk < 8; kk++) {
            uint32_t qh[4], ql[4];
            uint32_t qoff = (uint32_t)((w * 16 * FSTR + kk * 16) * 2);
            ldm4(qh, sQH + qoff + lA);
            ldm4(ql, sQL + qoff + lA);
            #pragma unroll
            for (int nj2 = 0; nj2 < 4; nj2++) {
                uint32_t koff = (uint32_t)((nj2 * 16 * FSTR + kk * 16) * 2);
                uint32_t rk[4];
                ldm4(rk, sK + koff + lB);
                mma_f16(s[nj2*2],   qh, rk);     mma_f16(s[nj2*2+1], qh, rk + 2);
                mma_f16(s[nj2*2],   ql, rk);     mma_f16(s[nj2*2+1], ql, rk + 2);
            }
        }

        float mx0 = -1e30f, mx1 = -1e30f;
        #pragma unroll
        for (int j = 0; j < 8; j++) {
            mx0 = fmaxf(mx0, fmaxf(s[j][0], s[j][1]));
            mx1 = fmaxf(mx1, fmaxf(s[j][2], s[j][3]));
        }
        mx0 = fmaxf(mx0, __shfl_xor_sync(0xffffffffu, mx0, 1));
        mx0 = fmaxf(mx0, __shfl_xor_sync(0xffffffffu, mx0, 2));
        mx1 = fmaxf(mx1, __shfl_xor_sync(0xffffffffu, mx1, 1));
        mx1 = fmaxf(mx1, __shfl_xor_sync(0xffffffffu, mx1, 2));
        float mn0 = fmaxf(m0, mx0), mn1 = fmaxf(m1, mx1);

        bool newmax = (mn0 > m0) || (mn1 > m1);
        if (__any_sync(0xffffffffu, newmax)) {
            float al0 = fast_exp2(m0 - mn0), al1 = fast_exp2(m1 - mn1);
            l0 *= al0; l1 *= al1;
            #pragma unroll
            for (int nd = 0; nd < 16; nd++) {
                o[nd][0] *= al0; o[nd][1] *= al0;
                o[nd][2] *= al1; o[nd][3] *= al1;
            }
        }
        m0 = mn0; m1 = mn1;

        uint32_t pf[4][4];
        float sum0 = 0.f, sum1 = 0.f;
        #pragma unroll
        for (int j = 0; j < 8; j++) {
            float p00 = fast_exp2(s[j][0] - mn0);
            float p01 = fast_exp2(s[j][1] - mn0);
            float p10 = fast_exp2(s[j][2] - mn1);
            float p11 = fast_exp2(s[j][3] - mn1);
            sum0 += p00 + p01; sum1 += p10 + p11;
            int kk2 = j >> 1, hf = (j & 1) << 1;
            pf[kk2][hf]     = cvt2h(p01, p00);
            pf[kk2][hf + 1] = cvt2h(p11, p10);
        }
        sum0 += __shfl_xor_sync(0xffffffffu, sum0, 1);
        sum0 += __shfl_xor_sync(0xffffffffu, sum0, 2);
        sum1 += __shfl_xor_sync(0xffffffffu, sum1, 1);
        sum1 += __shfl_xor_sync(0xffffffffu, sum1, 2);
        l0 += sum0;
        l1 += sum1;

        #pragma unroll
        for (int kk2 = 0; kk2 < 4; kk2++) {
            #pragma unroll
            for (int ndp = 0; ndp < 8; ndp++) {
                uint32_t voff = (uint32_t)((kk2 * 16 * FSTR + ndp * 16) * 2);
                uint32_t v[4];
                ldm4t(v, sV + voff + lV);
                mma_f16(o[ndp*2], pf[kk2], v);   mma_f16(o[ndp*2+1], pf[kk2], v + 2);
            }
        }
        __syncthreads();
    }

    float il0 = 1.f / l0, il1 = 1.f / l1;
    size_t rbase = (size_t)(b * SEQ + q0 + w * 16 + g) * QD + h * HD;
    __half* A1 = a1 + rbase;
    #pragma unroll
    for (int nd = 0; nd < 16; nd++) {
        int col = nd * 8 + t * 2;
        *(uint32_t*)(A1 + col) = cvt2h(o[nd][1] * il0, o[nd][0] * il0);
        *(uint32_t*)(A1 + (size_t)8 * QD + col) = cvt2h(o[nd][3] * il1, o[nd][2] * il1);
    }
}

// ---------------------------------------------------------------------------
extern "C" void kernel_launch(void* const* d_in, const int* in_sizes, int n_in,
                              void* d_out, int out_size)
{
    const float* hidden = (const float*)d_in[0];
    const int*   pos    = (const int*)d_in[1];
    const float* Wq     = (const float*)d_in[2];
    const float* Wk     = (const float*)d_in[3];
    const float* Wv     = (const float*)d_in[4];
    const float* Wo     = (const float*)d_in[5];
    float*       out    = (float*)d_out;

    float *qb;
    cudaGetSymbolAddress((void**)&qb, g_q);
    __half *h1,*wq,*wk,*wv,*wo,*a1,*k1,*v1;
    cudaGetSymbolAddress((void**)&h1, g_h1);
    cudaGetSymbolAddress((void**)&wq, g_wq); cudaGetSymbolAddress((void**)&wk, g_wk);
    cudaGetSymbolAddress((void**)&wv, g_wv); cudaGetSymbolAddress((void**)&wo, g_wo);
    cudaGetSymbolAddress((void**)&a1, g_a1);
    cudaGetSymbolAddress((void**)&k1, g_k1);
    cudaGetSymbolAddress((void**)&v1, g_v1);

    cudaFuncSetAttribute(gemm_qkv, cudaFuncAttributeMaxDynamicSharedMemorySize, GEMMQ_SMEM);
    cudaFuncSetAttribute(gemm_nt_single, cudaFuncAttributeMaxDynamicSharedMemorySize, GEMM_SMEM_MIN);
    cudaFuncSetAttribute(flash_attn_mma, cudaFuncAttributeMaxDynamicSharedMemorySize, FA_SMEM);

    // Splits: everything single-rounded fp16
    split_all_kernel<<<(SPL_N4 + 255)/256, 256>>>(hidden, Wq, Wk, Wv, Wo,
                                                  h1, wq, wk, wv, wo);

    // Fused Q/K/V projections (1-term)
    gemm_qkv<<<dim3(40, TOK/128), 256, GEMMQ_SMEM>>>(h1, wq, wk, wv,
                                                     qb, k1, v1, pos);

    // Flash attention (Q rope fused; QK 2-term, PV 1-term) -> single fp16 out
    flash_attn_mma<<<dim3(SEQ/128, BATCH*NH), 256, FA_SMEM>>>(qb, pos, k1, v1, a1);

    // O projection (1-term)
    gemm_nt_single<<<dim3(HID/128, TOK/128), 256, GEMM_SMEM_MIN>>>(a1, wo, out, HID, QD);
}